// round 1
// baseline (speedup 1.0000x reference)
#include <cuda_runtime.h>

#define NN   50000
#define EE   1600000
#define DINN 2000

// ---------------- device scratch (allocation-free contract) ----------------
__device__ float g_alpha1[2 * 500];
__device__ float g_bb1[2 * 500];
__device__ float g_alpha2[2 * 128];
__device__ float g_t2b[2 * 128];
__device__ float g_cmean[64];
__device__ float g_cprime[64];
__device__ float g_Wde2[2 * 128 * 64];   // 0.5 * alpha2[l] * (Wd @ Wg0)
__device__ float g_T[2 * 2000 * 128];    // (W1*alpha1) @ W2
__device__ float g_M[2 * 2000 * 64];     // folded encoder+Wg0 matrix
__device__ float g_xw0[NN * 64];
__device__ float g_agg0[NN * 64];
__device__ float g_xw1[NN * 32];
__device__ float g_agg1[NN * 32];
__device__ float g_xw2[NN * 4];
__device__ float g_agg2[NN * 4];
__device__ float g_cs[NN];
__device__ float g_cd[NN];
__device__ int   g_degS[NN];
__device__ int   g_degD[NN];

// ---------------- small helpers ----------------
__device__ __forceinline__ void ffma2(unsigned long long& c, unsigned long long a,
                                      unsigned long long b) {
    asm("fma.rn.f32x2 %0, %1, %2, %0;" : "+l"(c) : "l"(a), "l"(b));
}

// ---------------- init / degrees ----------------
__global__ void k_zero_deg() {
    int i = blockIdx.x * 256 + threadIdx.x;
    if (i < NN) { g_degS[i] = 0; g_degD[i] = 0; }
}

__global__ void k_zero_aggs() {
    int i = blockIdx.x * 256 + threadIdx.x;
    if (i < NN * 64) g_agg0[i] = 0.f;
    if (i < NN * 32) g_agg1[i] = 0.f;
    if (i < NN * 4)  g_agg2[i] = 0.f;
}

__global__ void k_deg(const int* __restrict__ src, const int* __restrict__ dst) {
    int i = blockIdx.x * 256 + threadIdx.x;
    if (i < EE) {
        atomicAdd(&g_degS[src[i]], 1);
        atomicAdd(&g_degD[dst[i]], 1);
    }
}

__global__ void k_norm() {
    int i = blockIdx.x * 256 + threadIdx.x;
    if (i < NN) {
        g_cs[i] = rsqrtf(fmaxf((float)g_degS[i], 1.0f));
        g_cd[i] = rsqrtf(fmaxf((float)g_degD[i], 1.0f));
    }
}

// ---------------- bias-chain fold (tiny, 1 block) ----------------
__global__ void k_prep(const float* __restrict__ b1, const float* __restrict__ g1,
                       const float* __restrict__ be1, const float* __restrict__ m1,
                       const float* __restrict__ v1, const float* __restrict__ W2,
                       const float* __restrict__ b2, const float* __restrict__ g2,
                       const float* __restrict__ be2, const float* __restrict__ m2,
                       const float* __restrict__ v2, const float* __restrict__ Wd,
                       const float* __restrict__ bd, const float* __restrict__ Wg0) {
    int t = threadIdx.x;
    for (int i = t; i < 1000; i += 512) {
        float a = g1[i] * rsqrtf(v1[i] + 1e-5f);
        g_alpha1[i] = a;
        g_bb1[i] = (b1[i] - m1[i]) * a + be1[i];
    }
    for (int i = t; i < 256; i += 512)
        g_alpha2[i] = g2[i] * rsqrtf(v2[i] + 1e-5f);
    __syncthreads();
    for (int i = t; i < 256; i += 512) {
        int mm = i >> 7, l = i & 127;
        float s = 0.f;
        for (int j = 0; j < 500; j++)
            s += g_bb1[mm * 500 + j] * W2[mm * 64000 + j * 128 + l];
        g_t2b[i] = (s + b2[i] - m2[i]) * g_alpha2[i] + be2[i];
    }
    __syncthreads();
    for (int d = t; d < 64; d += 512) {
        float s = 0.f;
        for (int mm = 0; mm < 2; mm++) {
            float sm = bd[mm * 64 + d];
            for (int l = 0; l < 128; l++)
                sm += g_t2b[mm * 128 + l] * Wd[mm * 8192 + l * 64 + d];
            s += sm;
        }
        g_cmean[d] = 0.5f * s;
    }
    __syncthreads();
    for (int e = t; e < 64; e += 512) {
        float s = 0.f;
        for (int d = 0; d < 64; d++) s += g_cmean[d] * Wg0[d * 64 + e];
        g_cprime[e] = s;
    }
}

// Wde2[m][l][e] = 0.5*alpha2[m][l] * sum_d Wd[m][l][d]*Wg0[d][e]
__global__ void k_wde2(const float* __restrict__ Wd, const float* __restrict__ Wg0) {
    int l = blockIdx.x, m = blockIdx.y, e = threadIdx.x;
    float s = 0.f;
    for (int d = 0; d < 64; d++) s += Wd[m * 8192 + l * 64 + d] * Wg0[d * 64 + e];
    g_Wde2[m * 8192 + l * 64 + e] = 0.5f * g_alpha2[m * 128 + l] * s;
}

// T[m][i][l] = sum_j (W1[m][i][j]*alpha1[m][j]) * W2[m][j][l], 8 rows per block
__global__ void k_T(const float* __restrict__ W1, const float* __restrict__ W2) {
    __shared__ float sA[8][500];
    int m = blockIdx.y, i0 = blockIdx.x * 8, t = threadIdx.x;  // 128 threads
    for (int idx = t; idx < 4000; idx += 128) {
        int r = idx / 500, j = idx - r * 500;
        sA[r][j] = W1[m * 1000000 + (i0 + r) * 500 + j] * g_alpha1[m * 500 + j];
    }
    __syncthreads();
    int l = t;
    float acc[8] = {0, 0, 0, 0, 0, 0, 0, 0};
    for (int j = 0; j < 500; j++) {
        float w = W2[m * 64000 + j * 128 + l];
#pragma unroll
        for (int r = 0; r < 8; r++) acc[r] += sA[r][j] * w;
    }
#pragma unroll
    for (int r = 0; r < 8; r++) g_T[m * 256000 + (i0 + r) * 128 + l] = acc[r];
}

// M[m][i][e] = sum_l T[m][i][l] * Wde2[m][l][e], 8 rows per block
__global__ void k_M() {
    __shared__ float sT[8][128];
    int m = blockIdx.y, i0 = blockIdx.x * 8, t = threadIdx.x;  // 64 threads
    for (int idx = t; idx < 1024; idx += 64) {
        int r = idx >> 7, l = idx & 127;
        sT[r][l] = g_T[m * 256000 + (i0 + r) * 128 + l];
    }
    __syncthreads();
    int e = t;
    float acc[8] = {0, 0, 0, 0, 0, 0, 0, 0};
    for (int l = 0; l < 128; l++) {
        float w = g_Wde2[m * 8192 + l * 64 + e];
#pragma unroll
        for (int r = 0; r < 8; r++) acc[r] += sT[r][l] * w;
    }
#pragma unroll
    for (int r = 0; r < 8; r++) g_M[m * 128000 + (i0 + r) * 64 + e] = acc[r];
}

// ---------------- main GEMM: xw0 = cs * (sum_m h_m @ M_m + c') ----------------
// BM=128, BN=64, BK=16, 256 threads, per-thread 8x4 via packed fma.rn.f32x2.
__global__ __launch_bounds__(256) void k_gemm(const float* __restrict__ h) {
    __shared__ __align__(16) float As2[2][16][256];  // A duplicated: [k][2r]=[k][2r+1]
    __shared__ __align__(16) float Bs[2][16][64];

    int tid = threadIdx.x;
    int tx = tid & 15;   // column group (4 outputs)
    int ty = tid >> 4;   // row group (8 outputs)
    int row0 = blockIdx.x * 128;

    int arow = tid >> 2;          // 0..63
    int acol = (tid & 3) << 2;    // 0,4,8,12
    int brow = tid >> 4;          // 0..15
    int bcol = (tid & 15) << 2;   // 0..60

    unsigned long long acc[8][2];
#pragma unroll
    for (int i = 0; i < 8; i++) { acc[i][0] = 0ull; acc[i][1] = 0ull; }

    auto ldA = [&](int buf, int m, int k0) {
#pragma unroll
        for (int p = 0; p < 2; p++) {
            int r = arow + p * 64;
            int gr = row0 + r;
            float4 v = make_float4(0.f, 0.f, 0.f, 0.f);
            if (gr < NN)
                v = *reinterpret_cast<const float4*>(
                    &h[(long long)m * NN * DINN + (long long)gr * DINN + k0 + acol]);
            *reinterpret_cast<float2*>(&As2[buf][acol + 0][2 * r]) = make_float2(v.x, v.x);
            *reinterpret_cast<float2*>(&As2[buf][acol + 1][2 * r]) = make_float2(v.y, v.y);
            *reinterpret_cast<float2*>(&As2[buf][acol + 2][2 * r]) = make_float2(v.z, v.z);
            *reinterpret_cast<float2*>(&As2[buf][acol + 3][2 * r]) = make_float2(v.w, v.w);
        }
    };
    auto ldB = [&](int buf, int m, int k0) {
        *reinterpret_cast<float4*>(&Bs[buf][brow][bcol]) =
            *reinterpret_cast<const float4*>(&g_M[m * 128000 + (k0 + brow) * 64 + bcol]);
    };

    ldA(0, 0, 0);
    ldB(0, 0, 0);
    __syncthreads();

    int buf = 0;
    for (int step = 0; step < 250; step++) {
        int nxt = step + 1;
        if (nxt < 250) {
            int m = nxt / 125;
            int k0 = (nxt - m * 125) * 16;
            ldA(buf ^ 1, m, k0);
            ldB(buf ^ 1, m, k0);
        }
#pragma unroll
        for (int k = 0; k < 16; k++) {
            const ulonglong2* ap =
                reinterpret_cast<const ulonglong2*>(&As2[buf][k][2 * (ty * 8)]);
            ulonglong2 a01 = ap[0];
            ulonglong2 a23 = ap[1];
            ulonglong2 a45 = ap[2];
            ulonglong2 a67 = ap[3];
            ulonglong2 bb = *reinterpret_cast<const ulonglong2*>(&Bs[buf][k][tx * 4]);
            ffma2(acc[0][0], a01.x, bb.x); ffma2(acc[0][1], a01.x, bb.y);
            ffma2(acc[1][0], a01.y, bb.x); ffma2(acc[1][1], a01.y, bb.y);
            ffma2(acc[2][0], a23.x, bb.x); ffma2(acc[2][1], a23.x, bb.y);
            ffma2(acc[3][0], a23.y, bb.x); ffma2(acc[3][1], a23.y, bb.y);
            ffma2(acc[4][0], a45.x, bb.x); ffma2(acc[4][1], a45.x, bb.y);
            ffma2(acc[5][0], a45.y, bb.x); ffma2(acc[5][1], a45.y, bb.y);
            ffma2(acc[6][0], a67.x, bb.x); ffma2(acc[6][1], a67.x, bb.y);
            ffma2(acc[7][0], a67.y, bb.x); ffma2(acc[7][1], a67.y, bb.y);
        }
        __syncthreads();
        buf ^= 1;
    }

    float cp0 = g_cprime[tx * 4 + 0];
    float cp1 = g_cprime[tx * 4 + 1];
    float cp2 = g_cprime[tx * 4 + 2];
    float cp3 = g_cprime[tx * 4 + 3];
#pragma unroll
    for (int i = 0; i < 8; i++) {
        int gr = row0 + ty * 8 + i;
        if (gr < NN) {
            float csv = g_cs[gr];
            float4 o;
            o.x = csv * (__uint_as_float((unsigned)(acc[i][0])) + cp0);
            o.y = csv * (__uint_as_float((unsigned)(acc[i][0] >> 32)) + cp1);
            o.z = csv * (__uint_as_float((unsigned)(acc[i][1])) + cp2);
            o.w = csv * (__uint_as_float((unsigned)(acc[i][1] >> 32)) + cp3);
            *reinterpret_cast<float4*>(&g_xw0[gr * 64 + tx * 4]) = o;
        }
    }
}

// ---------------- edge scatters (float4 atomics, agg tiles are L2-resident) -----
__global__ void k_scat64(const int* __restrict__ src, const int* __restrict__ dst) {
    long long idx = (long long)blockIdx.x * 256 + threadIdx.x;
    if (idx >= (long long)EE * 16) return;
    int e = (int)(idx >> 4), c = (int)(idx & 15);
    int s = src[e], d = dst[e];
    float4 v = *reinterpret_cast<const float4*>(&g_xw0[s * 64 + c * 4]);
    atomicAdd(reinterpret_cast<float4*>(&g_agg0[d * 64 + c * 4]), v);
}

__global__ void k_scat32(const int* __restrict__ src, const int* __restrict__ dst) {
    long long idx = (long long)blockIdx.x * 256 + threadIdx.x;
    if (idx >= (long long)EE * 8) return;
    int e = (int)(idx >> 3), c = (int)(idx & 7);
    int s = src[e], d = dst[e];
    float4 v = *reinterpret_cast<const float4*>(&g_xw1[s * 32 + c * 4]);
    atomicAdd(reinterpret_cast<float4*>(&g_agg1[d * 32 + c * 4]), v);
}

__global__ void k_scat4(const int* __restrict__ src, const int* __restrict__ dst) {
    int e = blockIdx.x * 256 + threadIdx.x;
    if (e >= EE) return;
    int s = src[e], d = dst[e];
    float4 v = *reinterpret_cast<const float4*>(&g_xw2[s * 4]);
    atomicAdd(reinterpret_cast<float4*>(&g_agg2[d * 4]), v);
}

// ---------------- fused relu/bias/norm + tiny GEMMs ----------------
// xw1[n][l<32] = sum_d relu(agg0[n][d]*cd[n]+bg0[d]) * cs[n] * Wg1[d][l]
__global__ void k_conv1(const float* __restrict__ bg0, const float* __restrict__ Wg1) {
    __shared__ float sW[64 * 32];
    __shared__ float sx[8][64];
    int t = threadIdx.x;  // 128
    int n0 = blockIdx.x * 8;
    for (int i = t; i < 2048; i += 128) sW[i] = Wg1[i];
    for (int idx = t; idx < 512; idx += 128) {
        int r = idx >> 6, d = idx & 63;
        int n = n0 + r;
        float v = 0.f;
        if (n < NN)
            v = fmaxf(g_agg0[n * 64 + d] * g_cd[n] + bg0[d], 0.f) * g_cs[n];
        sx[r][d] = v;
    }
    __syncthreads();
#pragma unroll
    for (int p = 0; p < 2; p++) {
        int o = t + p * 128;
        int r = o >> 5, l = o & 31;
        int n = n0 + r;
        if (n < NN) {
            float acc = 0.f;
#pragma unroll
            for (int d = 0; d < 64; d++) acc += sx[r][d] * sW[d * 32 + l];
            g_xw1[n * 32 + l] = acc;
        }
    }
}

// xw2[n][j<4] = sum_d relu(agg1[n][d]*cd[n]+bg1[d]) * cs[n] * Wg2[d][j]
__global__ void k_conv2(const float* __restrict__ bg1, const float* __restrict__ Wg2) {
    __shared__ float sW[32 * 4];
    __shared__ float sx[16][32];
    int t = threadIdx.x;  // 128
    int n0 = blockIdx.x * 16;
    if (t < 128) { if (t < 128) sW[t] = Wg2[t]; }
    for (int idx = t; idx < 512; idx += 128) {
        int r = idx >> 5, d = idx & 31;
        int n = n0 + r;
        float v = 0.f;
        if (n < NN)
            v = fmaxf(g_agg1[n * 32 + d] * g_cd[n] + bg1[d], 0.f) * g_cs[n];
        sx[r][d] = v;
    }
    __syncthreads();
    if (t < 64) {
        int r = t >> 2, j = t & 3;
        int n = n0 + r;
        if (n < NN) {
            float acc = 0.f;
#pragma unroll
            for (int d = 0; d < 32; d++) acc += sx[r][d] * sW[d * 4 + j];
            g_xw2[n * 4 + j] = acc;
        }
    }
}

__global__ void k_final(const float* __restrict__ bg2, float* __restrict__ out) {
    int idx = blockIdx.x * 256 + threadIdx.x;
    if (idx < NN * 4) {
        int n = idx >> 2, j = idx & 3;
        out[idx] = g_agg2[idx] * g_cd[n] + bg2[j];
    }
}

// ---------------- launch ----------------
extern "C" void kernel_launch(void* const* d_in, const int* in_sizes, int n_in,
                              void* d_out, int out_size) {
    const float* h   = (const float*)d_in[0];
    const int*   src = (const int*)d_in[1];
    const int*   dst = (const int*)d_in[2];
    const float* W1  = (const float*)d_in[3];
    const float* b1  = (const float*)d_in[4];
    const float* g1  = (const float*)d_in[5];
    const float* be1 = (const float*)d_in[6];
    const float* m1  = (const float*)d_in[7];
    const float* v1  = (const float*)d_in[8];
    const float* W2  = (const float*)d_in[9];
    const float* b2  = (const float*)d_in[10];
    const float* g2  = (const float*)d_in[11];
    const float* be2 = (const float*)d_in[12];
    const float* m2  = (const float*)d_in[13];
    const float* v2  = (const float*)d_in[14];
    const float* Wd  = (const float*)d_in[15];
    const float* bd  = (const float*)d_in[16];
    const float* Wg0 = (const float*)d_in[17];
    const float* bg0 = (const float*)d_in[18];
    const float* Wg1 = (const float*)d_in[19];
    const float* bg1 = (const float*)d_in[20];
    const float* Wg2 = (const float*)d_in[21];
    const float* bg2 = (const float*)d_in[22];
    float* out = (float*)d_out;

    // degrees + norms (independent of encoder fold)
    k_zero_deg<<<(NN + 255) / 256, 256>>>();
    k_zero_aggs<<<(NN * 64 + 255) / 256, 256>>>();
    k_deg<<<(EE + 255) / 256, 256>>>(src, dst);
    k_norm<<<(NN + 255) / 256, 256>>>();

    // fold encoder weights: M = 0.5 * W1a1 W2a2 Wd Wg0, c' = bias chain @ Wg0
    k_prep<<<1, 512>>>(b1, g1, be1, m1, v1, W2, b2, g2, be2, m2, v2, Wd, bd, Wg0);
    k_wde2<<<dim3(128, 2), 64>>>(Wd, Wg0);
    k_T<<<dim3(250, 2), 128>>>(W1, W2);
    k_M<<<dim3(250, 2), 64>>>();

    // big GEMM: xw0 = cs * (h @ M + c')
    k_gemm<<<(NN + 127) / 128, 256>>>(h);

    // conv0 aggregate, then fused layers
    k_scat64<<<(int)(((long long)EE * 16 + 255) / 256), 256>>>(src, dst);
    k_conv1<<<(NN + 7) / 8, 128>>>(bg0, Wg1);
    k_scat32<<<(int)(((long long)EE * 8 + 255) / 256), 256>>>(src, dst);
    k_conv2<<<(NN + 15) / 16, 128>>>(bg1, Wg2);
    k_scat4<<<(EE + 255) / 256, 256>>>(src, dst);
    k_final<<<(NN * 4 + 255) / 256, 256>>>(bg2, out);
}

// round 3
// speedup vs baseline: 1.7961x; 1.7961x over previous
#include <cuda_runtime.h>
#include <cuda_bf16.h>
#include <cstdint>

#define NN   50000
#define EE   1600000
#define DINN 2000

// ---------------- device scratch (allocation-free contract) ----------------
__device__ float g_alpha1[2 * 500];
__device__ float g_bb1[2 * 500];
__device__ float g_alpha2[2 * 128];
__device__ float g_t2b[2 * 128];
__device__ float g_cmean[64];
__device__ float g_cprime[64];
__device__ float g_Wde2[2 * 128 * 64];   // 0.5 * alpha2[l] * (Wd @ Wg0)
__device__ float g_T[2 * 2000 * 128];    // (W1*alpha1) @ W2
__device__ float g_M[2 * 2000 * 64];     // folded encoder+Wg0 matrix
__device__ __nv_bfloat16 g_Bhi[64 * 4096];  // [e][m*2048+k] split-high of M^T
__device__ __nv_bfloat16 g_Blo[64 * 4096];  // split-low
__device__ float g_xw0[NN * 64];
__device__ float g_agg0[NN * 64];
__device__ float g_xw1[NN * 32];
__device__ float g_agg1[NN * 32];
__device__ float g_xw2[NN * 4];
__device__ float g_agg2[NN * 4];
__device__ float g_cs[NN];
__device__ float g_cd[NN];
__device__ int   g_degS[NN];
__device__ int   g_degD[NN];

// ---------------- init / degrees ----------------
__global__ void k_zero_deg() {
    int i = blockIdx.x * 256 + threadIdx.x;
    if (i < NN) { g_degS[i] = 0; g_degD[i] = 0; }
}

__global__ void k_zero_aggs() {
    int i = blockIdx.x * 256 + threadIdx.x;
    if (i < NN * 64) g_agg0[i] = 0.f;
    if (i < NN * 32) g_agg1[i] = 0.f;
    if (i < NN * 4)  g_agg2[i] = 0.f;
}

__global__ void k_deg(const int* __restrict__ src, const int* __restrict__ dst) {
    int i = blockIdx.x * 256 + threadIdx.x;
    if (i < EE) {
        atomicAdd(&g_degS[src[i]], 1);
        atomicAdd(&g_degD[dst[i]], 1);
    }
}

__global__ void k_norm() {
    int i = blockIdx.x * 256 + threadIdx.x;
    if (i < NN) {
        g_cs[i] = rsqrtf(fmaxf((float)g_degS[i], 1.0f));
        g_cd[i] = rsqrtf(fmaxf((float)g_degD[i], 1.0f));
    }
}

// ---------------- bias-chain fold (tiny, 1 block) ----------------
__global__ void k_prep(const float* __restrict__ b1, const float* __restrict__ g1,
                       const float* __restrict__ be1, const float* __restrict__ m1,
                       const float* __restrict__ v1, const float* __restrict__ W2,
                       const float* __restrict__ b2, const float* __restrict__ g2,
                       const float* __restrict__ be2, const float* __restrict__ m2,
                       const float* __restrict__ v2, const float* __restrict__ Wd,
                       const float* __restrict__ bd, const float* __restrict__ Wg0) {
    int t = threadIdx.x;
    for (int i = t; i < 1000; i += 512) {
        float a = g1[i] * rsqrtf(v1[i] + 1e-5f);
        g_alpha1[i] = a;
        g_bb1[i] = (b1[i] - m1[i]) * a + be1[i];
    }
    for (int i = t; i < 256; i += 512)
        g_alpha2[i] = g2[i] * rsqrtf(v2[i] + 1e-5f);
    __syncthreads();
    for (int i = t; i < 256; i += 512) {
        int mm = i >> 7, l = i & 127;
        float s = 0.f;
        for (int j = 0; j < 500; j++)
            s += g_bb1[mm * 500 + j] * W2[mm * 64000 + j * 128 + l];
        g_t2b[i] = (s + b2[i] - m2[i]) * g_alpha2[i] + be2[i];
    }
    __syncthreads();
    for (int d = t; d < 64; d += 512) {
        float s = 0.f;
        for (int mm = 0; mm < 2; mm++) {
            float sm = bd[mm * 64 + d];
            for (int l = 0; l < 128; l++)
                sm += g_t2b[mm * 128 + l] * Wd[mm * 8192 + l * 64 + d];
            s += sm;
        }
        g_cmean[d] = 0.5f * s;
    }
    __syncthreads();
    for (int e = t; e < 64; e += 512) {
        float s = 0.f;
        for (int d = 0; d < 64; d++) s += g_cmean[d] * Wg0[d * 64 + e];
        g_cprime[e] = s;
    }
}

__global__ void k_wde2(const float* __restrict__ Wd, const float* __restrict__ Wg0) {
    int l = blockIdx.x, m = blockIdx.y, e = threadIdx.x;
    float s = 0.f;
    for (int d = 0; d < 64; d++) s += Wd[m * 8192 + l * 64 + d] * Wg0[d * 64 + e];
    g_Wde2[m * 8192 + l * 64 + e] = 0.5f * g_alpha2[m * 128 + l] * s;
}

__global__ void k_T(const float* __restrict__ W1, const float* __restrict__ W2) {
    __shared__ float sA[8][500];
    int m = blockIdx.y, i0 = blockIdx.x * 8, t = threadIdx.x;
    for (int idx = t; idx < 4000; idx += 128) {
        int r = idx / 500, j = idx - r * 500;
        sA[r][j] = W1[m * 1000000 + (i0 + r) * 500 + j] * g_alpha1[m * 500 + j];
    }
    __syncthreads();
    int l = t;
    float acc[8] = {0, 0, 0, 0, 0, 0, 0, 0};
    for (int j = 0; j < 500; j++) {
        float w = W2[m * 64000 + j * 128 + l];
#pragma unroll
        for (int r = 0; r < 8; r++) acc[r] += sA[r][j] * w;
    }
#pragma unroll
    for (int r = 0; r < 8; r++) g_T[m * 256000 + (i0 + r) * 128 + l] = acc[r];
}

__global__ void k_M() {
    __shared__ float sT[8][128];
    int m = blockIdx.y, i0 = blockIdx.x * 8, t = threadIdx.x;
    for (int idx = t; idx < 1024; idx += 64) {
        int r = idx >> 7, l = idx & 127;
        sT[r][l] = g_T[m * 256000 + (i0 + r) * 128 + l];
    }
    __syncthreads();
    int e = t;
    float acc[8] = {0, 0, 0, 0, 0, 0, 0, 0};
    for (int l = 0; l < 128; l++) {
        float w = g_Wde2[m * 8192 + l * 64 + e];
#pragma unroll
        for (int r = 0; r < 8; r++) acc[r] += sT[r][l] * w;
    }
#pragma unroll
    for (int r = 0; r < 8; r++) g_M[m * 128000 + (i0 + r) * 64 + e] = acc[r];
}

// Split folded matrix into bf16 hi/lo, transposed to [e][k'] with k' padded to 2048/mod.
__global__ void k_bsplit() {
    int idx = blockIdx.x * 256 + threadIdx.x;
    if (idx >= 64 * 4096) return;
    int e = idx >> 12, kk = idx & 4095;
    int m = kk >> 11, k = kk & 2047;
    float v = (k < 2000) ? g_M[m * 128000 + k * 64 + e] : 0.f;
    __nv_bfloat16 hi = __float2bfloat16(v);
    float lo = v - __bfloat162float(hi);
    g_Bhi[idx] = hi;
    g_Blo[idx] = __float2bfloat16(lo);
}

// ---------------- HMMA GEMM: xw0 = cs * (sum_m h_m @ M_m + c') ----------------
// Block tile 128x64, 8 warps in 4(M)x2(N), warp tile 32x32, K-chunk 64.
// bf16 hi/lo 3-term split: Ah*Bh + Ah*Bl + Al*Bh.
#define SM_CPR 0
#define SM_A   1024                 // 2 buf x (hi 16KB + lo 16KB) = 64KB
#define SM_B   (1024 + 65536)       // 2 buf x (hi 8KB + lo 8KB) = 32KB
#define SMEM_BYTES (1024 + 65536 + 32768)

#define MMA(c, a, b) \
    asm volatile( \
        "mma.sync.aligned.m16n8k16.row.col.f32.bf16.bf16.f32 " \
        "{%0,%1,%2,%3}, {%4,%5,%6,%7}, {%8,%9}, {%0,%1,%2,%3};" \
        : "+f"((c)[0]), "+f"((c)[1]), "+f"((c)[2]), "+f"((c)[3]) \
        : "r"((a)[0]), "r"((a)[1]), "r"((a)[2]), "r"((a)[3]), \
          "r"((b)[0]), "r"((b)[1]))

__global__ __launch_bounds__(256) void k_gemm_hmma(const float* __restrict__ h) {
    extern __shared__ __align__(1024) char smem[];
    int tid = threadIdx.x;
    int lane = tid & 31, wid = tid >> 5;
    int wm = wid >> 1, wn = wid & 1;
    int row0 = blockIdx.x * 128;

    if (tid < 64) *reinterpret_cast<float*>(smem + SM_CPR + tid * 4) = g_cprime[tid];

    int g = lane >> 2;               // 0..7
    uint32_t four = (lane & 3) * 4;  // byte offset within 16B chunk
    uint32_t xv = (uint32_t)(g & 7) << 4;
    uint32_t arow = (uint32_t)(wm * 32 + g) * 128;
    uint32_t brow = (uint32_t)(wn * 32 + g) * 128;

    float c_[2][4][4];
#pragma unroll
    for (int mt = 0; mt < 2; mt++)
#pragma unroll
        for (int nt = 0; nt < 4; nt++)
#pragma unroll
            for (int q = 0; q < 4; q++) c_[mt][nt][q] = 0.f;

    float4 va[8];
    uint4 vbh[2], vbl[2];

    auto ldg = [&](int c) {
        int m = c >> 5, k0 = (c & 31) * 64;
        const float* hb = h + (long long)m * NN * DINN;
#pragma unroll
        for (int i = 0; i < 8; i++) {
            int idx = tid + 256 * i;
            int r = idx >> 4, cg = idx & 15;
            int gr = row0 + r, k = k0 + cg * 4;
            if (gr < NN && k < 2000)
                va[i] = *reinterpret_cast<const float4*>(&hb[(long long)gr * DINN + k]);
            else
                va[i] = make_float4(0.f, 0.f, 0.f, 0.f);
        }
        int kg = m * 2048 + k0;
#pragma unroll
        for (int i = 0; i < 2; i++) {
            int idx = tid + 256 * i;
            int r = idx >> 3, cg = idx & 7;
            vbh[i] = *reinterpret_cast<const uint4*>(&g_Bhi[r * 4096 + kg + cg * 8]);
            vbl[i] = *reinterpret_cast<const uint4*>(&g_Blo[r * 4096 + kg + cg * 8]);
        }
    };

    auto sts = [&](int buf) {
        uint32_t aH = SM_A + buf * 32768, aL = aH + 16384;
#pragma unroll
        for (int i = 0; i < 8; i++) {
            int idx = tid + 256 * i;
            int r = idx >> 4, cg = idx & 15;
            float4 v = va[i];
            __nv_bfloat162 h01 = __floats2bfloat162_rn(v.x, v.y);
            __nv_bfloat162 h23 = __floats2bfloat162_rn(v.z, v.w);
            float2 f01 = __bfloat1622float2(h01);
            float2 f23 = __bfloat1622float2(h23);
            __nv_bfloat162 l01 = __floats2bfloat162_rn(v.x - f01.x, v.y - f01.y);
            __nv_bfloat162 l23 = __floats2bfloat162_rn(v.z - f23.x, v.w - f23.y);
            uint32_t off = (uint32_t)r * 128 + (((uint32_t)cg * 8) ^ (((uint32_t)r & 7) << 4));
            *reinterpret_cast<uint2*>(smem + aH + off) =
                make_uint2(*reinterpret_cast<uint32_t*>(&h01),
                           *reinterpret_cast<uint32_t*>(&h23));
            *reinterpret_cast<uint2*>(smem + aL + off) =
                make_uint2(*reinterpret_cast<uint32_t*>(&l01),
                           *reinterpret_cast<uint32_t*>(&l23));
        }
        uint32_t bH = SM_B + buf * 16384, bL = bH + 8192;
#pragma unroll
        for (int i = 0; i < 2; i++) {
            int idx = tid + 256 * i;
            int r = idx >> 3, cg = idx & 7;
            uint32_t off = (uint32_t)r * 128 + (((uint32_t)cg * 16) ^ (((uint32_t)r & 7) << 4));
            *reinterpret_cast<uint4*>(smem + bH + off) = vbh[i];
            *reinterpret_cast<uint4*>(smem + bL + off) = vbl[i];
        }
    };

    auto compute = [&](int buf) {
        uint32_t aH = SM_A + buf * 32768, aL = aH + 16384;
        uint32_t bH = SM_B + buf * 16384, bL = bH + 8192;
#pragma unroll
        for (int ks = 0; ks < 4; ks++) {
            uint32_t kb = (uint32_t)ks * 32 + four;
            uint32_t o0 = kb ^ xv, o1 = (kb + 16) ^ xv;
            uint32_t aF[2][4], bF[4][2], bF2[4][2];
#pragma unroll
            for (int mt = 0; mt < 2; mt++) {
                uint32_t base = aH + arow + mt * 2048;
                aF[mt][0] = *reinterpret_cast<uint32_t*>(smem + base + o0);
                aF[mt][1] = *reinterpret_cast<uint32_t*>(smem + base + 1024 + o0);
                aF[mt][2] = *reinterpret_cast<uint32_t*>(smem + base + o1);
                aF[mt][3] = *reinterpret_cast<uint32_t*>(smem + base + 1024 + o1);
            }
#pragma unroll
            for (int nt = 0; nt < 4; nt++) {
                uint32_t base = bH + brow + nt * 1024;
                bF[nt][0] = *reinterpret_cast<uint32_t*>(smem + base + o0);
                bF[nt][1] = *reinterpret_cast<uint32_t*>(smem + base + o1);
            }
#pragma unroll
            for (int mt = 0; mt < 2; mt++)
#pragma unroll
                for (int nt = 0; nt < 4; nt++) MMA(c_[mt][nt], aF[mt], bF[nt]);
            // term 2: Ah x Bl
#pragma unroll
            for (int nt = 0; nt < 4; nt++) {
                uint32_t base = bL + brow + nt * 1024;
                bF2[nt][0] = *reinterpret_cast<uint32_t*>(smem + base + o0);
                bF2[nt][1] = *reinterpret_cast<uint32_t*>(smem + base + o1);
            }
#pragma unroll
            for (int mt = 0; mt < 2; mt++)
#pragma unroll
                for (int nt = 0; nt < 4; nt++) MMA(c_[mt][nt], aF[mt], bF2[nt]);
            // term 3: Al x Bh (reuse bF)
#pragma unroll
            for (int mt = 0; mt < 2; mt++) {
                uint32_t base = aL + arow + mt * 2048;
                aF[mt][0] = *reinterpret_cast<uint32_t*>(smem + base + o0);
                aF[mt][1] = *reinterpret_cast<uint32_t*>(smem + base + 1024 + o0);
                aF[mt][2] = *reinterpret_cast<uint32_t*>(smem + base + o1);
                aF[mt][3] = *reinterpret_cast<uint32_t*>(smem + base + 1024 + o1);
            }
#pragma unroll
            for (int mt = 0; mt < 2; mt++)
#pragma unroll
                for (int nt = 0; nt < 4; nt++) MMA(c_[mt][nt], aF[mt], bF[nt]);
        }
    };

    ldg(0);
    sts(0);
    __syncthreads();
    for (int c = 0; c < 64; c++) {
        int buf = c & 1;
        bool more = (c + 1 < 64);
        if (more) ldg(c + 1);
        compute(buf);
        if (more) {
            sts(buf ^ 1);
            __syncthreads();
        }
    }

    // epilogue: xw0 = cs * (acc + cprime)
    int base_r = row0 + wm * 32 + g;
    int col0 = wn * 32 + (lane & 3) * 2;
#pragma unroll
    for (int mt = 0; mt < 2; mt++) {
#pragma unroll
        for (int rr = 0; rr < 2; rr++) {
            int gr = base_r + mt * 16 + rr * 8;
            if (gr < NN) {
                float csv = g_cs[gr];
#pragma unroll
                for (int nt = 0; nt < 4; nt++) {
                    int col = col0 + nt * 8;
                    float2 cp = *reinterpret_cast<float2*>(smem + SM_CPR + col * 4);
                    float2 o;
                    o.x = csv * (c_[mt][nt][rr * 2 + 0] + cp.x);
                    o.y = csv * (c_[mt][nt][rr * 2 + 1] + cp.y);
                    *reinterpret_cast<float2*>(&g_xw0[gr * 64 + col]) = o;
                }
            }
        }
    }
}

// ---------------- edge scatters ----------------
__global__ void k_scat64(const int* __restrict__ src, const int* __restrict__ dst) {
    long long idx = (long long)blockIdx.x * 256 + threadIdx.x;
    if (idx >= (long long)EE * 16) return;
    int e = (int)(idx >> 4), c = (int)(idx & 15);
    int s = src[e], d = dst[e];
    float4 v = *reinterpret_cast<const float4*>(&g_xw0[s * 64 + c * 4]);
    atomicAdd(reinterpret_cast<float4*>(&g_agg0[d * 64 + c * 4]), v);
}

__global__ void k_scat32(const int* __restrict__ src, const int* __restrict__ dst) {
    long long idx = (long long)blockIdx.x * 256 + threadIdx.x;
    if (idx >= (long long)EE * 8) return;
    int e = (int)(idx >> 3), c = (int)(idx & 7);
    int s = src[e], d = dst[e];
    float4 v = *reinterpret_cast<const float4*>(&g_xw1[s * 32 + c * 4]);
    atomicAdd(reinterpret_cast<float4*>(&g_agg1[d * 32 + c * 4]), v);
}

__global__ void k_scat4(const int* __restrict__ src, const int* __restrict__ dst) {
    int e = blockIdx.x * 256 + threadIdx.x;
    if (e >= EE) return;
    int s = src[e], d = dst[e];
    float4 v = *reinterpret_cast<const float4*>(&g_xw2[s * 4]);
    atomicAdd(reinterpret_cast<float4*>(&g_agg2[d * 4]), v);
}

// ---------------- fused relu/bias/norm + tiny GEMMs ----------------
__global__ void k_conv1(const float* __restrict__ bg0, const float* __restrict__ Wg1) {
    __shared__ float sW[64 * 32];
    __shared__ float sx[8][64];
    int t = threadIdx.x;
    int n0 = blockIdx.x * 8;
    for (int i = t; i < 2048; i += 128) sW[i] = Wg1[i];
    for (int idx = t; idx < 512; idx += 128) {
        int r = idx >> 6, d = idx & 63;
        int n = n0 + r;
        float v = 0.f;
        if (n < NN)
            v = fmaxf(g_agg0[n * 64 + d] * g_cd[n] + bg0[d], 0.f) * g_cs[n];
        sx[r][d] = v;
    }
    __syncthreads();
#pragma unroll
    for (int p = 0; p < 2; p++) {
        int o = t + p * 128;
        int r = o >> 5, l = o & 31;
        int n = n0 + r;
        if (n < NN) {
            float acc = 0.f;
#pragma unroll
            for (int d = 0; d < 64; d++) acc += sx[r][d] * sW[d * 32 + l];
            g_xw1[n * 32 + l] = acc;
        }
    }
}

__global__ void k_conv2(const float* __restrict__ bg1, const float* __restrict__ Wg2) {
    __shared__ float sW[32 * 4];
    __shared__ float sx[16][32];
    int t = threadIdx.x;
    int n0 = blockIdx.x * 16;
    if (t < 128) sW[t] = Wg2[t];
    for (int idx = t; idx < 512; idx += 128) {
        int r = idx >> 5, d = idx & 31;
        int n = n0 + r;
        float v = 0.f;
        if (n < NN)
            v = fmaxf(g_agg1[n * 32 + d] * g_cd[n] + bg1[d], 0.f) * g_cs[n];
        sx[r][d] = v;
    }
    __syncthreads();
    if (t < 64) {
        int r = t >> 2, j = t & 3;
        int n = n0 + r;
        if (n < NN) {
            float acc = 0.f;
#pragma unroll
            for (int d = 0; d < 32; d++) acc += sx[r][d] * sW[d * 4 + j];
            g_xw2[n * 4 + j] = acc;
        }
    }
}

__global__ void k_final(const float* __restrict__ bg2, float* __restrict__ out) {
    int idx = blockIdx.x * 256 + threadIdx.x;
    if (idx < NN * 4) {
        int n = idx >> 2, j = idx & 3;
        out[idx] = g_agg2[idx] * g_cd[n] + bg2[j];
    }
}

// ---------------- launch ----------------
extern "C" void kernel_launch(void* const* d_in, const int* in_sizes, int n_in,
                              void* d_out, int out_size) {
    const float* h   = (const float*)d_in[0];
    const int*   src = (const int*)d_in[1];
    const int*   dst = (const int*)d_in[2];
    const float* W1  = (const float*)d_in[3];
    const float* b1  = (const float*)d_in[4];
    const float* g1  = (const float*)d_in[5];
    const float* be1 = (const float*)d_in[6];
    const float* m1  = (const float*)d_in[7];
    const float* v1  = (const float*)d_in[8];
    const float* W2  = (const float*)d_in[9];
    const float* b2  = (const float*)d_in[10];
    const float* g2  = (const float*)d_in[11];
    const float* be2 = (const float*)d_in[12];
    const float* m2  = (const float*)d_in[13];
    const float* v2  = (const float*)d_in[14];
    const float* Wd  = (const float*)d_in[15];
    const float* bd  = (const float*)d_in[16];
    const float* Wg0 = (const float*)d_in[17];
    const float* bg0 = (const float*)d_in[18];
    const float* Wg1 = (const float*)d_in[19];
    const float* bg1 = (const float*)d_in[20];
    const float* Wg2 = (const float*)d_in[21];
    const float* bg2 = (const float*)d_in[22];
    float* out = (float*)d_out;

    cudaFuncSetAttribute(k_gemm_hmma, cudaFuncAttributeMaxDynamicSharedMemorySize,
                         SMEM_BYTES);

    k_zero_deg<<<(NN + 255) / 256, 256>>>();
    k_zero_aggs<<<(NN * 64 + 255) / 256, 256>>>();
    k_deg<<<(EE + 255) / 256, 256>>>(src, dst);
    k_norm<<<(NN + 255) / 256, 256>>>();

    k_prep<<<1, 512>>>(b1, g1, be1, m1, v1, W2, b2, g2, be2, m2, v2, Wd, bd, Wg0);
    k_wde2<<<dim3(128, 2), 64>>>(Wd, Wg0);
    k_T<<<dim3(250, 2), 128>>>(W1, W2);
    k_M<<<dim3(250, 2), 64>>>();
    k_bsplit<<<(64 * 4096 + 255) / 256, 256>>>();

    k_gemm_hmma<<<(NN + 127) / 128, 256, SMEM_BYTES>>>(h);

    k_scat64<<<(int)(((long long)EE * 16 + 255) / 256), 256>>>(src, dst);
    k_conv1<<<(NN + 7) / 8, 128>>>(bg0, Wg1);
    k_scat32<<<(int)(((long long)EE * 8 + 255) / 256), 256>>>(src, dst);
    k_conv2<<<(NN + 15) / 16, 128>>>(bg1, Wg2);
    k_scat4<<<(EE + 255) / 256, 256>>>(src, dst);
    k_final<<<(NN * 4 + 255) / 256, 256>>>(bg2, out);
}

// round 4
// speedup vs baseline: 1.8541x; 1.0323x over previous
#include <cuda_runtime.h>
#include <cuda_bf16.h>
#include <cstdint>

#define NN   50000
#define EE   1600000
#define DINN 2000

// ---------------- device scratch (allocation-free contract) ----------------
__device__ float g_alpha1[2 * 500];
__device__ float g_bb1[2 * 500];
__device__ float g_alpha2[2 * 128];
__device__ float g_t2b[2 * 128];
__device__ float g_cmean[64];
__device__ float g_cprime[64];
__device__ float g_Wde2[2 * 128 * 64];      // 0.5 * alpha2[l] * (Wd @ Wg0)
__device__ float g_T[2 * 2000 * 128];       // (W1*alpha1) @ W2
__device__ __nv_bfloat16 g_Bhi[64 * 4096];  // [e][m*2048+k] split-high of folded M^T
__device__ __nv_bfloat16 g_Blo[64 * 4096];  // split-low (padding stays zero-init)
__device__ float g_xw0[NN * 64];
__device__ float g_xw1[NN * 32];
__device__ float g_xw2[NN * 4];
__device__ float g_cs[NN];
__device__ float g_cd[NN];
__device__ int   g_degS[NN];
__device__ int   g_degD[NN];
__device__ int   g_off[NN + 1];
__device__ int   g_cur[NN];
__device__ int   g_esrc[EE];

// ---------------- PTX helpers ----------------
__device__ __forceinline__ uint32_t smem_u32(const void* p) {
    uint32_t a;
    asm("{ .reg .u64 t; cvta.to.shared.u64 t, %1; cvt.u32.u64 %0, t; }"
        : "=r"(a) : "l"(p));
    return a;
}

#define LDSM4(r, a) \
    asm volatile("ldmatrix.sync.aligned.m8n8.x4.shared.b16 {%0,%1,%2,%3}, [%4];" \
                 : "=r"((r)[0]), "=r"((r)[1]), "=r"((r)[2]), "=r"((r)[3]) : "r"(a))

#define MMA2(c, a, b0, b1) \
    asm volatile( \
        "mma.sync.aligned.m16n8k16.row.col.f32.bf16.bf16.f32 " \
        "{%0,%1,%2,%3}, {%4,%5,%6,%7}, {%8,%9}, {%0,%1,%2,%3};" \
        : "+f"((c)[0]), "+f"((c)[1]), "+f"((c)[2]), "+f"((c)[3]) \
        : "r"((a)[0]), "r"((a)[1]), "r"((a)[2]), "r"((a)[3]), \
          "r"(b0), "r"(b1))

// ---------------- L1: zero degree counters ----------------
__global__ void k_zero() {
    int i = blockIdx.x * 256 + threadIdx.x;
    if (i < NN) { g_degS[i] = 0; g_degD[i] = 0; }
}

// ---------------- L2: degrees ----------------
__global__ void k_deg(const int* __restrict__ src, const int* __restrict__ dst) {
    int i = blockIdx.x * 256 + threadIdx.x;
    if (i < EE) {
        atomicAdd(&g_degS[src[i]], 1);
        atomicAdd(&g_degD[dst[i]], 1);
    }
}

// ---------------- L3: norms + bias-chain fold (fused via block branch) ----------
__global__ void k_normprep(const float* __restrict__ b1, const float* __restrict__ g1,
                           const float* __restrict__ be1, const float* __restrict__ m1,
                           const float* __restrict__ v1, const float* __restrict__ W2,
                           const float* __restrict__ b2, const float* __restrict__ g2,
                           const float* __restrict__ be2, const float* __restrict__ m2,
                           const float* __restrict__ v2, const float* __restrict__ Wd,
                           const float* __restrict__ bd, const float* __restrict__ Wg0) {
    if (blockIdx.x < 98) {
        int i = blockIdx.x * 512 + threadIdx.x;
        if (i < NN) {
            g_cs[i] = rsqrtf(fmaxf((float)g_degS[i], 1.0f));
            g_cd[i] = rsqrtf(fmaxf((float)g_degD[i], 1.0f));
        }
        return;
    }
    int t = threadIdx.x;
    for (int i = t; i < 1000; i += 512) {
        float a = g1[i] * rsqrtf(v1[i] + 1e-5f);
        g_alpha1[i] = a;
        g_bb1[i] = (b1[i] - m1[i]) * a + be1[i];
    }
    for (int i = t; i < 256; i += 512)
        g_alpha2[i] = g2[i] * rsqrtf(v2[i] + 1e-5f);
    __syncthreads();
    for (int i = t; i < 256; i += 512) {
        int mm = i >> 7, l = i & 127;
        float s = 0.f;
        for (int j = 0; j < 500; j++)
            s += g_bb1[mm * 500 + j] * W2[mm * 64000 + j * 128 + l];
        g_t2b[i] = (s + b2[i] - m2[i]) * g_alpha2[i] + be2[i];
    }
    __syncthreads();
    for (int d = t; d < 64; d += 512) {
        float s = 0.f;
        for (int mm = 0; mm < 2; mm++) {
            float sm = bd[mm * 64 + d];
            for (int l = 0; l < 128; l++)
                sm += g_t2b[mm * 128 + l] * Wd[mm * 8192 + l * 64 + d];
            s += sm;
        }
        g_cmean[d] = 0.5f * s;
    }
    __syncthreads();
    for (int e = t; e < 64; e += 512) {
        float s = 0.f;
        for (int d = 0; d < 64; d++) s += g_cmean[d] * Wg0[d * 64 + e];
        g_cprime[e] = s;
    }
}

// ---------------- L4: Wde2 + T (fused via block branch) ----------------
__global__ void k_wT(const float* __restrict__ Wd, const float* __restrict__ Wg0,
                     const float* __restrict__ W1, const float* __restrict__ W2) {
    __shared__ float sA[8][500];
    int b = blockIdx.x;
    if (b < 256) {
        if (threadIdx.x < 64) {
            int m = b >> 7, l = b & 127, e = threadIdx.x;
            float s = 0.f;
            for (int d = 0; d < 64; d++)
                s += Wd[m * 8192 + l * 64 + d] * Wg0[d * 64 + e];
            g_Wde2[m * 8192 + l * 64 + e] = 0.5f * g_alpha2[m * 128 + l] * s;
        }
        return;
    }
    int bb = b - 256;
    int m = bb / 250, i0 = (bb % 250) * 8, t = threadIdx.x;
    for (int idx = t; idx < 4000; idx += 128) {
        int r = idx / 500, j = idx - r * 500;
        sA[r][j] = W1[m * 1000000 + (i0 + r) * 500 + j] * g_alpha1[m * 500 + j];
    }
    __syncthreads();
    int l = t;
    float acc[8] = {0, 0, 0, 0, 0, 0, 0, 0};
    for (int j = 0; j < 500; j++) {
        float w = W2[m * 64000 + j * 128 + l];
#pragma unroll
        for (int r = 0; r < 8; r++) acc[r] += sA[r][j] * w;
    }
#pragma unroll
    for (int r = 0; r < 8; r++) g_T[m * 256000 + (i0 + r) * 128 + l] = acc[r];
}

// ---------------- L5: M = T @ Wde2, immediately split to bf16 hi/lo ------------
__global__ void k_Msplit() {
    __shared__ float sT[8][128];
    int m = blockIdx.y, i0 = blockIdx.x * 8, t = threadIdx.x;  // 64 threads
    for (int idx = t; idx < 1024; idx += 64) {
        int r = idx >> 7, l = idx & 127;
        sT[r][l] = g_T[m * 256000 + (i0 + r) * 128 + l];
    }
    __syncthreads();
    int e = t;
    float acc[8] = {0, 0, 0, 0, 0, 0, 0, 0};
    for (int l = 0; l < 128; l++) {
        float w = g_Wde2[m * 8192 + l * 64 + e];
#pragma unroll
        for (int r = 0; r < 8; r++) acc[r] += sT[r][l] * w;
    }
#pragma unroll
    for (int r = 0; r < 8; r++) {
        int i = i0 + r;
        float v = acc[r];
        __nv_bfloat16 hi = __float2bfloat16(v);
        g_Bhi[e * 4096 + m * 2048 + i] = hi;
        g_Blo[e * 4096 + m * 2048 + i] = __float2bfloat16(v - __bfloat162float(hi));
    }
}

// ---------------- L6: HMMA GEMM: xw0 = cs * (sum_m h_m @ M_m + c') --------------
// Block tile 128x64, 8 warps 4(M)x2(N), warp tile 32x32, K-chunk 64.
// bf16 hi/lo 3-term split: Ah*Bh + Ah*Bl + Al*Bh. ldmatrix fragment loads.
#define SM_CPR 0
#define SM_A   1024                 // 2 buf x (hi 16KB + lo 16KB)
#define SM_B   (1024 + 65536)       // 2 buf x (hi 8KB + lo 8KB)
#define SMEM_BYTES (1024 + 65536 + 32768)

__global__ __launch_bounds__(256) void k_gemm_hmma(const float* __restrict__ h) {
    extern __shared__ __align__(1024) char smem[];
    uint32_t sbase = smem_u32(smem);
    int tid = threadIdx.x;
    int lane = tid & 31, wid = tid >> 5;
    int wm = wid >> 1, wn = wid & 1;
    int row0 = blockIdx.x * 128;

    if (tid < 64) *reinterpret_cast<float*>(smem + SM_CPR + tid * 4) = g_cprime[tid];

    // ldmatrix per-lane addressing
    uint32_t swz = (uint32_t)(lane & 7) << 4;
    uint32_t aoff = (uint32_t)(wm * 32 + (lane & 15)) * 128;
    uint32_t acolsel = (uint32_t)(lane >> 4) << 4;
    uint32_t boff = (uint32_t)(wn * 32 + lane) * 128;

    float c_[2][4][4];
#pragma unroll
    for (int mt = 0; mt < 2; mt++)
#pragma unroll
        for (int nt = 0; nt < 4; nt++)
#pragma unroll
            for (int q = 0; q < 4; q++) c_[mt][nt][q] = 0.f;

    float4 va[8];
    uint4 vbh[2], vbl[2];

    auto ldg = [&](int c) {
        int m = c >> 5, k0 = (c & 31) * 64;
        const float* hb = h + (long long)m * NN * DINN;
#pragma unroll
        for (int i = 0; i < 8; i++) {
            int idx = tid + 256 * i;
            int r = idx >> 4, cg = idx & 15;
            int gr = row0 + r, k = k0 + cg * 4;
            if (gr < NN && k < 2000)
                va[i] = *reinterpret_cast<const float4*>(&hb[(long long)gr * DINN + k]);
            else
                va[i] = make_float4(0.f, 0.f, 0.f, 0.f);
        }
        int kg = m * 2048 + k0;
#pragma unroll
        for (int i = 0; i < 2; i++) {
            int idx = tid + 256 * i;
            int r = idx >> 3, cg = idx & 7;
            vbh[i] = *reinterpret_cast<const uint4*>(&g_Bhi[r * 4096 + kg + cg * 8]);
            vbl[i] = *reinterpret_cast<const uint4*>(&g_Blo[r * 4096 + kg + cg * 8]);
        }
    };

    auto sts = [&](int buf) {
        uint32_t aH = SM_A + buf * 32768, aL = aH + 16384;
#pragma unroll
        for (int i = 0; i < 8; i++) {
            int idx = tid + 256 * i;
            int r = idx >> 4, cg = idx & 15;
            float4 v = va[i];
            __nv_bfloat162 h01 = __floats2bfloat162_rn(v.x, v.y);
            __nv_bfloat162 h23 = __floats2bfloat162_rn(v.z, v.w);
            float2 f01 = __bfloat1622float2(h01);
            float2 f23 = __bfloat1622float2(h23);
            __nv_bfloat162 l01 = __floats2bfloat162_rn(v.x - f01.x, v.y - f01.y);
            __nv_bfloat162 l23 = __floats2bfloat162_rn(v.z - f23.x, v.w - f23.y);
            uint32_t off = (uint32_t)r * 128 + (((uint32_t)cg * 8) ^ (((uint32_t)r & 7) << 4));
            *reinterpret_cast<uint2*>(smem + aH + off) =
                make_uint2(*reinterpret_cast<uint32_t*>(&h01),
                           *reinterpret_cast<uint32_t*>(&h23));
            *reinterpret_cast<uint2*>(smem + aL + off) =
                make_uint2(*reinterpret_cast<uint32_t*>(&l01),
                           *reinterpret_cast<uint32_t*>(&l23));
        }
        uint32_t bH = SM_B + buf * 16384, bL = bH + 8192;
#pragma unroll
        for (int i = 0; i < 2; i++) {
            int idx = tid + 256 * i;
            int r = idx >> 3, cg = idx & 7;
            uint32_t off = (uint32_t)r * 128 + (((uint32_t)cg * 16) ^ (((uint32_t)r & 7) << 4));
            *reinterpret_cast<uint4*>(smem + bH + off) = vbh[i];
            *reinterpret_cast<uint4*>(smem + bL + off) = vbl[i];
        }
    };

    auto compute = [&](int buf) {
        uint32_t aH = sbase + SM_A + buf * 32768, aL = aH + 16384;
        uint32_t bH = sbase + SM_B + buf * 16384, bL = bH + 8192;
#pragma unroll
        for (int ks = 0; ks < 4; ks++) {
            uint32_t kb = (uint32_t)ks * 32;
            uint32_t aFh[2][4], aFl[2][4];
            uint32_t b0h[4], b1h[4], b0l[4], b1l[4];
#pragma unroll
            for (int mt = 0; mt < 2; mt++) {
                uint32_t adr = aoff + (uint32_t)mt * 2048 + ((kb + acolsel) ^ swz);
                LDSM4(aFh[mt], aH + adr);
                LDSM4(aFl[mt], aL + adr);
            }
            LDSM4(b0h, bH + boff + ((kb + 0) ^ swz));
            LDSM4(b1h, bH + boff + ((kb + 16) ^ swz));
            LDSM4(b0l, bL + boff + ((kb + 0) ^ swz));
            LDSM4(b1l, bL + boff + ((kb + 16) ^ swz));
#pragma unroll
            for (int mt = 0; mt < 2; mt++)
#pragma unroll
                for (int nt = 0; nt < 4; nt++) {
                    MMA2(c_[mt][nt], aFh[mt], b0h[nt], b1h[nt]);
                    MMA2(c_[mt][nt], aFh[mt], b0l[nt], b1l[nt]);
                    MMA2(c_[mt][nt], aFl[mt], b0h[nt], b1h[nt]);
                }
        }
    };

    ldg(0);
    sts(0);
    __syncthreads();
    for (int c = 0; c < 64; c++) {
        int buf = c & 1;
        bool more = (c + 1 < 64);
        if (more) ldg(c + 1);
        compute(buf);
        if (more) {
            sts(buf ^ 1);
            __syncthreads();
        }
    }

    // epilogue: xw0 = cs * (acc + cprime)
    int g = lane >> 2;
    int base_r = row0 + wm * 32 + g;
    int col0 = wn * 32 + (lane & 3) * 2;
#pragma unroll
    for (int mt = 0; mt < 2; mt++) {
#pragma unroll
        for (int rr = 0; rr < 2; rr++) {
            int gr = base_r + mt * 16 + rr * 8;
            if (gr < NN) {
                float csv = g_cs[gr];
#pragma unroll
                for (int nt = 0; nt < 4; nt++) {
                    int col = col0 + nt * 8;
                    float2 cp = *reinterpret_cast<float2*>(smem + SM_CPR + col * 4);
                    float2 o;
                    o.x = csv * (c_[mt][nt][rr * 2 + 0] + cp.x);
                    o.y = csv * (c_[mt][nt][rr * 2 + 1] + cp.y);
                    *reinterpret_cast<float2*>(&g_xw0[gr * 64 + col]) = o;
                }
            }
        }
    }
}

// ---------------- L7: exclusive scan of in-degrees -> CSR offsets --------------
__global__ void k_scan() {
    __shared__ int sd[1024];
    int t = threadIdx.x;
    int running = 0;
    for (int c0 = 0; c0 < NN; c0 += 1024) {
        int idx = c0 + t;
        int v = (idx < NN) ? g_degD[idx] : 0;
        sd[t] = v;
        __syncthreads();
        for (int s = 1; s < 1024; s <<= 1) {
            int x = (t >= s) ? sd[t - s] : 0;
            __syncthreads();
            sd[t] += x;
            __syncthreads();
        }
        if (idx < NN) {
            int excl = running + sd[t] - v;
            g_off[idx] = excl;
            g_cur[idx] = excl;
        }
        running += sd[1023];
        __syncthreads();
    }
    if (t == 0) g_off[NN] = running;
}

// ---------------- L8: fill CSR (src ids sorted by dst) ----------------
__global__ void k_fill(const int* __restrict__ src, const int* __restrict__ dst) {
    int e = blockIdx.x * 256 + threadIdx.x;
    if (e < EE) {
        int pos = atomicAdd(&g_cur[dst[e]], 1);
        g_esrc[pos] = src[e];
    }
}

// ---------------- L9: gather xw0 + relu/bias/norm + GEMV 64->32 -> xw1 ---------
__global__ __launch_bounds__(128) void k_g64(const float* __restrict__ bg0,
                                             const float* __restrict__ Wg1) {
    __shared__ float sW[64 * 32];
    __shared__ float sb[64];
    int t = threadIdx.x;
    for (int i = t; i < 2048; i += 128) sW[i] = Wg1[i];
    if (t < 64) sb[t] = bg0[t];
    __syncthreads();
    int wid = t >> 5, lane = t & 31;
    int n = blockIdx.x * 4 + wid;
    if (n >= NN) return;
    int beg = g_off[n], end = g_off[n + 1];
    int half = lane >> 4, l16 = lane & 15;
    float4 acc = make_float4(0.f, 0.f, 0.f, 0.f);
    int i = beg + half;
    while (i + 6 < end) {
        int s0 = g_esrc[i], s1 = g_esrc[i + 2], s2 = g_esrc[i + 4], s3 = g_esrc[i + 6];
        float4 v0 = *reinterpret_cast<const float4*>(&g_xw0[s0 * 64 + l16 * 4]);
        float4 v1 = *reinterpret_cast<const float4*>(&g_xw0[s1 * 64 + l16 * 4]);
        float4 v2 = *reinterpret_cast<const float4*>(&g_xw0[s2 * 64 + l16 * 4]);
        float4 v3 = *reinterpret_cast<const float4*>(&g_xw0[s3 * 64 + l16 * 4]);
        acc.x += v0.x + v1.x + v2.x + v3.x;
        acc.y += v0.y + v1.y + v2.y + v3.y;
        acc.z += v0.z + v1.z + v2.z + v3.z;
        acc.w += v0.w + v1.w + v2.w + v3.w;
        i += 8;
    }
    while (i < end) {
        int s = g_esrc[i];
        float4 v = *reinterpret_cast<const float4*>(&g_xw0[s * 64 + l16 * 4]);
        acc.x += v.x; acc.y += v.y; acc.z += v.z; acc.w += v.w;
        i += 2;
    }
    acc.x += __shfl_xor_sync(0xFFFFFFFFu, acc.x, 16);
    acc.y += __shfl_xor_sync(0xFFFFFFFFu, acc.y, 16);
    acc.z += __shfl_xor_sync(0xFFFFFFFFu, acc.z, 16);
    acc.w += __shfl_xor_sync(0xFFFFFFFFu, acc.w, 16);
    float cdv = g_cd[n], csv = g_cs[n];
    float val[4];
    val[0] = fmaxf(fmaf(acc.x, cdv, sb[l16 * 4 + 0]), 0.f) * csv;
    val[1] = fmaxf(fmaf(acc.y, cdv, sb[l16 * 4 + 1]), 0.f) * csv;
    val[2] = fmaxf(fmaf(acc.z, cdv, sb[l16 * 4 + 2]), 0.f) * csv;
    val[3] = fmaxf(fmaf(acc.w, cdv, sb[l16 * 4 + 3]), 0.f) * csv;
    float o = 0.f;
#pragma unroll
    for (int d = 0; d < 64; d++) {
        float v = __shfl_sync(0xFFFFFFFFu, val[d & 3], d >> 2);
        o = fmaf(v, sW[d * 32 + lane], o);
    }
    g_xw1[n * 32 + lane] = o;
}

// ---------------- L10: gather xw1 + relu/bias/norm + GEMV 32->4 -> xw2 ---------
__global__ __launch_bounds__(128) void k_g32(const float* __restrict__ bg1,
                                             const float* __restrict__ Wg2) {
    __shared__ float sW[32 * 4];
    __shared__ float sb[32];
    int t = threadIdx.x;
    if (t < 128) sW[t] = Wg2[t];
    if (t < 32) sb[t] = bg1[t];
    __syncthreads();
    int wid = t >> 5, lane = t & 31;
    int n = blockIdx.x * 4 + wid;
    if (n >= NN) return;
    int beg = g_off[n], end = g_off[n + 1];
    int q = lane >> 3, l8 = lane & 7;
    float4 acc = make_float4(0.f, 0.f, 0.f, 0.f);
    int i = beg + q;
    while (i + 12 < end) {
        int s0 = g_esrc[i], s1 = g_esrc[i + 4], s2 = g_esrc[i + 8], s3 = g_esrc[i + 12];
        float4 v0 = *reinterpret_cast<const float4*>(&g_xw1[s0 * 32 + l8 * 4]);
        float4 v1 = *reinterpret_cast<const float4*>(&g_xw1[s1 * 32 + l8 * 4]);
        float4 v2 = *reinterpret_cast<const float4*>(&g_xw1[s2 * 32 + l8 * 4]);
        float4 v3 = *reinterpret_cast<const float4*>(&g_xw1[s3 * 32 + l8 * 4]);
        acc.x += v0.x + v1.x + v2.x + v3.x;
        acc.y += v0.y + v1.y + v2.y + v3.y;
        acc.z += v0.z + v1.z + v2.z + v3.z;
        acc.w += v0.w + v1.w + v2.w + v3.w;
        i += 16;
    }
    while (i < end) {
        int s = g_esrc[i];
        float4 v = *reinterpret_cast<const float4*>(&g_xw1[s * 32 + l8 * 4]);
        acc.x += v.x; acc.y += v.y; acc.z += v.z; acc.w += v.w;
        i += 4;
    }
    acc.x += __shfl_xor_sync(0xFFFFFFFFu, acc.x, 8);
    acc.y += __shfl_xor_sync(0xFFFFFFFFu, acc.y, 8);
    acc.z += __shfl_xor_sync(0xFFFFFFFFu, acc.z, 8);
    acc.w += __shfl_xor_sync(0xFFFFFFFFu, acc.w, 8);
    acc.x += __shfl_xor_sync(0xFFFFFFFFu, acc.x, 16);
    acc.y += __shfl_xor_sync(0xFFFFFFFFu, acc.y, 16);
    acc.z += __shfl_xor_sync(0xFFFFFFFFu, acc.z, 16);
    acc.w += __shfl_xor_sync(0xFFFFFFFFu, acc.w, 16);
    float cdv = g_cd[n], csv = g_cs[n];
    float val[4];
    val[0] = fmaxf(fmaf(acc.x, cdv, sb[l8 * 4 + 0]), 0.f) * csv;
    val[1] = fmaxf(fmaf(acc.y, cdv, sb[l8 * 4 + 1]), 0.f) * csv;
    val[2] = fmaxf(fmaf(acc.z, cdv, sb[l8 * 4 + 2]), 0.f) * csv;
    val[3] = fmaxf(fmaf(acc.w, cdv, sb[l8 * 4 + 3]), 0.f) * csv;
    float o = 0.f;
#pragma unroll
    for (int d = 0; d < 32; d++) {
        float v = __shfl_sync(0xFFFFFFFFu, val[d & 3], d >> 2);
        o = fmaf(v, sW[d * 4 + (lane & 3)], o);
    }
    if (lane < 4) g_xw2[n * 4 + lane] = o;
}

// ---------------- L11: gather xw2 + bias -> out ----------------
__global__ __launch_bounds__(128) void k_g4(const float* __restrict__ bg2,
                                            float* __restrict__ out) {
    int t = threadIdx.x;
    int wid = t >> 5, lane = t & 31;
    int n = blockIdx.x * 4 + wid;
    if (n >= NN) return;
    int beg = g_off[n], end = g_off[n + 1];
    float4 acc = make_float4(0.f, 0.f, 0.f, 0.f);
    for (int i = beg + lane; i < end; i += 32) {
        int s = g_esrc[i];
        float4 v = *reinterpret_cast<const float4*>(&g_xw2[s * 4]);
        acc.x += v.x; acc.y += v.y; acc.z += v.z; acc.w += v.w;
    }
#pragma unroll
    for (int off = 16; off >= 1; off >>= 1) {
        acc.x += __shfl_xor_sync(0xFFFFFFFFu, acc.x, off);
        acc.y += __shfl_xor_sync(0xFFFFFFFFu, acc.y, off);
        acc.z += __shfl_xor_sync(0xFFFFFFFFu, acc.z, off);
        acc.w += __shfl_xor_sync(0xFFFFFFFFu, acc.w, off);
    }
    if (lane == 0) {
        float cdv = g_cd[n];
        float4 o;
        o.x = fmaf(acc.x, cdv, bg2[0]);
        o.y = fmaf(acc.y, cdv, bg2[1]);
        o.z = fmaf(acc.z, cdv, bg2[2]);
        o.w = fmaf(acc.w, cdv, bg2[3]);
        *reinterpret_cast<float4*>(&out[n * 4]) = o;
    }
}

// ---------------- launch ----------------
extern "C" void kernel_launch(void* const* d_in, const int* in_sizes, int n_in,
                              void* d_out, int out_size) {
    const float* h   = (const float*)d_in[0];
    const int*   src = (const int*)d_in[1];
    const int*   dst = (const int*)d_in[2];
    const float* W1  = (const float*)d_in[3];
    const float* b1  = (const float*)d_in[4];
    const float* g1  = (const float*)d_in[5];
    const float* be1 = (const float*)d_in[6];
    const float* m1  = (const float*)d_in[7];
    const float* v1  = (const float*)d_in[8];
    const float* W2  = (const float*)d_in[9];
    const float* b2  = (const float*)d_in[10];
    const float* g2  = (const float*)d_in[11];
    const float* be2 = (const float*)d_in[12];
    const float* m2  = (const float*)d_in[13];
    const float* v2  = (const float*)d_in[14];
    const float* Wd  = (const float*)d_in[15];
    const float* bd  = (const float*)d_in[16];
    const float* Wg0 = (const float*)d_in[17];
    const float* bg0 = (const float*)d_in[18];
    const float* Wg1 = (const float*)d_in[19];
    const float* bg1 = (const float*)d_in[20];
    const float* Wg2 = (const float*)d_in[21];
    const float* bg2 = (const float*)d_in[22];
    float* out = (float*)d_out;

    cudaFuncSetAttribute(k_gemm_hmma, cudaFuncAttributeMaxDynamicSharedMemorySize,
                         SMEM_BYTES);

    k_zero<<<(NN + 255) / 256, 256>>>();                       // 1
    k_deg<<<(EE + 255) / 256, 256>>>(src, dst);                // 2
    k_normprep<<<99, 512>>>(b1, g1, be1, m1, v1, W2, b2, g2,   // 3
                            be2, m2, v2, Wd, bd, Wg0);
    k_wT<<<756, 128>>>(Wd, Wg0, W1, W2);                       // 4
    k_Msplit<<<dim3(250, 2), 64>>>();                          // 5
    k_gemm_hmma<<<(NN + 127) / 128, 256, SMEM_BYTES>>>(h);     // 6  <- ncu -s 5
    k_scan<<<1, 1024>>>();                                     // 7
    k_fill<<<(EE + 255) / 256, 256>>>(src, dst);               // 8
    k_g64<<<(NN + 3) / 4, 128>>>(bg0, Wg1);                    // 9
    k_g32<<<(NN + 3) / 4, 128>>>(bg1, Wg2);                    // 10
    k_g4<<<(NN + 3) / 4, 128>>>(bg2, out);                     // 11
}

// round 5
// speedup vs baseline: 1.9770x; 1.0663x over previous
#include <cuda_runtime.h>
#include <cuda_bf16.h>
#include <cstdint>

#define NN   50000
#define EE   1600000
#define DINN 2000

// ---------------- device scratch (allocation-free contract) ----------------
__device__ float g_alpha1[2 * 500];
__device__ float g_bb1[2 * 500];
__device__ float g_alpha2[2 * 128];
__device__ float g_t2b[2 * 128];
__device__ float g_cmean[64];
__device__ float g_cprime[64];
__device__ float g_Wde2[2 * 128 * 64];      // 0.5 * alpha2[l] * (Wd @ Wg0)
__device__ float g_R[2 * 500 * 64];         // W2 @ Wde2
__device__ __nv_bfloat16 g_Bhi[64 * 4096];  // [e][m*2048+k] split-high of folded M^T
__device__ __nv_bfloat16 g_Blo[64 * 4096];  // split-low (padding stays zero-init)
__device__ float g_xw0[NN * 64];            // h@M + c'  (cs applied at gather)
__device__ float g_xw1[NN * 32];
__device__ float g_xw2[NN * 4];
__device__ float g_cs[NN];
__device__ float g_cd[NN];
__device__ int   g_degS[NN];
__device__ int   g_degD[NN];
__device__ int   g_off[NN + 1];
__device__ int   g_cur[NN];
__device__ int   g_esrc[EE];
__device__ int   g_bsum[64];
__device__ int   g_boff[64];

// ---------------- PTX helpers ----------------
__device__ __forceinline__ uint32_t smem_u32(const void* p) {
    uint32_t a;
    asm("{ .reg .u64 t; cvta.to.shared.u64 t, %1; cvt.u32.u64 %0, t; }"
        : "=r"(a) : "l"(p));
    return a;
}

#define LDSM4(r, a) \
    asm volatile("ldmatrix.sync.aligned.m8n8.x4.shared.b16 {%0,%1,%2,%3}, [%4];" \
                 : "=r"((r)[0]), "=r"((r)[1]), "=r"((r)[2]), "=r"((r)[3]) : "r"(a))

#define MMA2(c, a, b0, b1) \
    asm volatile( \
        "mma.sync.aligned.m16n8k16.row.col.f32.bf16.bf16.f32 " \
        "{%0,%1,%2,%3}, {%4,%5,%6,%7}, {%8,%9}, {%0,%1,%2,%3};" \
        : "+f"((c)[0]), "+f"((c)[1]), "+f"((c)[2]), "+f"((c)[3]) \
        : "r"((a)[0]), "r"((a)[1]), "r"((a)[2]), "r"((a)[3]), \
          "r"(b0), "r"(b1))

// ---------------- L1: zero degrees + bias-chain fold + Wde2 ----------------
__global__ void k_fold(const float* __restrict__ b1, const float* __restrict__ g1,
                       const float* __restrict__ be1, const float* __restrict__ m1,
                       const float* __restrict__ v1, const float* __restrict__ W2,
                       const float* __restrict__ b2, const float* __restrict__ g2,
                       const float* __restrict__ be2, const float* __restrict__ m2,
                       const float* __restrict__ v2, const float* __restrict__ Wd,
                       const float* __restrict__ bd, const float* __restrict__ Wg0) {
    if (blockIdx.x < 98) {
        int i = blockIdx.x * 512 + threadIdx.x;
        if (i < NN) { g_degS[i] = 0; g_degD[i] = 0; }
        return;
    }
    __shared__ float sWg0[64 * 64];
    int t = threadIdx.x;
    for (int i = t; i < 1000; i += 512) {
        float a = g1[i] * rsqrtf(v1[i] + 1e-5f);
        g_alpha1[i] = a;
        g_bb1[i] = (b1[i] - m1[i]) * a + be1[i];
    }
    for (int i = t; i < 256; i += 512)
        g_alpha2[i] = g2[i] * rsqrtf(v2[i] + 1e-5f);
    for (int i = t; i < 4096; i += 512) sWg0[i] = Wg0[i];
    __syncthreads();
    for (int i = t; i < 256; i += 512) {
        int mm = i >> 7, l = i & 127;
        float s = 0.f;
        for (int j = 0; j < 500; j++)
            s += g_bb1[mm * 500 + j] * W2[mm * 64000 + j * 128 + l];
        g_t2b[i] = (s + b2[i] - m2[i]) * g_alpha2[i] + be2[i];
    }
    // Wde2[m][l][e] = 0.5*alpha2[m][l]*sum_d Wd[m][l][d]*Wg0[d][e]
    for (int idx = t; idx < 16384; idx += 512) {
        int m = idx >> 13, rem = idx & 8191, l = rem >> 6, e = rem & 63;
        float s = 0.f;
        for (int d = 0; d < 64; d++)
            s += Wd[m * 8192 + l * 64 + d] * sWg0[d * 64 + e];
        g_Wde2[idx] = 0.5f * g_alpha2[m * 128 + l] * s;
    }
    __syncthreads();
    for (int d = t; d < 64; d += 512) {
        float s = 0.f;
        for (int mm = 0; mm < 2; mm++) {
            float sm = bd[mm * 64 + d];
            for (int l = 0; l < 128; l++)
                sm += g_t2b[mm * 128 + l] * Wd[mm * 8192 + l * 64 + d];
            s += sm;
        }
        g_cmean[d] = 0.5f * s;
    }
    __syncthreads();
    for (int e = t; e < 64; e += 512) {
        float s = 0.f;
        for (int d = 0; d < 64; d++) s += g_cmean[d] * sWg0[d * 64 + e];
        g_cprime[e] = s;
    }
}

// ---------------- L2: R[m][j][e] = sum_l W2[m][j][l] * Wde2[m][l][e] ------------
__global__ void k_R(const float* __restrict__ W2) {
    __shared__ float sW2[8][128];
    int m = blockIdx.y, j0 = blockIdx.x * 8, t = threadIdx.x;  // 64 threads
    for (int idx = t; idx < 1024; idx += 64) {
        int r = idx >> 7, l = idx & 127;
        int j = j0 + r;
        sW2[r][l] = (j < 500) ? W2[m * 64000 + j * 128 + l] : 0.f;
    }
    __syncthreads();
    int e = t;
    float acc[8] = {0, 0, 0, 0, 0, 0, 0, 0};
    for (int l = 0; l < 128; l++) {
        float w = g_Wde2[m * 8192 + l * 64 + e];
#pragma unroll
        for (int r = 0; r < 8; r++) acc[r] += sW2[r][l] * w;
    }
#pragma unroll
    for (int r = 0; r < 8; r++) {
        int j = j0 + r;
        if (j < 500) g_R[m * 32000 + j * 64 + e] = acc[r];
    }
}

// ---------------- L3: M = (W1*alpha1) @ R -> bf16 hi/lo split (transposed) ------
__global__ void k_MB(const float* __restrict__ W1) {
    __shared__ float sA[8][500];
    int m = blockIdx.y, i0 = blockIdx.x * 8, t = threadIdx.x;  // 64 threads
    for (int idx = t; idx < 4000; idx += 64) {
        int r = idx / 500, j = idx - r * 500;
        sA[r][j] = W1[m * 1000000 + (i0 + r) * 500 + j] * g_alpha1[m * 500 + j];
    }
    __syncthreads();
    int e = t;
    float acc[8] = {0, 0, 0, 0, 0, 0, 0, 0};
    for (int j = 0; j < 500; j++) {
        float w = g_R[m * 32000 + j * 64 + e];
#pragma unroll
        for (int r = 0; r < 8; r++) acc[r] += sA[r][j] * w;
    }
#pragma unroll
    for (int r = 0; r < 8; r++) {
        int i = i0 + r;
        float v = acc[r];
        __nv_bfloat16 hi = __float2bfloat16(v);
        g_Bhi[e * 4096 + m * 2048 + i] = hi;
        g_Blo[e * 4096 + m * 2048 + i] = __float2bfloat16(v - __bfloat162float(hi));
    }
}

// ---------------- L4: HMMA GEMM: xw0 = sum_m h_m @ M_m + c' ---------------------
// Block tile 128x64, 8 warps 4(M)x2(N), warp tile 32x32, K-chunk 64.
// bf16 hi/lo 3-term split: Ah*Bh + Ah*Bl + Al*Bh. ldmatrix fragment loads.
#define SM_CPR 0
#define SM_A   1024                 // 2 buf x (hi 16KB + lo 16KB)
#define SM_B   (1024 + 65536)       // 2 buf x (hi 8KB + lo 8KB)
#define SMEM_BYTES (1024 + 65536 + 32768)

__global__ __launch_bounds__(256) void k_gemm_hmma(const float* __restrict__ h) {
    extern __shared__ __align__(1024) char smem[];
    uint32_t sbase = smem_u32(smem);
    int tid = threadIdx.x;
    int lane = tid & 31, wid = tid >> 5;
    int wm = wid >> 1, wn = wid & 1;
    int row0 = blockIdx.x * 128;

    if (tid < 64) *reinterpret_cast<float*>(smem + SM_CPR + tid * 4) = g_cprime[tid];

    uint32_t swz = (uint32_t)(lane & 7) << 4;
    uint32_t aoff = (uint32_t)(wm * 32 + (lane & 15)) * 128;
    uint32_t acolsel = (uint32_t)(lane >> 4) << 4;
    uint32_t boff = (uint32_t)(wn * 32 + lane) * 128;

    float c_[2][4][4];
#pragma unroll
    for (int mt = 0; mt < 2; mt++)
#pragma unroll
        for (int nt = 0; nt < 4; nt++)
#pragma unroll
            for (int q = 0; q < 4; q++) c_[mt][nt][q] = 0.f;

    float4 va[8];
    uint4 vbh[2], vbl[2];

    auto ldg = [&](int c) {
        int m = c >> 5, k0 = (c & 31) * 64;
        const float* hb = h + (long long)m * NN * DINN;
#pragma unroll
        for (int i = 0; i < 8; i++) {
            int idx = tid + 256 * i;
            int r = idx >> 4, cg = idx & 15;
            int gr = row0 + r, k = k0 + cg * 4;
            if (gr < NN && k < 2000)
                va[i] = *reinterpret_cast<const float4*>(&hb[(long long)gr * DINN + k]);
            else
                va[i] = make_float4(0.f, 0.f, 0.f, 0.f);
        }
        int kg = m * 2048 + k0;
#pragma unroll
        for (int i = 0; i < 2; i++) {
            int idx = tid + 256 * i;
            int r = idx >> 3, cg = idx & 7;
            vbh[i] = *reinterpret_cast<const uint4*>(&g_Bhi[r * 4096 + kg + cg * 8]);
            vbl[i] = *reinterpret_cast<const uint4*>(&g_Blo[r * 4096 + kg + cg * 8]);
        }
    };

    auto sts = [&](int buf) {
        uint32_t aH = SM_A + buf * 32768, aL = aH + 16384;
#pragma unroll
        for (int i = 0; i < 8; i++) {
            int idx = tid + 256 * i;
            int r = idx >> 4, cg = idx & 15;
            float4 v = va[i];
            __nv_bfloat162 h01 = __floats2bfloat162_rn(v.x, v.y);
            __nv_bfloat162 h23 = __floats2bfloat162_rn(v.z, v.w);
            float2 f01 = __bfloat1622float2(h01);
            float2 f23 = __bfloat1622float2(h23);
            __nv_bfloat162 l01 = __floats2bfloat162_rn(v.x - f01.x, v.y - f01.y);
            __nv_bfloat162 l23 = __floats2bfloat162_rn(v.z - f23.x, v.w - f23.y);
            uint32_t off = (uint32_t)r * 128 + (((uint32_t)cg * 8) ^ (((uint32_t)r & 7) << 4));
            *reinterpret_cast<uint2*>(smem + aH + off) =
                make_uint2(*reinterpret_cast<uint32_t*>(&h01),
                           *reinterpret_cast<uint32_t*>(&h23));
            *reinterpret_cast<uint2*>(smem + aL + off) =
                make_uint2(*reinterpret_cast<uint32_t*>(&l01),
                           *reinterpret_cast<uint32_t*>(&l23));
        }
        uint32_t bH = SM_B + buf * 16384, bL = bH + 8192;
#pragma unroll
        for (int i = 0; i < 2; i++) {
            int idx = tid + 256 * i;
            int r = idx >> 3, cg = idx & 7;
            uint32_t off = (uint32_t)r * 128 + (((uint32_t)cg * 16) ^ (((uint32_t)r & 7) << 4));
            *reinterpret_cast<uint4*>(smem + bH + off) = vbh[i];
            *reinterpret_cast<uint4*>(smem + bL + off) = vbl[i];
        }
    };

    auto compute = [&](int buf) {
        uint32_t aH = sbase + SM_A + buf * 32768, aL = aH + 16384;
        uint32_t bH = sbase + SM_B + buf * 16384, bL = bH + 8192;
#pragma unroll
        for (int ks = 0; ks < 4; ks++) {
            uint32_t kb = (uint32_t)ks * 32;
            uint32_t aFh[2][4], aFl[2][4];
            uint32_t b0h[4], b1h[4], b0l[4], b1l[4];
#pragma unroll
            for (int mt = 0; mt < 2; mt++) {
                uint32_t adr = aoff + (uint32_t)mt * 2048 + ((kb + acolsel) ^ swz);
                LDSM4(aFh[mt], aH + adr);
                LDSM4(aFl[mt], aL + adr);
            }
            LDSM4(b0h, bH + boff + ((kb + 0) ^ swz));
            LDSM4(b1h, bH + boff + ((kb + 16) ^ swz));
            LDSM4(b0l, bL + boff + ((kb + 0) ^ swz));
            LDSM4(b1l, bL + boff + ((kb + 16) ^ swz));
#pragma unroll
            for (int mt = 0; mt < 2; mt++)
#pragma unroll
                for (int nt = 0; nt < 4; nt++) {
                    MMA2(c_[mt][nt], aFh[mt], b0h[nt], b1h[nt]);
                    MMA2(c_[mt][nt], aFh[mt], b0l[nt], b1l[nt]);
                    MMA2(c_[mt][nt], aFl[mt], b0h[nt], b1h[nt]);
                }
        }
    };

    ldg(0);
    sts(0);
    __syncthreads();
    for (int c = 0; c < 64; c++) {
        int buf = c & 1;
        bool more = (c + 1 < 64);
        if (more) ldg(c + 1);
        compute(buf);
        if (more) {
            sts(buf ^ 1);
            __syncthreads();
        }
    }

    // epilogue: xw0 = acc + cprime   (cs applied later at gather)
    int g = lane >> 2;
    int base_r = row0 + wm * 32 + g;
    int col0 = wn * 32 + (lane & 3) * 2;
#pragma unroll
    for (int mt = 0; mt < 2; mt++) {
#pragma unroll
        for (int rr = 0; rr < 2; rr++) {
            int gr = base_r + mt * 16 + rr * 8;
            if (gr < NN) {
#pragma unroll
                for (int nt = 0; nt < 4; nt++) {
                    int col = col0 + nt * 8;
                    float2 cp = *reinterpret_cast<float2*>(smem + SM_CPR + col * 4);
                    float2 o;
                    o.x = c_[mt][nt][rr * 2 + 0] + cp.x;
                    o.y = c_[mt][nt][rr * 2 + 1] + cp.y;
                    *reinterpret_cast<float2*>(&g_xw0[gr * 64 + col]) = o;
                }
            }
        }
    }
}

// ---------------- L5: degrees ----------------
__global__ void k_deg(const int* __restrict__ src, const int* __restrict__ dst) {
    int i = blockIdx.x * 256 + threadIdx.x;
    if (i < EE) {
        atomicAdd(&g_degS[src[i]], 1);
        atomicAdd(&g_degD[dst[i]], 1);
    }
}

// ---------------- L6-L8: scan of in-degrees -> CSR offsets + cs/cd -------------
__global__ void k_scanA() {
    __shared__ int sw[32];
    int t = threadIdx.x;
    int i = blockIdx.x * 1024 + t;
    int v = (i < NN) ? g_degD[i] : 0;
#pragma unroll
    for (int o = 16; o >= 1; o >>= 1) v += __shfl_xor_sync(0xFFFFFFFFu, v, o);
    if ((t & 31) == 0) sw[t >> 5] = v;
    __syncthreads();
    if (t < 32) {
        int x = sw[t];
#pragma unroll
        for (int o = 16; o >= 1; o >>= 1) x += __shfl_xor_sync(0xFFFFFFFFu, x, o);
        if (t == 0) g_bsum[blockIdx.x] = x;
    }
}

__global__ void k_scanB() {
    if (threadIdx.x == 0) {
        int run = 0;
        for (int i = 0; i < 49; i++) { g_boff[i] = run; run += g_bsum[i]; }
        g_off[NN] = run;
    }
}

__global__ void k_scanC() {
    __shared__ int sd[1024];
    int t = threadIdx.x;
    int i = blockIdx.x * 1024 + t;
    int v = (i < NN) ? g_degD[i] : 0;
    sd[t] = v;
    __syncthreads();
    for (int s = 1; s < 1024; s <<= 1) {
        int x = (t >= s) ? sd[t - s] : 0;
        __syncthreads();
        sd[t] += x;
        __syncthreads();
    }
    if (i < NN) {
        int excl = g_boff[blockIdx.x] + sd[t] - v;
        g_off[i] = excl;
        g_cur[i] = excl;
        g_cs[i] = rsqrtf(fmaxf((float)g_degS[i], 1.0f));
        g_cd[i] = rsqrtf(fmaxf((float)v, 1.0f));
    }
}

// ---------------- L9: fill CSR (src ids grouped by dst) ----------------
__global__ void k_fill(const int* __restrict__ src, const int* __restrict__ dst) {
    int e = blockIdx.x * 256 + threadIdx.x;
    if (e < EE) {
        int pos = atomicAdd(&g_cur[dst[e]], 1);
        g_esrc[pos] = src[e];
    }
}

// ---------------- L10: gather cs*xw0 + relu/bias/norm + GEMV 64->32 -> xw1 ------
__global__ __launch_bounds__(128) void k_g64(const float* __restrict__ bg0,
                                             const float* __restrict__ Wg1) {
    __shared__ float sW[64 * 32];
    __shared__ float sb[64];
    int t = threadIdx.x;
    for (int i = t; i < 2048; i += 128) sW[i] = Wg1[i];
    if (t < 64) sb[t] = bg0[t];
    __syncthreads();
    int wid = t >> 5, lane = t & 31;
    int n = blockIdx.x * 4 + wid;
    if (n >= NN) return;
    int beg = g_off[n], end = g_off[n + 1];
    int half = lane >> 4, l16 = lane & 15;
    float4 acc = make_float4(0.f, 0.f, 0.f, 0.f);
    int i = beg + half;
    while (i + 6 < end) {
        int s0 = g_esrc[i], s1 = g_esrc[i + 2], s2 = g_esrc[i + 4], s3 = g_esrc[i + 6];
        float cs0 = g_cs[s0], cs1 = g_cs[s1], cs2 = g_cs[s2], cs3 = g_cs[s3];
        float4 v0 = *reinterpret_cast<const float4*>(&g_xw0[s0 * 64 + l16 * 4]);
        float4 v1 = *reinterpret_cast<const float4*>(&g_xw0[s1 * 64 + l16 * 4]);
        float4 v2 = *reinterpret_cast<const float4*>(&g_xw0[s2 * 64 + l16 * 4]);
        float4 v3 = *reinterpret_cast<const float4*>(&g_xw0[s3 * 64 + l16 * 4]);
        acc.x += v0.x * cs0 + v1.x * cs1 + v2.x * cs2 + v3.x * cs3;
        acc.y += v0.y * cs0 + v1.y * cs1 + v2.y * cs2 + v3.y * cs3;
        acc.z += v0.z * cs0 + v1.z * cs1 + v2.z * cs2 + v3.z * cs3;
        acc.w += v0.w * cs0 + v1.w * cs1 + v2.w * cs2 + v3.w * cs3;
        i += 8;
    }
    while (i < end) {
        int s = g_esrc[i];
        float cs0 = g_cs[s];
        float4 v = *reinterpret_cast<const float4*>(&g_xw0[s * 64 + l16 * 4]);
        acc.x += v.x * cs0; acc.y += v.y * cs0; acc.z += v.z * cs0; acc.w += v.w * cs0;
        i += 2;
    }
    acc.x += __shfl_xor_sync(0xFFFFFFFFu, acc.x, 16);
    acc.y += __shfl_xor_sync(0xFFFFFFFFu, acc.y, 16);
    acc.z += __shfl_xor_sync(0xFFFFFFFFu, acc.z, 16);
    acc.w += __shfl_xor_sync(0xFFFFFFFFu, acc.w, 16);
    float cdv = g_cd[n], csv = g_cs[n];
    float val[4];
    val[0] = fmaxf(fmaf(acc.x, cdv, sb[l16 * 4 + 0]), 0.f) * csv;
    val[1] = fmaxf(fmaf(acc.y, cdv, sb[l16 * 4 + 1]), 0.f) * csv;
    val[2] = fmaxf(fmaf(acc.z, cdv, sb[l16 * 4 + 2]), 0.f) * csv;
    val[3] = fmaxf(fmaf(acc.w, cdv, sb[l16 * 4 + 3]), 0.f) * csv;
    float o = 0.f;
#pragma unroll
    for (int d = 0; d < 64; d++) {
        float v = __shfl_sync(0xFFFFFFFFu, val[d & 3], d >> 2);
        o = fmaf(v, sW[d * 32 + lane], o);
    }
    g_xw1[n * 32 + lane] = o;
}

// ---------------- L11: gather xw1 + relu/bias/norm + GEMV 32->4 -> xw2 ----------
__global__ __launch_bounds__(128) void k_g32(const float* __restrict__ bg1,
                                             const float* __restrict__ Wg2) {
    __shared__ float sW[32 * 4];
    __shared__ float sb[32];
    int t = threadIdx.x;
    if (t < 128) sW[t] = Wg2[t];
    if (t < 32) sb[t] = bg1[t];
    __syncthreads();
    int wid = t >> 5, lane = t & 31;
    int n = blockIdx.x * 4 + wid;
    if (n >= NN) return;
    int beg = g_off[n], end = g_off[n + 1];
    int q = lane >> 3, l8 = lane & 7;
    float4 acc = make_float4(0.f, 0.f, 0.f, 0.f);
    int i = beg + q;
    while (i + 12 < end) {
        int s0 = g_esrc[i], s1 = g_esrc[i + 4], s2 = g_esrc[i + 8], s3 = g_esrc[i + 12];
        float4 v0 = *reinterpret_cast<const float4*>(&g_xw1[s0 * 32 + l8 * 4]);
        float4 v1 = *reinterpret_cast<const float4*>(&g_xw1[s1 * 32 + l8 * 4]);
        float4 v2 = *reinterpret_cast<const float4*>(&g_xw1[s2 * 32 + l8 * 4]);
        float4 v3 = *reinterpret_cast<const float4*>(&g_xw1[s3 * 32 + l8 * 4]);
        acc.x += v0.x + v1.x + v2.x + v3.x;
        acc.y += v0.y + v1.y + v2.y + v3.y;
        acc.z += v0.z + v1.z + v2.z + v3.z;
        acc.w += v0.w + v1.w + v2.w + v3.w;
        i += 16;
    }
    while (i < end) {
        int s = g_esrc[i];
        float4 v = *reinterpret_cast<const float4*>(&g_xw1[s * 32 + l8 * 4]);
        acc.x += v.x; acc.y += v.y; acc.z += v.z; acc.w += v.w;
        i += 4;
    }
    acc.x += __shfl_xor_sync(0xFFFFFFFFu, acc.x, 8);
    acc.y += __shfl_xor_sync(0xFFFFFFFFu, acc.y, 8);
    acc.z += __shfl_xor_sync(0xFFFFFFFFu, acc.z, 8);
    acc.w += __shfl_xor_sync(0xFFFFFFFFu, acc.w, 8);
    acc.x += __shfl_xor_sync(0xFFFFFFFFu, acc.x, 16);
    acc.y += __shfl_xor_sync(0xFFFFFFFFu, acc.y, 16);
    acc.z += __shfl_xor_sync(0xFFFFFFFFu, acc.z, 16);
    acc.w += __shfl_xor_sync(0xFFFFFFFFu, acc.w, 16);
    float cdv = g_cd[n], csv = g_cs[n];
    float val[4];
    val[0] = fmaxf(fmaf(acc.x, cdv, sb[l8 * 4 + 0]), 0.f) * csv;
    val[1] = fmaxf(fmaf(acc.y, cdv, sb[l8 * 4 + 1]), 0.f) * csv;
    val[2] = fmaxf(fmaf(acc.z, cdv, sb[l8 * 4 + 2]), 0.f) * csv;
    val[3] = fmaxf(fmaf(acc.w, cdv, sb[l8 * 4 + 3]), 0.f) * csv;
    float o = 0.f;
#pragma unroll
    for (int d = 0; d < 32; d++) {
        float v = __shfl_sync(0xFFFFFFFFu, val[d & 3], d >> 2);
        o = fmaf(v, sW[d * 4 + (lane & 3)], o);
    }
    if (lane < 4) g_xw2[n * 4 + lane] = o;
}

// ---------------- L12: gather xw2 + bias -> out ----------------
__global__ __launch_bounds__(128) void k_g4(const float* __restrict__ bg2,
                                            float* __restrict__ out) {
    int t = threadIdx.x;
    int wid = t >> 5, lane = t & 31;
    int n = blockIdx.x * 4 + wid;
    if (n >= NN) return;
    int beg = g_off[n], end = g_off[n + 1];
    float4 acc = make_float4(0.f, 0.f, 0.f, 0.f);
    for (int i = beg + lane; i < end; i += 32) {
        int s = g_esrc[i];
        float4 v = *reinterpret_cast<const float4*>(&g_xw2[s * 4]);
        acc.x += v.x; acc.y += v.y; acc.z += v.z; acc.w += v.w;
    }
#pragma unroll
    for (int off = 16; off >= 1; off >>= 1) {
        acc.x += __shfl_xor_sync(0xFFFFFFFFu, acc.x, off);
        acc.y += __shfl_xor_sync(0xFFFFFFFFu, acc.y, off);
        acc.z += __shfl_xor_sync(0xFFFFFFFFu, acc.z, off);
        acc.w += __shfl_xor_sync(0xFFFFFFFFu, acc.w, off);
    }
    if (lane == 0) {
        float cdv = g_cd[n];
        float4 o;
        o.x = fmaf(acc.x, cdv, bg2[0]);
        o.y = fmaf(acc.y, cdv, bg2[1]);
        o.z = fmaf(acc.z, cdv, bg2[2]);
        o.w = fmaf(acc.w, cdv, bg2[3]);
        *reinterpret_cast<float4*>(&out[n * 4]) = o;
    }
}

// ---------------- launch ----------------
extern "C" void kernel_launch(void* const* d_in, const int* in_sizes, int n_in,
                              void* d_out, int out_size) {
    const float* h   = (const float*)d_in[0];
    const int*   src = (const int*)d_in[1];
    const int*   dst = (const int*)d_in[2];
    const float* W1  = (const float*)d_in[3];
    const float* b1  = (const float*)d_in[4];
    const float* g1  = (const float*)d_in[5];
    const float* be1 = (const float*)d_in[6];
    const float* m1  = (const float*)d_in[7];
    const float* v1  = (const float*)d_in[8];
    const float* W2  = (const float*)d_in[9];
    const float* b2  = (const float*)d_in[10];
    const float* g2  = (const float*)d_in[11];
    const float* be2 = (const float*)d_in[12];
    const float* m2  = (const float*)d_in[13];
    const float* v2  = (const float*)d_in[14];
    const float* Wd  = (const float*)d_in[15];
    const float* bd  = (const float*)d_in[16];
    const float* Wg0 = (const float*)d_in[17];
    const float* bg0 = (const float*)d_in[18];
    const float* Wg1 = (const float*)d_in[19];
    const float* bg1 = (const float*)d_in[20];
    const float* Wg2 = (const float*)d_in[21];
    const float* bg2 = (const float*)d_in[22];
    float* out = (float*)d_out;

    cudaFuncSetAttribute(k_gemm_hmma, cudaFuncAttributeMaxDynamicSharedMemorySize,
                         SMEM_BYTES);

    k_fold<<<99, 512>>>(b1, g1, be1, m1, v1, W2, b2, g2,       // 1
                        be2, m2, v2, Wd, bd, Wg0);
    k_R<<<dim3(63, 2), 64>>>(W2);                              // 2
    k_MB<<<dim3(250, 2), 64>>>(W1);                            // 3
    k_gemm_hmma<<<(NN + 127) / 128, 256, SMEM_BYTES>>>(h);     // 4  <- ncu lands here
    k_deg<<<(EE + 255) / 256, 256>>>(src, dst);                // 5
    k_scanA<<<49, 1024>>>();                                   // 6
    k_scanB<<<1, 32>>>();                                      // 7
    k_scanC<<<49, 1024>>>();                                   // 8
    k_fill<<<(EE + 255) / 256, 256>>>(src, dst);               // 9
    k_g64<<<(NN + 3) / 4, 128>>>(bg0, Wg1);                    // 10
    k_g32<<<(NN + 3) / 4, 128>>>(bg1, Wg2);                    // 11
    k_g4<<<(NN + 3) / 4, 128>>>(bg2, out);                     // 12
}

// round 6
// speedup vs baseline: 2.5887x; 1.3094x over previous
#include <cuda_runtime.h>
#include <cuda_fp16.h>
#include <cstdint>

#define NN   50000
#define EE   1600000
#define DINN 2000
#define BSCALE 4096.0f
#define BINV   (1.0f / 4096.0f)

// ---------------- device scratch (allocation-free contract) ----------------
__device__ float g_alpha1[2 * 500];
__device__ float g_bb1[2 * 500];
__device__ float g_alpha2[2 * 128];
__device__ float g_t2b[2 * 128];
__device__ float g_cmean[64];
__device__ float g_cprime[64];
__device__ float g_Wde2[2 * 128 * 64];   // 0.5 * alpha2[l] * (Wd @ Wg0)
__device__ float g_R[2 * 500 * 64];      // W2 @ Wde2
__device__ __half g_Bhi[64 * 4096];      // [e][m*2048+k] hi of 4096*M^T (pad zero)
__device__ __half g_Blo[64 * 4096];      // lo
__device__ float g_xw0[NN * 64];         // sum_m h_m@M_m (scaled back; no c')
__device__ float g_xw1[NN * 32];
__device__ float g_xw2[NN * 4];
__device__ float g_cs[NN];
__device__ float g_cd[NN];
__device__ int   g_degS[NN];
__device__ int   g_degD[NN];
__device__ int   g_off[NN + 1];
__device__ int   g_cur[NN];
__device__ int   g_esrc[EE];
__device__ int   g_bsum[64];
__device__ int   g_boff[64];

// ---------------- PTX helpers ----------------
__device__ __forceinline__ uint32_t smem_u32(const void* p) {
    uint32_t a;
    asm("{ .reg .u64 t; cvta.to.shared.u64 t, %1; cvt.u32.u64 %0, t; }"
        : "=r"(a) : "l"(p));
    return a;
}

#define LDSM4(r, a) \
    asm volatile("ldmatrix.sync.aligned.m8n8.x4.shared.b16 {%0,%1,%2,%3}, [%4];" \
                 : "=r"((r)[0]), "=r"((r)[1]), "=r"((r)[2]), "=r"((r)[3]) : "r"(a))

#define MMA2(c, a, b0, b1) \
    asm volatile( \
        "mma.sync.aligned.m16n8k16.row.col.f32.f16.f16.f32 " \
        "{%0,%1,%2,%3}, {%4,%5,%6,%7}, {%8,%9}, {%0,%1,%2,%3};" \
        : "+f"((c)[0]), "+f"((c)[1]), "+f"((c)[2]), "+f"((c)[3]) \
        : "r"((a)[0]), "r"((a)[1]), "r"((a)[2]), "r"((a)[3]), \
          "r"(b0), "r"(b1))

#define CP_ASYNC16(dst, src) \
    asm volatile("cp.async.cg.shared.global [%0], [%1], 16;" \
                 :: "r"(dst), "l"(src) : "memory")
#define CP_COMMIT() asm volatile("cp.async.commit_group;" ::: "memory")
#define CP_WAIT0()  asm volatile("cp.async.wait_group 0;" ::: "memory")

// ---------------- L1: zero degrees + zero xw0 + bias-chain fold + Wde2 ---------
__global__ void k_fold(const float* __restrict__ b1, const float* __restrict__ g1,
                       const float* __restrict__ be1, const float* __restrict__ m1,
                       const float* __restrict__ v1, const float* __restrict__ W2,
                       const float* __restrict__ b2, const float* __restrict__ g2,
                       const float* __restrict__ be2, const float* __restrict__ m2,
                       const float* __restrict__ v2, const float* __restrict__ Wd,
                       const float* __restrict__ bd, const float* __restrict__ Wg0) {
    if (blockIdx.x < 98) {
        int i = blockIdx.x * 512 + threadIdx.x;
        if (i < NN) { g_degS[i] = 0; g_degD[i] = 0; }
        return;
    }
    if (blockIdx.x < 298) {
        // zero xw0 (NN*64 floats = 800000 float4)
        float4 z = make_float4(0.f, 0.f, 0.f, 0.f);
        for (int i = (blockIdx.x - 98) * 512 + threadIdx.x; i < NN * 16; i += 200 * 512)
            reinterpret_cast<float4*>(g_xw0)[i] = z;
        return;
    }
    __shared__ float sWg0[64 * 64];
    int t = threadIdx.x;
    for (int i = t; i < 1000; i += 512) {
        float a = g1[i] * rsqrtf(v1[i] + 1e-5f);
        g_alpha1[i] = a;
        g_bb1[i] = (b1[i] - m1[i]) * a + be1[i];
    }
    for (int i = t; i < 256; i += 512)
        g_alpha2[i] = g2[i] * rsqrtf(v2[i] + 1e-5f);
    for (int i = t; i < 4096; i += 512) sWg0[i] = Wg0[i];
    __syncthreads();
    for (int i = t; i < 256; i += 512) {
        int mm = i >> 7, l = i & 127;
        float s = 0.f;
        for (int j = 0; j < 500; j++)
            s += g_bb1[mm * 500 + j] * W2[mm * 64000 + j * 128 + l];
        g_t2b[i] = (s + b2[i] - m2[i]) * g_alpha2[i] + be2[i];
    }
    for (int idx = t; idx < 16384; idx += 512) {
        int m = idx >> 13, rem = idx & 8191, l = rem >> 6, e = rem & 63;
        float s = 0.f;
        for (int d = 0; d < 64; d++)
            s += Wd[m * 8192 + l * 64 + d] * sWg0[d * 64 + e];
        g_Wde2[idx] = 0.5f * g_alpha2[m * 128 + l] * s;
    }
    __syncthreads();
    for (int d = t; d < 64; d += 512) {
        float s = 0.f;
        for (int mm = 0; mm < 2; mm++) {
            float sm = bd[mm * 64 + d];
            for (int l = 0; l < 128; l++)
                sm += g_t2b[mm * 128 + l] * Wd[mm * 8192 + l * 64 + d];
            s += sm;
        }
        g_cmean[d] = 0.5f * s;
    }
    __syncthreads();
    for (int e = t; e < 64; e += 512) {
        float s = 0.f;
        for (int d = 0; d < 64; d++) s += g_cmean[d] * sWg0[d * 64 + e];
        g_cprime[e] = s;
    }
}

// ---------------- L2: R[m][j][e] = sum_l W2[m][j][l] * Wde2[m][l][e] ------------
__global__ void k_R(const float* __restrict__ W2) {
    __shared__ float sW2[8][128];
    int m = blockIdx.y, j0 = blockIdx.x * 8, t = threadIdx.x;  // 64 threads
    for (int idx = t; idx < 1024; idx += 64) {
        int r = idx >> 7, l = idx & 127;
        int j = j0 + r;
        sW2[r][l] = (j < 500) ? W2[m * 64000 + j * 128 + l] : 0.f;
    }
    __syncthreads();
    int e = t;
    float acc[8] = {0, 0, 0, 0, 0, 0, 0, 0};
    for (int l = 0; l < 128; l++) {
        float w = g_Wde2[m * 8192 + l * 64 + e];
#pragma unroll
        for (int r = 0; r < 8; r++) acc[r] += sW2[r][l] * w;
    }
#pragma unroll
    for (int r = 0; r < 8; r++) {
        int j = j0 + r;
        if (j < 500) g_R[m * 32000 + j * 64 + e] = acc[r];
    }
}

// ---------------- L3: M = (W1*alpha1) @ R -> fp16 hi/lo (scaled x4096) ----------
__global__ __launch_bounds__(256) void k_MB(const float* __restrict__ W1) {
    __shared__ float sA[8][500];
    __shared__ float red[3][8][64];
    int m = blockIdx.y, i0 = blockIdx.x * 8, t = threadIdx.x;  // 256 threads
    for (int idx = t; idx < 4000; idx += 256) {
        int r = idx / 500, j = idx - r * 500;
        sA[r][j] = W1[m * 1000000 + (i0 + r) * 500 + j] * g_alpha1[m * 500 + j];
    }
    __syncthreads();
    int e = t & 63, jp = t >> 6;
    float acc[8] = {0, 0, 0, 0, 0, 0, 0, 0};
    for (int j = jp; j < 500; j += 4) {
        float w = g_R[m * 32000 + j * 64 + e];
#pragma unroll
        for (int r = 0; r < 8; r++) acc[r] += sA[r][j] * w;
    }
    if (jp > 0) {
#pragma unroll
        for (int r = 0; r < 8; r++) red[jp - 1][r][e] = acc[r];
    }
    __syncthreads();
    if (jp == 0) {
#pragma unroll
        for (int r = 0; r < 8; r++) {
            float v = (acc[r] + red[0][r][e] + red[1][r][e] + red[2][r][e]) * BSCALE;
            __half hi = __float2half_rn(v);
            g_Bhi[e * 4096 + m * 2048 + i0 + r] = hi;
            g_Blo[e * 4096 + m * 2048 + i0 + r] = __float2half_rn(v - __half2float(hi));
        }
    }
}

// ---------------- L4: HMMA GEMM (splitK over m): xw0 += h_m @ M_m ---------------
// Block tile 128x64, 8 warps 4(M)x2(N), warp tile 32x32, K-chunk 64, 32 chunks.
// fp16 2-term split: Ah*Bh + Ah*Bl. A via LDG+cvt, B via cp.async.
#define SM_A 0                       // 2 buf x 16384 (fp16 A-hi)
#define SM_B 32768                   // 2 buf x (8192 hi + 8192 lo)
#define SMEM_BYTES 65536

__global__ __launch_bounds__(256) void k_gemm_hmma(const float* __restrict__ h) {
    extern __shared__ __align__(1024) char smem[];
    uint32_t sbase = smem_u32(smem);
    int tid = threadIdx.x;
    int lane = tid & 31, wid = tid >> 5;
    int wm = wid >> 1, wn = wid & 1;
    int row0 = blockIdx.x * 128;
    int m = blockIdx.y;
    const float* hb = h + (long long)m * NN * DINN;
    const __half* bhi = g_Bhi + m * 2048;
    const __half* blo = g_Blo + m * 2048;

    uint32_t swz = (uint32_t)(lane & 7) << 4;
    uint32_t aoff = (uint32_t)(wm * 32 + (lane & 15)) * 128;
    uint32_t acolsel = (uint32_t)(lane >> 4) << 4;
    uint32_t boff = (uint32_t)(wn * 32 + lane) * 128;

    float c_[2][4][4];
#pragma unroll
    for (int mt = 0; mt < 2; mt++)
#pragma unroll
        for (int nt = 0; nt < 4; nt++)
#pragma unroll
            for (int q = 0; q < 4; q++) c_[mt][nt][q] = 0.f;

    float4 va[8];

    auto ldgA = [&](int c) {
        int k0 = c * 64;
#pragma unroll
        for (int i = 0; i < 8; i++) {
            int idx = tid + 256 * i;
            int r = idx >> 4, cg = idx & 15;
            int gr = row0 + r, k = k0 + cg * 4;
            if (gr < NN && k < 2000)
                va[i] = *reinterpret_cast<const float4*>(&hb[(long long)gr * DINN + k]);
            else
                va[i] = make_float4(0.f, 0.f, 0.f, 0.f);
        }
    };

    auto cpB = [&](int c, int buf) {
        int k0 = c * 64;
        uint32_t bH = sbase + SM_B + buf * 16384, bL = bH + 8192;
#pragma unroll
        for (int i = 0; i < 2; i++) {
            int idx = tid + 256 * i;
            int r = idx >> 3, cg = idx & 7;
            uint32_t off = (uint32_t)r * 128 +
                           (((uint32_t)cg * 16) ^ (((uint32_t)r & 7) << 4));
            CP_ASYNC16(bH + off, bhi + r * 4096 + k0 + cg * 8);
            CP_ASYNC16(bL + off, blo + r * 4096 + k0 + cg * 8);
        }
        CP_COMMIT();
    };

    auto stsA = [&](int buf) {
        uint32_t aH = SM_A + buf * 16384;
#pragma unroll
        for (int i = 0; i < 8; i++) {
            int idx = tid + 256 * i;
            int r = idx >> 4, cg = idx & 15;
            float4 v = va[i];
            __half2 h01 = __float22half2_rn(make_float2(v.x, v.y));
            __half2 h23 = __float22half2_rn(make_float2(v.z, v.w));
            uint32_t off = (uint32_t)r * 128 +
                           (((uint32_t)cg * 8) ^ (((uint32_t)r & 7) << 4));
            *reinterpret_cast<uint2*>(smem + aH + off) =
                make_uint2(*reinterpret_cast<uint32_t*>(&h01),
                           *reinterpret_cast<uint32_t*>(&h23));
        }
    };

    auto compute = [&](int buf) {
        uint32_t aH = sbase + SM_A + buf * 16384;
        uint32_t bH = sbase + SM_B + buf * 16384, bL = bH + 8192;
#pragma unroll
        for (int ks = 0; ks < 4; ks++) {
            uint32_t kb = (uint32_t)ks * 32;
            uint32_t aF[2][4];
            uint32_t b0h[4], b1h[4], b0l[4], b1l[4];
#pragma unroll
            for (int mt = 0; mt < 2; mt++) {
                uint32_t adr = aoff + (uint32_t)mt * 2048 + ((kb + acolsel) ^ swz);
                LDSM4(aF[mt], aH + adr);
            }
            LDSM4(b0h, bH + boff + ((kb + 0) ^ swz));
            LDSM4(b1h, bH + boff + ((kb + 16) ^ swz));
            LDSM4(b0l, bL + boff + ((kb + 0) ^ swz));
            LDSM4(b1l, bL + boff + ((kb + 16) ^ swz));
#pragma unroll
            for (int mt = 0; mt < 2; mt++)
#pragma unroll
                for (int nt = 0; nt < 4; nt++) {
                    MMA2(c_[mt][nt], aF[mt], b0h[nt], b1h[nt]);
                    MMA2(c_[mt][nt], aF[mt], b0l[nt], b1l[nt]);
                }
        }
    };

    ldgA(0);
    cpB(0, 0);
    stsA(0);
    CP_WAIT0();
    __syncthreads();

    for (int c = 0; c < 32; c++) {
        int buf = c & 1;
        bool more = (c + 1 < 32);
        if (more) {
            cpB(c + 1, buf ^ 1);
            ldgA(c + 1);
        }
        compute(buf);
        if (more) {
            stsA(buf ^ 1);
            CP_WAIT0();
            __syncthreads();
        }
    }

    // epilogue: atomic accumulate (scale back by 1/4096); c' applied in k_g64
    int g = lane >> 2;
    int base_r = row0 + wm * 32 + g;
    int col0 = wn * 32 + (lane & 3) * 2;
#pragma unroll
    for (int mt = 0; mt < 2; mt++) {
#pragma unroll
        for (int rr = 0; rr < 2; rr++) {
            int gr = base_r + mt * 16 + rr * 8;
            if (gr < NN) {
#pragma unroll
                for (int nt = 0; nt < 4; nt++) {
                    int col = col0 + nt * 8;
                    float2 v;
                    v.x = c_[mt][nt][rr * 2 + 0] * BINV;
                    v.y = c_[mt][nt][rr * 2 + 1] * BINV;
                    atomicAdd(reinterpret_cast<float2*>(&g_xw0[gr * 64 + col]), v);
                }
            }
        }
    }
}

// ---------------- L5: degrees ----------------
__global__ void k_deg(const int* __restrict__ src, const int* __restrict__ dst) {
    int i = blockIdx.x * 256 + threadIdx.x;
    if (i < EE) {
        atomicAdd(&g_degS[src[i]], 1);
        atomicAdd(&g_degD[dst[i]], 1);
    }
}

// ---------------- L6-L8: scan of in-degrees -> CSR offsets + cs/cd -------------
__global__ void k_scanA() {
    __shared__ int sw[32];
    int t = threadIdx.x;
    int i = blockIdx.x * 1024 + t;
    int v = (i < NN) ? g_degD[i] : 0;
#pragma unroll
    for (int o = 16; o >= 1; o >>= 1) v += __shfl_xor_sync(0xFFFFFFFFu, v, o);
    if ((t & 31) == 0) sw[t >> 5] = v;
    __syncthreads();
    if (t < 32) {
        int x = sw[t];
#pragma unroll
        for (int o = 16; o >= 1; o >>= 1) x += __shfl_xor_sync(0xFFFFFFFFu, x, o);
        if (t == 0) g_bsum[blockIdx.x] = x;
    }
}

__global__ void k_scanB() {
    if (threadIdx.x == 0) {
        int run = 0;
        for (int i = 0; i < 49; i++) { g_boff[i] = run; run += g_bsum[i]; }
        g_off[NN] = run;
    }
}

__global__ void k_scanC() {
    __shared__ int sd[1024];
    int t = threadIdx.x;
    int i = blockIdx.x * 1024 + t;
    int v = (i < NN) ? g_degD[i] : 0;
    sd[t] = v;
    __syncthreads();
    for (int s = 1; s < 1024; s <<= 1) {
        int x = (t >= s) ? sd[t - s] : 0;
        __syncthreads();
        sd[t] += x;
        __syncthreads();
    }
    if (i < NN) {
        int excl = g_boff[blockIdx.x] + sd[t] - v;
        g_off[i] = excl;
        g_cur[i] = excl;
        g_cs[i] = rsqrtf(fmaxf((float)g_degS[i], 1.0f));
        g_cd[i] = rsqrtf(fmaxf((float)v, 1.0f));
    }
}

// ---------------- L9: fill CSR (src ids grouped by dst) ----------------
__global__ void k_fill(const int* __restrict__ src, const int* __restrict__ dst) {
    int e = blockIdx.x * 256 + threadIdx.x;
    if (e < EE) {
        int pos = atomicAdd(&g_cur[dst[e]], 1);
        g_esrc[pos] = src[e];
    }
}

// ---------------- L10: gather cs*(xw0+c') + relu/bias/norm + GEMV 64->32 --------
__global__ __launch_bounds__(128) void k_g64(const float* __restrict__ bg0,
                                             const float* __restrict__ Wg1) {
    __shared__ float sW[64 * 32];
    __shared__ float sb[64];
    __shared__ float sc[64];
    int t = threadIdx.x;
    for (int i = t; i < 2048; i += 128) sW[i] = Wg1[i];
    if (t < 64) { sb[t] = bg0[t]; sc[t] = g_cprime[t]; }
    __syncthreads();
    int wid = t >> 5, lane = t & 31;
    int n = blockIdx.x * 4 + wid;
    if (n >= NN) return;
    int beg = g_off[n], end = g_off[n + 1];
    int half = lane >> 4, l16 = lane & 15;
    float4 acc = make_float4(0.f, 0.f, 0.f, 0.f);
    float scs = 0.f;
    int i = beg + half;
    while (i + 6 < end) {
        int s0 = g_esrc[i], s1 = g_esrc[i + 2], s2 = g_esrc[i + 4], s3 = g_esrc[i + 6];
        float cs0 = g_cs[s0], cs1 = g_cs[s1], cs2 = g_cs[s2], cs3 = g_cs[s3];
        float4 v0 = *reinterpret_cast<const float4*>(&g_xw0[s0 * 64 + l16 * 4]);
        float4 v1 = *reinterpret_cast<const float4*>(&g_xw0[s1 * 64 + l16 * 4]);
        float4 v2 = *reinterpret_cast<const float4*>(&g_xw0[s2 * 64 + l16 * 4]);
        float4 v3 = *reinterpret_cast<const float4*>(&g_xw0[s3 * 64 + l16 * 4]);
        acc.x += v0.x * cs0 + v1.x * cs1 + v2.x * cs2 + v3.x * cs3;
        acc.y += v0.y * cs0 + v1.y * cs1 + v2.y * cs2 + v3.y * cs3;
        acc.z += v0.z * cs0 + v1.z * cs1 + v2.z * cs2 + v3.z * cs3;
        acc.w += v0.w * cs0 + v1.w * cs1 + v2.w * cs2 + v3.w * cs3;
        scs += cs0 + cs1 + cs2 + cs3;
        i += 8;
    }
    while (i < end) {
        int s = g_esrc[i];
        float cs0 = g_cs[s];
        float4 v = *reinterpret_cast<const float4*>(&g_xw0[s * 64 + l16 * 4]);
        acc.x += v.x * cs0; acc.y += v.y * cs0; acc.z += v.z * cs0; acc.w += v.w * cs0;
        scs += cs0;
        i += 2;
    }
    acc.x += __shfl_xor_sync(0xFFFFFFFFu, acc.x, 16);
    acc.y += __shfl_xor_sync(0xFFFFFFFFu, acc.y, 16);
    acc.z += __shfl_xor_sync(0xFFFFFFFFu, acc.z, 16);
    acc.w += __shfl_xor_sync(0xFFFFFFFFu, acc.w, 16);
    scs   += __shfl_xor_sync(0xFFFFFFFFu, scs, 16);
    float cdv = g_cd[n], csv = g_cs[n];
    float val[4];
    val[0] = fmaxf(fmaf(fmaf(sc[l16 * 4 + 0], scs, acc.x), cdv, sb[l16 * 4 + 0]), 0.f) * csv;
    val[1] = fmaxf(fmaf(fmaf(sc[l16 * 4 + 1], scs, acc.y), cdv, sb[l16 * 4 + 1]), 0.f) * csv;
    val[2] = fmaxf(fmaf(fmaf(sc[l16 * 4 + 2], scs, acc.z), cdv, sb[l16 * 4 + 2]), 0.f) * csv;
    val[3] = fmaxf(fmaf(fmaf(sc[l16 * 4 + 3], scs, acc.w), cdv, sb[l16 * 4 + 3]), 0.f) * csv;
    float o = 0.f;
#pragma unroll
    for (int d = 0; d < 64; d++) {
        float v = __shfl_sync(0xFFFFFFFFu, val[d & 3], d >> 2);
        o = fmaf(v, sW[d * 32 + lane], o);
    }
    g_xw1[n * 32 + lane] = o;
}

// ---------------- L11: gather xw1 + relu/bias/norm + GEMV 32->4 -> xw2 ----------
__global__ __launch_bounds__(128) void k_g32(const float* __restrict__ bg1,
                                             const float* __restrict__ Wg2) {
    __shared__ float sW[32 * 4];
    __shared__ float sb[32];
    int t = threadIdx.x;
    if (t < 128) sW[t] = Wg2[t];
    if (t < 32) sb[t] = bg1[t];
    __syncthreads();
    int wid = t >> 5, lane = t & 31;
    int n = blockIdx.x * 4 + wid;
    if (n >= NN) return;
    int beg = g_off[n], end = g_off[n + 1];
    int q = lane >> 3, l8 = lane & 7;
    float4 acc = make_float4(0.f, 0.f, 0.f, 0.f);
    int i = beg + q;
    while (i + 12 < end) {
        int s0 = g_esrc[i], s1 = g_esrc[i + 4], s2 = g_esrc[i + 8], s3 = g_esrc[i + 12];
        float4 v0 = *reinterpret_cast<const float4*>(&g_xw1[s0 * 32 + l8 * 4]);
        float4 v1 = *reinterpret_cast<const float4*>(&g_xw1[s1 * 32 + l8 * 4]);
        float4 v2 = *reinterpret_cast<const float4*>(&g_xw1[s2 * 32 + l8 * 4]);
        float4 v3 = *reinterpret_cast<const float4*>(&g_xw1[s3 * 32 + l8 * 4]);
        acc.x += v0.x + v1.x + v2.x + v3.x;
        acc.y += v0.y + v1.y + v2.y + v3.y;
        acc.z += v0.z + v1.z + v2.z + v3.z;
        acc.w += v0.w + v1.w + v2.w + v3.w;
        i += 16;
    }
    while (i < end) {
        int s = g_esrc[i];
        float4 v = *reinterpret_cast<const float4*>(&g_xw1[s * 32 + l8 * 4]);
        acc.x += v.x; acc.y += v.y; acc.z += v.z; acc.w += v.w;
        i += 4;
    }
    acc.x += __shfl_xor_sync(0xFFFFFFFFu, acc.x, 8);
    acc.y += __shfl_xor_sync(0xFFFFFFFFu, acc.y, 8);
    acc.z += __shfl_xor_sync(0xFFFFFFFFu, acc.z, 8);
    acc.w += __shfl_xor_sync(0xFFFFFFFFu, acc.w, 8);
    acc.x += __shfl_xor_sync(0xFFFFFFFFu, acc.x, 16);
    acc.y += __shfl_xor_sync(0xFFFFFFFFu, acc.y, 16);
    acc.z += __shfl_xor_sync(0xFFFFFFFFu, acc.z, 16);
    acc.w += __shfl_xor_sync(0xFFFFFFFFu, acc.w, 16);
    float cdv = g_cd[n], csv = g_cs[n];
    float val[4];
    val[0] = fmaxf(fmaf(acc.x, cdv, sb[l8 * 4 + 0]), 0.f) * csv;
    val[1] = fmaxf(fmaf(acc.y, cdv, sb[l8 * 4 + 1]), 0.f) * csv;
    val[2] = fmaxf(fmaf(acc.z, cdv, sb[l8 * 4 + 2]), 0.f) * csv;
    val[3] = fmaxf(fmaf(acc.w, cdv, sb[l8 * 4 + 3]), 0.f) * csv;
    float o = 0.f;
#pragma unroll
    for (int d = 0; d < 32; d++) {
        float v = __shfl_sync(0xFFFFFFFFu, val[d & 3], d >> 2);
        o = fmaf(v, sW[d * 4 + (lane & 3)], o);
    }
    if (lane < 4) g_xw2[n * 4 + lane] = o;
}

// ---------------- L12: gather xw2 + bias -> out ----------------
__global__ __launch_bounds__(128) void k_g4(const float* __restrict__ bg2,
                                            float* __restrict__ out) {
    int t = threadIdx.x;
    int wid = t >> 5, lane = t & 31;
    int n = blockIdx.x * 4 + wid;
    if (n >= NN) return;
    int beg = g_off[n], end = g_off[n + 1];
    float4 acc = make_float4(0.f, 0.f, 0.f, 0.f);
    for (int i = beg + lane; i < end; i += 32) {
        int s = g_esrc[i];
        float4 v = *reinterpret_cast<const float4*>(&g_xw2[s * 4]);
        acc.x += v.x; acc.y += v.y; acc.z += v.z; acc.w += v.w;
    }
#pragma unroll
    for (int off = 16; off >= 1; off >>= 1) {
        acc.x += __shfl_xor_sync(0xFFFFFFFFu, acc.x, off);
        acc.y += __shfl_xor_sync(0xFFFFFFFFu, acc.y, off);
        acc.z += __shfl_xor_sync(0xFFFFFFFFu, acc.z, off);
        acc.w += __shfl_xor_sync(0xFFFFFFFFu, acc.w, off);
    }
    if (lane == 0) {
        float cdv = g_cd[n];
        float4 o;
        o.x = fmaf(acc.x, cdv, bg2[0]);
        o.y = fmaf(acc.y, cdv, bg2[1]);
        o.z = fmaf(acc.z, cdv, bg2[2]);
        o.w = fmaf(acc.w, cdv, bg2[3]);
        *reinterpret_cast<float4*>(&out[n * 4]) = o;
    }
}

// ---------------- launch ----------------
extern "C" void kernel_launch(void* const* d_in, const int* in_sizes, int n_in,
                              void* d_out, int out_size) {
    const float* h   = (const float*)d_in[0];
    const int*   src = (const int*)d_in[1];
    const int*   dst = (const int*)d_in[2];
    const float* W1  = (const float*)d_in[3];
    const float* b1  = (const float*)d_in[4];
    const float* g1  = (const float*)d_in[5];
    const float* be1 = (const float*)d_in[6];
    const float* m1  = (const float*)d_in[7];
    const float* v1  = (const float*)d_in[8];
    const float* W2  = (const float*)d_in[9];
    const float* b2  = (const float*)d_in[10];
    const float* g2  = (const float*)d_in[11];
    const float* be2 = (const float*)d_in[12];
    const float* m2  = (const float*)d_in[13];
    const float* v2  = (const float*)d_in[14];
    const float* Wd  = (const float*)d_in[15];
    const float* bd  = (const float*)d_in[16];
    const float* Wg0 = (const float*)d_in[17];
    const float* bg0 = (const float*)d_in[18];
    const float* Wg1 = (const float*)d_in[19];
    const float* bg1 = (const float*)d_in[20];
    const float* Wg2 = (const float*)d_in[21];
    const float* bg2 = (const float*)d_in[22];
    float* out = (float*)d_out;

    cudaFuncSetAttribute(k_gemm_hmma, cudaFuncAttributeMaxDynamicSharedMemorySize,
                         SMEM_BYTES);

    k_fold<<<299, 512>>>(b1, g1, be1, m1, v1, W2, b2, g2,            // 1
                         be2, m2, v2, Wd, bd, Wg0);
    k_R<<<dim3(63, 2), 64>>>(W2);                                    // 2
    k_MB<<<dim3(250, 2), 256>>>(W1);                                 // 3
    k_gemm_hmma<<<dim3((NN + 127) / 128, 2), 256, SMEM_BYTES>>>(h);  // 4 <- ncu
    k_deg<<<(EE + 255) / 256, 256>>>(src, dst);                      // 5
    k_scanA<<<49, 1024>>>();                                         // 6
    k_scanB<<<1, 32>>>();                                            // 7
    k_scanC<<<49, 1024>>>();                                         // 8
    k_fill<<<(EE + 255) / 256, 256>>>(src, dst);                     // 9
    k_g64<<<(NN + 3) / 4, 128>>>(bg0, Wg1);                          // 10
    k_g32<<<(NN + 3) / 4, 128>>>(bg1, Wg2);                          // 11
    k_g4<<<(NN + 3) / 4, 128>>>(bg2, out);                           // 12
}

// round 7
// speedup vs baseline: 2.8319x; 1.0940x over previous
#include <cuda_runtime.h>
#include <cuda_fp16.h>
#include <cstdint>

#define NN   50000
#define EE   1600000
#define DINN 2000
#define BSCALE 4096.0f
#define BINV   (1.0f / 4096.0f)

// ---------------- device scratch (allocation-free contract) ----------------
__device__ float g_alpha1[2 * 500];
__device__ float g_bb1[2 * 500];
__device__ float g_alpha2[2 * 128];
__device__ float g_t2b[2 * 128];
__device__ float g_cmean[64];
__device__ float g_cprime[64];
__device__ float g_Wde2[2 * 128 * 64];   // 0.5 * alpha2[l] * (Wd @ Wg0)
__device__ float g_R[2 * 500 * 64];      // W2 @ Wde2
__device__ __half g_Bhi[64 * 4096];      // [e][m*2048+k] hi of 4096*M^T (pad zero)
__device__ __half g_Blo[64 * 4096];      // lo
__device__ float g_xw0[NN * 64];         // sum h@M partials (no c'; cs at gather)
__device__ float g_xw1[NN * 32];
__device__ float g_xw2[NN * 4];
__device__ float g_cs[NN];
__device__ float g_cd[NN];
__device__ int   g_degS[NN];             // zero at module load; re-zeroed each call
__device__ int   g_degD[NN];
__device__ int   g_off[NN + 1];
__device__ int   g_epos[EE];
__device__ int   g_esrc[EE];
__device__ int   g_bsum[64];
__device__ int   g_boff[64];

// ---------------- PTX helpers ----------------
__device__ __forceinline__ uint32_t smem_u32(const void* p) {
    uint32_t a;
    asm("{ .reg .u64 t; cvta.to.shared.u64 t, %1; cvt.u32.u64 %0, t; }"
        : "=r"(a) : "l"(p));
    return a;
}

#define LDSM4(r, a) \
    asm volatile("ldmatrix.sync.aligned.m8n8.x4.shared.b16 {%0,%1,%2,%3}, [%4];" \
                 : "=r"((r)[0]), "=r"((r)[1]), "=r"((r)[2]), "=r"((r)[3]) : "r"(a))

#define MMA2(c, a, b0, b1) \
    asm volatile( \
        "mma.sync.aligned.m16n8k16.row.col.f32.f16.f16.f32 " \
        "{%0,%1,%2,%3}, {%4,%5,%6,%7}, {%8,%9}, {%0,%1,%2,%3};" \
        : "+f"((c)[0]), "+f"((c)[1]), "+f"((c)[2]), "+f"((c)[3]) \
        : "r"((a)[0]), "r"((a)[1]), "r"((a)[2]), "r"((a)[3]), \
          "r"(b0), "r"(b1))

#define CP_ASYNC16(dst, src) \
    asm volatile("cp.async.cg.shared.global [%0], [%1], 16;" \
                 :: "r"(dst), "l"(src) : "memory")
#define CP_COMMIT() asm volatile("cp.async.commit_group;" ::: "memory")
#define CP_WAIT0()  asm volatile("cp.async.wait_group 0;" ::: "memory")

// ---- L1: fold (blk 0) + degrees/epos (blk 1..3125) + zero xw0 (rest) ----------
__global__ __launch_bounds__(512) void k_fold(
    const int* __restrict__ src, const int* __restrict__ dst,
    const float* __restrict__ b1, const float* __restrict__ g1,
    const float* __restrict__ be1, const float* __restrict__ m1,
    const float* __restrict__ v1, const float* __restrict__ W2,
    const float* __restrict__ b2, const float* __restrict__ g2,
    const float* __restrict__ be2, const float* __restrict__ m2,
    const float* __restrict__ v2, const float* __restrict__ Wd,
    const float* __restrict__ bd, const float* __restrict__ Wg0) {
    int b = blockIdx.x;
    if (b >= 1 && b <= 3125) {
        int e = (b - 1) * 512 + threadIdx.x;
        if (e < EE) {
            g_epos[e] = atomicAdd(&g_degD[dst[e]], 1);
            atomicAdd(&g_degS[src[e]], 1);
        }
        return;
    }
    if (b > 3125) {
        float4 z = make_float4(0.f, 0.f, 0.f, 0.f);
        for (int i = (b - 3126) * 512 + threadIdx.x; i < NN * 16; i += 200 * 512)
            reinterpret_cast<float4*>(g_xw0)[i] = z;
        return;
    }
    // block 0: bias-chain fold + Wde2
    __shared__ float sWg0[64 * 64];
    int t = threadIdx.x;
    for (int i = t; i < 1000; i += 512) {
        float a = g1[i] * rsqrtf(v1[i] + 1e-5f);
        g_alpha1[i] = a;
        g_bb1[i] = (b1[i] - m1[i]) * a + be1[i];
    }
    for (int i = t; i < 256; i += 512)
        g_alpha2[i] = g2[i] * rsqrtf(v2[i] + 1e-5f);
    for (int i = t; i < 4096; i += 512) sWg0[i] = Wg0[i];
    __syncthreads();
    for (int i = t; i < 256; i += 512) {
        int mm = i >> 7, l = i & 127;
        float s = 0.f;
        for (int j = 0; j < 500; j++)
            s += g_bb1[mm * 500 + j] * W2[mm * 64000 + j * 128 + l];
        g_t2b[i] = (s + b2[i] - m2[i]) * g_alpha2[i] + be2[i];
    }
    for (int idx = t; idx < 16384; idx += 512) {
        int m = idx >> 13, rem = idx & 8191, l = rem >> 6, e = rem & 63;
        float s = 0.f;
        for (int d = 0; d < 64; d++)
            s += Wd[m * 8192 + l * 64 + d] * sWg0[d * 64 + e];
        g_Wde2[idx] = 0.5f * g_alpha2[m * 128 + l] * s;
    }
    __syncthreads();
    for (int d = t; d < 64; d += 512) {
        float s = 0.f;
        for (int mm = 0; mm < 2; mm++) {
            float sm = bd[mm * 64 + d];
            for (int l = 0; l < 128; l++)
                sm += g_t2b[mm * 128 + l] * Wd[mm * 8192 + l * 64 + d];
            s += sm;
        }
        g_cmean[d] = 0.5f * s;
    }
    __syncthreads();
    for (int e = t; e < 64; e += 512) {
        float s = 0.f;
        for (int d = 0; d < 64; d++) s += g_cmean[d] * sWg0[d * 64 + e];
        g_cprime[e] = s;
    }
}

// ---------------- L2: R[m][j][e] = sum_l W2[m][j][l] * Wde2[m][l][e] ------------
__global__ void k_R(const float* __restrict__ W2) {
    __shared__ float sW2[8][128];
    int m = blockIdx.y, j0 = blockIdx.x * 8, t = threadIdx.x;  // 64 threads
    for (int idx = t; idx < 1024; idx += 64) {
        int r = idx >> 7, l = idx & 127;
        int j = j0 + r;
        sW2[r][l] = (j < 500) ? W2[m * 64000 + j * 128 + l] : 0.f;
    }
    __syncthreads();
    int e = t;
    float acc[8] = {0, 0, 0, 0, 0, 0, 0, 0};
    for (int l = 0; l < 128; l++) {
        float w = g_Wde2[m * 8192 + l * 64 + e];
#pragma unroll
        for (int r = 0; r < 8; r++) acc[r] += sW2[r][l] * w;
    }
#pragma unroll
    for (int r = 0; r < 8; r++) {
        int j = j0 + r;
        if (j < 500) g_R[m * 32000 + j * 64 + e] = acc[r];
    }
}

// ---------------- L3: M = (W1*alpha1) @ R -> fp16 hi/lo (scaled x4096) ----------
__global__ __launch_bounds__(256) void k_MB(const float* __restrict__ W1) {
    __shared__ float sA[8][500];
    __shared__ float red[3][8][64];
    int m = blockIdx.y, i0 = blockIdx.x * 8, t = threadIdx.x;  // 256 threads
    for (int idx = t; idx < 4000; idx += 256) {
        int r = idx / 500, j = idx - r * 500;
        sA[r][j] = W1[m * 1000000 + (i0 + r) * 500 + j] * g_alpha1[m * 500 + j];
    }
    __syncthreads();
    int e = t & 63, jp = t >> 6;
    float acc[8] = {0, 0, 0, 0, 0, 0, 0, 0};
    for (int j = jp; j < 500; j += 4) {
        float w = g_R[m * 32000 + j * 64 + e];
#pragma unroll
        for (int r = 0; r < 8; r++) acc[r] += sA[r][j] * w;
    }
    if (jp > 0) {
#pragma unroll
        for (int r = 0; r < 8; r++) red[jp - 1][r][e] = acc[r];
    }
    __syncthreads();
    if (jp == 0) {
#pragma unroll
        for (int r = 0; r < 8; r++) {
            float v = (acc[r] + red[0][r][e] + red[1][r][e] + red[2][r][e]) * BSCALE;
            __half hi = __float2half_rn(v);
            g_Bhi[e * 4096 + m * 2048 + i0 + r] = hi;
            g_Blo[e * 4096 + m * 2048 + i0 + r] = __float2half_rn(v - __half2float(hi));
        }
    }
}

// ------- L4: HMMA GEMM splitK=4 (m x khalf): xw0 += h_m[:, kr] @ M_m[kr, :] -----
#define SM_A 0                       // 2 buf x 16384 (fp16 A-hi)
#define SM_B 32768                   // 2 buf x (8192 hi + 8192 lo)
#define SMEM_BYTES 65536

__global__ __launch_bounds__(256) void k_gemm_hmma(const float* __restrict__ h) {
    extern __shared__ __align__(1024) char smem[];
    uint32_t sbase = smem_u32(smem);
    int tid = threadIdx.x;
    int lane = tid & 31, wid = tid >> 5;
    int wm = wid >> 1, wn = wid & 1;
    int row0 = blockIdx.x * 128;
    int m = blockIdx.y >> 1;
    int kh = blockIdx.y & 1;
    const float* hb = h + (long long)m * NN * DINN;
    const __half* bhi = g_Bhi + m * 2048 + kh * 1024;
    const __half* blo = g_Blo + m * 2048 + kh * 1024;
    int kbase = kh * 1024;

    uint32_t swz = (uint32_t)(lane & 7) << 4;
    uint32_t aoff = (uint32_t)(wm * 32 + (lane & 15)) * 128;
    uint32_t acolsel = (uint32_t)(lane >> 4) << 4;
    uint32_t boff = (uint32_t)(wn * 32 + lane) * 128;

    float c_[2][4][4];
#pragma unroll
    for (int mt = 0; mt < 2; mt++)
#pragma unroll
        for (int nt = 0; nt < 4; nt++)
#pragma unroll
            for (int q = 0; q < 4; q++) c_[mt][nt][q] = 0.f;

    float4 va[8];

    auto ldgA = [&](int c) {
        int k0 = kbase + c * 64;
#pragma unroll
        for (int i = 0; i < 8; i++) {
            int idx = tid + 256 * i;
            int r = idx >> 4, cg = idx & 15;
            int gr = row0 + r, k = k0 + cg * 4;
            if (gr < NN && k < 2000)
                va[i] = *reinterpret_cast<const float4*>(&hb[(long long)gr * DINN + k]);
            else
                va[i] = make_float4(0.f, 0.f, 0.f, 0.f);
        }
    };

    auto cpB = [&](int c, int buf) {
        int k0 = c * 64;
        uint32_t bH = sbase + SM_B + buf * 16384, bL = bH + 8192;
#pragma unroll
        for (int i = 0; i < 2; i++) {
            int idx = tid + 256 * i;
            int r = idx >> 3, cg = idx & 7;
            uint32_t off = (uint32_t)r * 128 +
                           (((uint32_t)cg * 16) ^ (((uint32_t)r & 7) << 4));
            CP_ASYNC16(bH + off, bhi + r * 4096 + k0 + cg * 8);
            CP_ASYNC16(bL + off, blo + r * 4096 + k0 + cg * 8);
        }
        CP_COMMIT();
    };

    auto stsA = [&](int buf) {
        uint32_t aH = SM_A + buf * 16384;
#pragma unroll
        for (int i = 0; i < 8; i++) {
            int idx = tid + 256 * i;
            int r = idx >> 4, cg = idx & 15;
            float4 v = va[i];
            __half2 h01 = __float22half2_rn(make_float2(v.x, v.y));
            __half2 h23 = __float22half2_rn(make_float2(v.z, v.w));
            uint32_t off = (uint32_t)r * 128 +
                           (((uint32_t)cg * 8) ^ (((uint32_t)r & 7) << 4));
            *reinterpret_cast<uint2*>(smem + aH + off) =
                make_uint2(*reinterpret_cast<uint32_t*>(&h01),
                           *reinterpret_cast<uint32_t*>(&h23));
        }
    };

    auto compute = [&](int buf) {
        uint32_t aH = sbase + SM_A + buf * 16384;
        uint32_t bH = sbase + SM_B + buf * 16384, bL = bH + 8192;
#pragma unroll
        for (int ks = 0; ks < 4; ks++) {
            uint32_t kb = (uint32_t)ks * 32;
            uint32_t aF[2][4];
            uint32_t b0h[4], b1h[4], b0l[4], b1l[4];
#pragma unroll
            for (int mt = 0; mt < 2; mt++) {
                uint32_t adr = aoff + (uint32_t)mt * 2048 + ((kb + acolsel) ^ swz);
                LDSM4(aF[mt], aH + adr);
            }
            LDSM4(b0h, bH + boff + ((kb + 0) ^ swz));
            LDSM4(b1h, bH + boff + ((kb + 16) ^ swz));
            LDSM4(b0l, bL + boff + ((kb + 0) ^ swz));
            LDSM4(b1l, bL + boff + ((kb + 16) ^ swz));
#pragma unroll
            for (int mt = 0; mt < 2; mt++)
#pragma unroll
                for (int nt = 0; nt < 4; nt++) {
                    MMA2(c_[mt][nt], aF[mt], b0h[nt], b1h[nt]);
                    MMA2(c_[mt][nt], aF[mt], b0l[nt], b1l[nt]);
                }
        }
    };

    ldgA(0);
    cpB(0, 0);
    stsA(0);
    CP_WAIT0();
    __syncthreads();

    for (int c = 0; c < 16; c++) {
        int buf = c & 1;
        bool more = (c + 1 < 16);
        if (more) {
            cpB(c + 1, buf ^ 1);
            ldgA(c + 1);
        }
        compute(buf);
        if (more) {
            stsA(buf ^ 1);
            CP_WAIT0();
            __syncthreads();
        }
    }

    // epilogue: atomic accumulate (scale back by 1/4096); c' applied in k_g64
    int g = lane >> 2;
    int base_r = row0 + wm * 32 + g;
    int col0 = wn * 32 + (lane & 3) * 2;
#pragma unroll
    for (int mt = 0; mt < 2; mt++) {
#pragma unroll
        for (int rr = 0; rr < 2; rr++) {
            int gr = base_r + mt * 16 + rr * 8;
            if (gr < NN) {
#pragma unroll
                for (int nt = 0; nt < 4; nt++) {
                    int col = col0 + nt * 8;
                    float2 v;
                    v.x = c_[mt][nt][rr * 2 + 0] * BINV;
                    v.y = c_[mt][nt][rr * 2 + 1] * BINV;
                    atomicAdd(reinterpret_cast<float2*>(&g_xw0[gr * 64 + col]), v);
                }
            }
        }
    }
}

// ---------------- L5-L7: scan of in-degrees -> CSR offsets + cs/cd -------------
__global__ void k_scanA() {
    __shared__ int sw[32];
    int t = threadIdx.x;
    int i = blockIdx.x * 1024 + t;
    int v = (i < NN) ? g_degD[i] : 0;
#pragma unroll
    for (int o = 16; o >= 1; o >>= 1) v += __shfl_xor_sync(0xFFFFFFFFu, v, o);
    if ((t & 31) == 0) sw[t >> 5] = v;
    __syncthreads();
    if (t < 32) {
        int x = sw[t];
#pragma unroll
        for (int o = 16; o >= 1; o >>= 1) x += __shfl_xor_sync(0xFFFFFFFFu, x, o);
        if (t == 0) g_bsum[blockIdx.x] = x;
    }
}

__global__ void k_scanB() {
    if (threadIdx.x == 0) {
        int run = 0;
        for (int i = 0; i < 49; i++) { g_boff[i] = run; run += g_bsum[i]; }
        g_off[NN] = run;
    }
}

__global__ void k_scanC() {
    __shared__ int sd[1024];
    int t = threadIdx.x;
    int i = blockIdx.x * 1024 + t;
    int v = (i < NN) ? g_degD[i] : 0;
    sd[t] = v;
    __syncthreads();
    for (int s = 1; s < 1024; s <<= 1) {
        int x = (t >= s) ? sd[t - s] : 0;
        __syncthreads();
        sd[t] += x;
        __syncthreads();
    }
    if (i < NN) {
        g_off[i] = g_boff[blockIdx.x] + sd[t] - v;
        g_cs[i] = rsqrtf(fmaxf((float)g_degS[i], 1.0f));
        g_cd[i] = rsqrtf(fmaxf((float)v, 1.0f));
    }
}

// ---- L8: atomic-free CSR fill (+ re-zero degrees for next call) ----------------
__global__ __launch_bounds__(512) void k_fill(const int* __restrict__ src,
                                              const int* __restrict__ dst) {
    int b = blockIdx.x;
    if (b < 3125) {
        int e = b * 512 + threadIdx.x;
        g_esrc[g_off[dst[e]] + g_epos[e]] = src[e];
        return;
    }
    int i = (b - 3125) * 512 + threadIdx.x;
    if (i < NN) { g_degS[i] = 0; g_degD[i] = 0; }
}

// ---------------- L9: gather cs*(xw0+c') + relu/bias/norm + GEMV 64->32 --------
__global__ __launch_bounds__(256) void k_g64(const float* __restrict__ bg0,
                                             const float* __restrict__ Wg1) {
    __shared__ float sW[64 * 32];
    __shared__ float sb[64];
    __shared__ float sc[64];
    int t = threadIdx.x;
    for (int i = t; i < 2048; i += 256) sW[i] = Wg1[i];
    if (t < 64) { sb[t] = bg0[t]; sc[t] = g_cprime[t]; }
    __syncthreads();
    int wid = t >> 5, lane = t & 31;
    int n = blockIdx.x * 8 + wid;
    if (n >= NN) return;
    int beg = g_off[n], end = g_off[n + 1];
    int half = lane >> 4, l16 = lane & 15;
    float4 acc = make_float4(0.f, 0.f, 0.f, 0.f);
    float scs = 0.f;
    int i = beg + half;
    while (i + 6 < end) {
        int s0 = __ldg(&g_esrc[i]), s1 = __ldg(&g_esrc[i + 2]);
        int s2 = __ldg(&g_esrc[i + 4]), s3 = __ldg(&g_esrc[i + 6]);
        float cs0 = __ldg(&g_cs[s0]), cs1 = __ldg(&g_cs[s1]);
        float cs2 = __ldg(&g_cs[s2]), cs3 = __ldg(&g_cs[s3]);
        float4 v0 = __ldg(reinterpret_cast<const float4*>(&g_xw0[s0 * 64 + l16 * 4]));
        float4 v1 = __ldg(reinterpret_cast<const float4*>(&g_xw0[s1 * 64 + l16 * 4]));
        float4 v2 = __ldg(reinterpret_cast<const float4*>(&g_xw0[s2 * 64 + l16 * 4]));
        float4 v3 = __ldg(reinterpret_cast<const float4*>(&g_xw0[s3 * 64 + l16 * 4]));
        acc.x += v0.x * cs0 + v1.x * cs1 + v2.x * cs2 + v3.x * cs3;
        acc.y += v0.y * cs0 + v1.y * cs1 + v2.y * cs2 + v3.y * cs3;
        acc.z += v0.z * cs0 + v1.z * cs1 + v2.z * cs2 + v3.z * cs3;
        acc.w += v0.w * cs0 + v1.w * cs1 + v2.w * cs2 + v3.w * cs3;
        scs += cs0 + cs1 + cs2 + cs3;
        i += 8;
    }
    while (i < end) {
        int s = __ldg(&g_esrc[i]);
        float cs0 = __ldg(&g_cs[s]);
        float4 v = __ldg(reinterpret_cast<const float4*>(&g_xw0[s * 64 + l16 * 4]));
        acc.x += v.x * cs0; acc.y += v.y * cs0; acc.z += v.z * cs0; acc.w += v.w * cs0;
        scs += cs0;
        i += 2;
    }
    acc.x += __shfl_xor_sync(0xFFFFFFFFu, acc.x, 16);
    acc.y += __shfl_xor_sync(0xFFFFFFFFu, acc.y, 16);
    acc.z += __shfl_xor_sync(0xFFFFFFFFu, acc.z, 16);
    acc.w += __shfl_xor_sync(0xFFFFFFFFu, acc.w, 16);
    scs   += __shfl_xor_sync(0xFFFFFFFFu, scs, 16);
    float cdv = g_cd[n], csv = g_cs[n];
    float val[4];
    val[0] = fmaxf(fmaf(fmaf(sc[l16 * 4 + 0], scs, acc.x), cdv, sb[l16 * 4 + 0]), 0.f) * csv;
    val[1] = fmaxf(fmaf(fmaf(sc[l16 * 4 + 1], scs, acc.y), cdv, sb[l16 * 4 + 1]), 0.f) * csv;
    val[2] = fmaxf(fmaf(fmaf(sc[l16 * 4 + 2], scs, acc.z), cdv, sb[l16 * 4 + 2]), 0.f) * csv;
    val[3] = fmaxf(fmaf(fmaf(sc[l16 * 4 + 3], scs, acc.w), cdv, sb[l16 * 4 + 3]), 0.f) * csv;
    float o = 0.f;
#pragma unroll
    for (int d = 0; d < 64; d++) {
        float v = __shfl_sync(0xFFFFFFFFu, val[d & 3], d >> 2);
        o = fmaf(v, sW[d * 32 + lane], o);
    }
    g_xw1[n * 32 + lane] = o;
}

// ---------------- L10: gather xw1 + relu/bias/norm + GEMV 32->4 -> xw2 ----------
__global__ __launch_bounds__(256) void k_g32(const float* __restrict__ bg1,
                                             const float* __restrict__ Wg2) {
    __shared__ float sW[32 * 4];
    __shared__ float sb[32];
    int t = threadIdx.x;
    if (t < 128) sW[t] = Wg2[t];
    if (t < 32) sb[t] = bg1[t];
    __syncthreads();
    int wid = t >> 5, lane = t & 31;
    int n = blockIdx.x * 8 + wid;
    if (n >= NN) return;
    int beg = g_off[n], end = g_off[n + 1];
    int q = lane >> 3, l8 = lane & 7;
    float4 acc = make_float4(0.f, 0.f, 0.f, 0.f);
    int i = beg + q;
    while (i + 12 < end) {
        int s0 = __ldg(&g_esrc[i]), s1 = __ldg(&g_esrc[i + 4]);
        int s2 = __ldg(&g_esrc[i + 8]), s3 = __ldg(&g_esrc[i + 12]);
        float4 v0 = __ldg(reinterpret_cast<const float4*>(&g_xw1[s0 * 32 + l8 * 4]));
        float4 v1 = __ldg(reinterpret_cast<const float4*>(&g_xw1[s1 * 32 + l8 * 4]));
        float4 v2 = __ldg(reinterpret_cast<const float4*>(&g_xw1[s2 * 32 + l8 * 4]));
        float4 v3 = __ldg(reinterpret_cast<const float4*>(&g_xw1[s3 * 32 + l8 * 4]));
        acc.x += v0.x + v1.x + v2.x + v3.x;
        acc.y += v0.y + v1.y + v2.y + v3.y;
        acc.z += v0.z + v1.z + v2.z + v3.z;
        acc.w += v0.w + v1.w + v2.w + v3.w;
        i += 16;
    }
    while (i < end) {
        int s = __ldg(&g_esrc[i]);
        float4 v = __ldg(reinterpret_cast<const float4*>(&g_xw1[s * 32 + l8 * 4]));
        acc.x += v.x; acc.y += v.y; acc.z += v.z; acc.w += v.w;
        i += 4;
    }
    acc.x += __shfl_xor_sync(0xFFFFFFFFu, acc.x, 8);
    acc.y += __shfl_xor_sync(0xFFFFFFFFu, acc.y, 8);
    acc.z += __shfl_xor_sync(0xFFFFFFFFu, acc.z, 8);
    acc.w += __shfl_xor_sync(0xFFFFFFFFu, acc.w, 8);
    acc.x += __shfl_xor_sync(0xFFFFFFFFu, acc.x, 16);
    acc.y += __shfl_xor_sync(0xFFFFFFFFu, acc.y, 16);
    acc.z += __shfl_xor_sync(0xFFFFFFFFu, acc.z, 16);
    acc.w += __shfl_xor_sync(0xFFFFFFFFu, acc.w, 16);
    float cdv = g_cd[n], csv = g_cs[n];
    float val[4];
    val[0] = fmaxf(fmaf(acc.x, cdv, sb[l8 * 4 + 0]), 0.f) * csv;
    val[1] = fmaxf(fmaf(acc.y, cdv, sb[l8 * 4 + 1]), 0.f) * csv;
    val[2] = fmaxf(fmaf(acc.z, cdv, sb[l8 * 4 + 2]), 0.f) * csv;
    val[3] = fmaxf(fmaf(acc.w, cdv, sb[l8 * 4 + 3]), 0.f) * csv;
    float o = 0.f;
#pragma unroll
    for (int d = 0; d < 32; d++) {
        float v = __shfl_sync(0xFFFFFFFFu, val[d & 3], d >> 2);
        o = fmaf(v, sW[d * 4 + (lane & 3)], o);
    }
    if (lane < 4) g_xw2[n * 4 + lane] = o;
}

// ---------------- L11: gather xw2 + bias -> out ----------------
__global__ __launch_bounds__(256) void k_g4(const float* __restrict__ bg2,
                                            float* __restrict__ out) {
    int t = threadIdx.x;
    int wid = t >> 5, lane = t & 31;
    int n = blockIdx.x * 8 + wid;
    if (n >= NN) return;
    int beg = g_off[n], end = g_off[n + 1];
    float4 acc = make_float4(0.f, 0.f, 0.f, 0.f);
    for (int i = beg + lane; i < end; i += 32) {
        int s = __ldg(&g_esrc[i]);
        float4 v = __ldg(reinterpret_cast<const float4*>(&g_xw2[s * 4]));
        acc.x += v.x; acc.y += v.y; acc.z += v.z; acc.w += v.w;
    }
#pragma unroll
    for (int off = 16; off >= 1; off >>= 1) {
        acc.x += __shfl_xor_sync(0xFFFFFFFFu, acc.x, off);
        acc.y += __shfl_xor_sync(0xFFFFFFFFu, acc.y, off);
        acc.z += __shfl_xor_sync(0xFFFFFFFFu, acc.z, off);
        acc.w += __shfl_xor_sync(0xFFFFFFFFu, acc.w, off);
    }
    if (lane == 0) {
        float cdv = g_cd[n];
        float4 o;
        o.x = fmaf(acc.x, cdv, bg2[0]);
        o.y = fmaf(acc.y, cdv, bg2[1]);
        o.z = fmaf(acc.z, cdv, bg2[2]);
        o.w = fmaf(acc.w, cdv, bg2[3]);
        *reinterpret_cast<float4*>(&out[n * 4]) = o;
    }
}

// ---------------- launch ----------------
extern "C" void kernel_launch(void* const* d_in, const int* in_sizes, int n_in,
                              void* d_out, int out_size) {
    const float* h   = (const float*)d_in[0];
    const int*   src = (const int*)d_in[1];
    const int*   dst = (const int*)d_in[2];
    const float* W1  = (const float*)d_in[3];
    const float* b1  = (const float*)d_in[4];
    const float* g1  = (const float*)d_in[5];
    const float* be1 = (const float*)d_in[6];
    const float* m1  = (const float*)d_in[7];
    const float* v1  = (const float*)d_in[8];
    const float* W2  = (const float*)d_in[9];
    const float* b2  = (const float*)d_in[10];
    const float* g2  = (const float*)d_in[11];
    const float* be2 = (const float*)d_in[12];
    const float* m2  = (const float*)d_in[13];
    const float* v2  = (const float*)d_in[14];
    const float* Wd  = (const float*)d_in[15];
    const float* bd  = (const float*)d_in[16];
    const float* Wg0 = (const float*)d_in[17];
    const float* bg0 = (const float*)d_in[18];
    const float* Wg1 = (const float*)d_in[19];
    const float* bg1 = (const float*)d_in[20];
    const float* Wg2 = (const float*)d_in[21];
    const float* bg2 = (const float*)d_in[22];
    float* out = (float*)d_out;

    cudaFuncSetAttribute(k_gemm_hmma, cudaFuncAttributeMaxDynamicSharedMemorySize,
                         SMEM_BYTES);

    k_fold<<<3326, 512>>>(src, dst, b1, g1, be1, m1, v1, W2, b2, g2,  // 1
                          be2, m2, v2, Wd, bd, Wg0);
    k_R<<<dim3(63, 2), 64>>>(W2);                                     // 2
    k_MB<<<dim3(250, 2), 256>>>(W1);                                  // 3
    k_gemm_hmma<<<dim3(391, 4), 256, SMEM_BYTES>>>(h);                // 4 <- ncu
    k_scanA<<<49, 1024>>>();                                          // 5
    k_scanB<<<1, 32>>>();                                             // 6
    k_scanC<<<49, 1024>>>();                                          // 7
    k_fill<<<3223, 512>>>(src, dst);                                  // 8
    k_g64<<<(NN + 7) / 8, 256>>>(bg0, Wg1);                           // 9
    k_g32<<<(NN + 7) / 8, 256>>>(bg1, Wg2);                           // 10
    k_g4<<<(NN + 7) / 8, 256>>>(bg2, out);                            // 11
}

// round 8
// speedup vs baseline: 3.0601x; 1.0806x over previous
#include <cuda_runtime.h>
#include <cuda_fp16.h>
#include <cstdint>

#define NN   50000
#define EE   1600000
#define DINN 2000
#define BSCALE 4096.0f
#define BINV   (1.0f / 4096.0f)

// ---------------- device scratch (allocation-free contract) ----------------
__device__ float g_alpha1[2 * 500];
__device__ float g_bb1[2 * 500];
__device__ float g_alpha2[2 * 128];
__device__ float g_t2b[2 * 128];
__device__ float g_cmean[64];
__device__ float g_cprime[64];
__device__ float g_Wde2[2 * 128 * 64];   // 0.5 * alpha2[l] * (Wd @ Wg0)
__device__ float g_R[2 * 500 * 64];      // W2 @ Wde2
__device__ __half g_Bhi[64 * 4096];      // [e][m*2048+k] hi of 4096*M^T (pad zero)
__device__ __half g_Blo[64 * 4096];      // lo
__device__ float g_xw0[NN * 64];         // sum h@M partials (no c'; cs at gather)
__device__ float g_xw1[NN * 32];
__device__ float g_xw2[NN * 4];
__device__ float g_cs[NN];
__device__ float g_cd[NN];
__device__ int   g_degS[NN];             // zero at load; re-zeroed each call
__device__ int   g_degD[NN];
__device__ int   g_off[NN + 1];
__device__ int   g_epos[EE];
__device__ int   g_esrc[EE];
__device__ int   g_bsum[128];

// ---------------- PTX helpers ----------------
__device__ __forceinline__ uint32_t smem_u32(const void* p) {
    uint32_t a;
    asm("{ .reg .u64 t; cvta.to.shared.u64 t, %1; cvt.u32.u64 %0, t; }"
        : "=r"(a) : "l"(p));
    return a;
}

#define LDSM4(r, a) \
    asm volatile("ldmatrix.sync.aligned.m8n8.x4.shared.b16 {%0,%1,%2,%3}, [%4];" \
                 : "=r"((r)[0]), "=r"((r)[1]), "=r"((r)[2]), "=r"((r)[3]) : "r"(a))

#define MMA2(c, a, b0, b1) \
    asm volatile( \
        "mma.sync.aligned.m16n8k16.row.col.f32.f16.f16.f32 " \
        "{%0,%1,%2,%3}, {%4,%5,%6,%7}, {%8,%9}, {%0,%1,%2,%3};" \
        : "+f"((c)[0]), "+f"((c)[1]), "+f"((c)[2]), "+f"((c)[3]) \
        : "r"((a)[0]), "r"((a)[1]), "r"((a)[2]), "r"((a)[3]), \
          "r"(b0), "r"(b1))

#define CP_ASYNC16(dst, src) \
    asm volatile("cp.async.cg.shared.global [%0], [%1], 16;" \
                 :: "r"(dst), "l"(src) : "memory")
#define CP_COMMIT() asm volatile("cp.async.commit_group;" ::: "memory")
#define CP_WAIT0()  asm volatile("cp.async.wait_group 0;" ::: "memory")

// ---- L1: fold (blk 0) + degrees/epos (blk 1..3125) + zero xw0 (rest) ----------
__global__ __launch_bounds__(512) void k_fold(
    const int* __restrict__ src, const int* __restrict__ dst,
    const float* __restrict__ b1, const float* __restrict__ g1,
    const float* __restrict__ be1, const float* __restrict__ m1,
    const float* __restrict__ v1, const float* __restrict__ W2,
    const float* __restrict__ b2, const float* __restrict__ g2,
    const float* __restrict__ be2, const float* __restrict__ m2,
    const float* __restrict__ v2, const float* __restrict__ Wd,
    const float* __restrict__ bd, const float* __restrict__ Wg0) {
    int b = blockIdx.x;
    if (b >= 1 && b <= 3125) {
        int e = (b - 1) * 512 + threadIdx.x;
        if (e < EE) {
            g_epos[e] = atomicAdd(&g_degD[dst[e]], 1);
            atomicAdd(&g_degS[src[e]], 1);
        }
        return;
    }
    if (b > 3125) {
        float4 z = make_float4(0.f, 0.f, 0.f, 0.f);
        for (int i = (b - 3126) * 512 + threadIdx.x; i < NN * 16; i += 200 * 512)
            reinterpret_cast<float4*>(g_xw0)[i] = z;
        return;
    }
    __shared__ float sWg0[64 * 64];
    int t = threadIdx.x;
    for (int i = t; i < 1000; i += 512) {
        float a = g1[i] * rsqrtf(v1[i] + 1e-5f);
        g_alpha1[i] = a;
        g_bb1[i] = (b1[i] - m1[i]) * a + be1[i];
    }
    for (int i = t; i < 256; i += 512)
        g_alpha2[i] = g2[i] * rsqrtf(v2[i] + 1e-5f);
    for (int i = t; i < 4096; i += 512) sWg0[i] = Wg0[i];
    __syncthreads();
    for (int i = t; i < 256; i += 512) {
        int mm = i >> 7, l = i & 127;
        float s = 0.f;
        for (int j = 0; j < 500; j++)
            s += g_bb1[mm * 500 + j] * W2[mm * 64000 + j * 128 + l];
        g_t2b[i] = (s + b2[i] - m2[i]) * g_alpha2[i] + be2[i];
    }
    for (int idx = t; idx < 16384; idx += 512) {
        int m = idx >> 13, rem = idx & 8191, l = rem >> 6, e = rem & 63;
        float s = 0.f;
        for (int d = 0; d < 64; d++)
            s += Wd[m * 8192 + l * 64 + d] * sWg0[d * 64 + e];
        g_Wde2[idx] = 0.5f * g_alpha2[m * 128 + l] * s;
    }
    __syncthreads();
    for (int d = t; d < 64; d += 512) {
        float s = 0.f;
        for (int mm = 0; mm < 2; mm++) {
            float sm = bd[mm * 64 + d];
            for (int l = 0; l < 128; l++)
                sm += g_t2b[mm * 128 + l] * Wd[mm * 8192 + l * 64 + d];
            s += sm;
        }
        g_cmean[d] = 0.5f * s;
    }
    __syncthreads();
    for (int e = t; e < 64; e += 512) {
        float s = 0.f;
        for (int d = 0; d < 64; d++) s += g_cmean[d] * sWg0[d * 64 + e];
        g_cprime[e] = s;
    }
}

// ---- L2: R (blocks 0..125, 64 thr active) + scanA (blocks 126..223) -----------
__global__ __launch_bounds__(512) void k_Rscan(const float* __restrict__ W2) {
    int b = blockIdx.x;
    int t = threadIdx.x;
    if (b < 126) {
        if (t >= 64) return;
        __shared__ float sW2[8][128];
        int m = b / 63, j0 = (b % 63) * 8;
        for (int idx = t; idx < 1024; idx += 64) {
            int r = idx >> 7, l = idx & 127;
            int j = j0 + r;
            sW2[r][l] = (j < 500) ? W2[m * 64000 + j * 128 + l] : 0.f;
        }
        __syncthreads();
        int e = t;
        float acc[8] = {0, 0, 0, 0, 0, 0, 0, 0};
        for (int l = 0; l < 128; l++) {
            float w = g_Wde2[m * 8192 + l * 64 + e];
#pragma unroll
            for (int r = 0; r < 8; r++) acc[r] += sW2[r][l] * w;
        }
#pragma unroll
        for (int r = 0; r < 8; r++) {
            int j = j0 + r;
            if (j < 500) g_R[m * 32000 + j * 64 + e] = acc[r];
        }
        return;
    }
    // scanA: block sums of degD (98 blocks of 512)
    __shared__ int sw[16];
    int bid = b - 126;
    int i = bid * 512 + t;
    int v = (i < NN) ? g_degD[i] : 0;
#pragma unroll
    for (int o = 16; o >= 1; o >>= 1) v += __shfl_xor_sync(0xFFFFFFFFu, v, o);
    if ((t & 31) == 0) sw[t >> 5] = v;
    __syncthreads();
    if (t < 32) {
        int x = (t < 16) ? sw[t] : 0;
#pragma unroll
        for (int o = 8; o >= 1; o >>= 1) x += __shfl_xor_sync(0xFFFFFFFFu, x, o);
        if (t == 0) g_bsum[bid] = x;
    }
}

// ---- L3: MB (blocks 0..499, 256 thr active) + scanC (blocks 500..597) ---------
__global__ __launch_bounds__(512) void k_MBscan(const float* __restrict__ W1) {
    int b = blockIdx.x;
    int t = threadIdx.x;
    if (b < 500) {
        if (t >= 256) return;
        __shared__ float sA[8][500];
        __shared__ float red[3][8][64];
        int m = b / 250, i0 = (b % 250) * 8;
        for (int idx = t; idx < 4000; idx += 256) {
            int r = idx / 500, j = idx - r * 500;
            sA[r][j] = W1[m * 1000000 + (i0 + r) * 500 + j] * g_alpha1[m * 500 + j];
        }
        __syncthreads();
        int e = t & 63, jp = t >> 6;
        float acc[8] = {0, 0, 0, 0, 0, 0, 0, 0};
        for (int j = jp; j < 500; j += 4) {
            float w = g_R[m * 32000 + j * 64 + e];
#pragma unroll
            for (int r = 0; r < 8; r++) acc[r] += sA[r][j] * w;
        }
        if (jp > 0) {
#pragma unroll
            for (int r = 0; r < 8; r++) red[jp - 1][r][e] = acc[r];
        }
        __syncthreads();
        if (jp == 0) {
#pragma unroll
            for (int r = 0; r < 8; r++) {
                float v = (acc[r] + red[0][r][e] + red[1][r][e] + red[2][r][e]) * BSCALE;
                __half hi = __float2half_rn(v);
                g_Bhi[e * 4096 + m * 2048 + i0 + r] = hi;
                g_Blo[e * 4096 + m * 2048 + i0 + r] = __float2half_rn(v - __half2float(hi));
            }
        }
        return;
    }
    // scanC: CSR offsets + cs/cd
    __shared__ int sd[512];
    __shared__ int sboff;
    int bid = b - 500;
    int i = bid * 512 + t;
    int v = (i < NN) ? g_degD[i] : 0;
    sd[t] = v;
    __syncthreads();
    for (int s = 1; s < 512; s <<= 1) {
        int x = (t >= s) ? sd[t - s] : 0;
        __syncthreads();
        sd[t] += x;
        __syncthreads();
    }
    if (t == 0) {
        int run = 0;
        for (int j = 0; j < bid; j++) run += g_bsum[j];
        sboff = run;
        if (bid == 0) g_off[NN] = EE;
    }
    __syncthreads();
    if (i < NN) {
        g_off[i] = sboff + sd[t] - v;
        g_cs[i] = rsqrtf(fmaxf((float)g_degS[i], 1.0f));
        g_cd[i] = rsqrtf(fmaxf((float)v, 1.0f));
    }
}

// ---- L4: 64x64-tile HMMA GEMM (splitK=4) + CSR fill + degree rezero ------------
// Blocks 0..3127: GEMM (x = b%782 row-tile, y = b/782 -> m,khalf), 128 thr, 4 CTA/SM.
// Blocks 3128..6252: CSR fill.  Blocks 6253..6350: rezero degrees.
#define SM_A 0                       // 2 buf x 8192 (fp16 A-hi, 64 rows)
#define SM_B 16384                   // 2 buf x (8192 hi + 8192 lo)
#define SMEM_BYTES 49152
#define GEMM_BLKS 3128
#define FILL_BLKS 3125

__global__ __launch_bounds__(128, 4) void k_gemm_hmma(const float* __restrict__ h,
                                                      const int* __restrict__ src,
                                                      const int* __restrict__ dst) {
    int b = blockIdx.x;
    int tid = threadIdx.x;
    if (b >= GEMM_BLKS) {
        if (b < GEMM_BLKS + FILL_BLKS) {
            int e0 = (b - GEMM_BLKS) * 512;
#pragma unroll
            for (int it = 0; it < 4; it++) {
                int e = e0 + it * 128 + tid;
                g_esrc[g_off[dst[e]] + g_epos[e]] = src[e];
            }
        } else {
            int i0 = (b - GEMM_BLKS - FILL_BLKS) * 512;
#pragma unroll
            for (int it = 0; it < 4; it++) {
                int i = i0 + it * 128 + tid;
                if (i < NN) { g_degS[i] = 0; g_degD[i] = 0; }
            }
        }
        return;
    }

    extern __shared__ __align__(1024) char smem[];
    uint32_t sbase = smem_u32(smem);
    int lane = tid & 31, wid = tid >> 5;
    int wm = wid >> 1, wn = wid & 1;
    int bx = b % 782, by = b / 782;
    int row0 = bx * 64;
    int m = by >> 1, kh = by & 1;
    const float* hb = h + (long long)m * NN * DINN;
    const __half* bhi = g_Bhi + m * 2048 + kh * 1024;
    const __half* blo = g_Blo + m * 2048 + kh * 1024;
    int kbase = kh * 1024;

    uint32_t swz = (uint32_t)(lane & 7) << 4;
    uint32_t aoff = (uint32_t)(wm * 32 + (lane & 15)) * 128;
    uint32_t acolsel = (uint32_t)(lane >> 4) << 4;
    uint32_t boff = (uint32_t)(wn * 32 + lane) * 128;

    float c_[2][4][4];
#pragma unroll
    for (int mt = 0; mt < 2; mt++)
#pragma unroll
        for (int nt = 0; nt < 4; nt++)
#pragma unroll
            for (int q = 0; q < 4; q++) c_[mt][nt][q] = 0.f;

    float4 va[8];

    auto ldgA = [&](int c) {
        int k0 = kbase + c * 64;
        const float* base = hb + (long long)row0 * DINN + k0;
        if (row0 + 64 <= NN && k0 + 64 <= 2000) {
#pragma unroll
            for (int i = 0; i < 8; i++) {
                int idx = tid + 128 * i;
                int r = idx >> 4, cg = idx & 15;
                va[i] = *reinterpret_cast<const float4*>(base + (long long)r * DINN + cg * 4);
            }
        } else {
#pragma unroll
            for (int i = 0; i < 8; i++) {
                int idx = tid + 128 * i;
                int r = idx >> 4, cg = idx & 15;
                if (row0 + r < NN && k0 + cg * 4 + 3 < 2000)
                    va[i] = *reinterpret_cast<const float4*>(base + (long long)r * DINN + cg * 4);
                else
                    va[i] = make_float4(0.f, 0.f, 0.f, 0.f);
            }
        }
    };

    auto cpB = [&](int c, int buf) {
        int k0 = c * 64;
        uint32_t bH = sbase + SM_B + buf * 16384, bL = bH + 8192;
#pragma unroll
        for (int i = 0; i < 4; i++) {
            int idx = tid + 128 * i;
            int r = idx >> 3, cg = idx & 7;
            uint32_t off = (uint32_t)r * 128 +
                           (((uint32_t)cg * 16) ^ (((uint32_t)r & 7) << 4));
            CP_ASYNC16(bH + off, bhi + r * 4096 + k0 + cg * 8);
            CP_ASYNC16(bL + off, blo + r * 4096 + k0 + cg * 8);
        }
        CP_COMMIT();
    };

    auto stsA = [&](int buf) {
        uint32_t aH = SM_A + buf * 8192;
#pragma unroll
        for (int i = 0; i < 8; i++) {
            int idx = tid + 128 * i;
            int r = idx >> 4, cg = idx & 15;
            float4 v = va[i];
            __half2 h01 = __float22half2_rn(make_float2(v.x, v.y));
            __half2 h23 = __float22half2_rn(make_float2(v.z, v.w));
            uint32_t off = (uint32_t)r * 128 +
                           (((uint32_t)cg * 8) ^ (((uint32_t)r & 7) << 4));
            *reinterpret_cast<uint2*>(smem + aH + off) =
                make_uint2(*reinterpret_cast<uint32_t*>(&h01),
                           *reinterpret_cast<uint32_t*>(&h23));
        }
    };

    auto compute = [&](int buf) {
        uint32_t aH = sbase + SM_A + buf * 8192;
        uint32_t bH = sbase + SM_B + buf * 16384, bL = bH + 8192;
#pragma unroll
        for (int ks = 0; ks < 4; ks++) {
            uint32_t kb = (uint32_t)ks * 32;
            uint32_t aF[2][4];
            uint32_t b0h[4], b1h[4], b0l[4], b1l[4];
#pragma unroll
            for (int mt = 0; mt < 2; mt++) {
                uint32_t adr = aoff + (uint32_t)mt * 2048 + ((kb + acolsel) ^ swz);
                LDSM4(aF[mt], aH + adr);
            }
            LDSM4(b0h, bH + boff + ((kb + 0) ^ swz));
            LDSM4(b1h, bH + boff + ((kb + 16) ^ swz));
            LDSM4(b0l, bL + boff + ((kb + 0) ^ swz));
            LDSM4(b1l, bL + boff + ((kb + 16) ^ swz));
#pragma unroll
            for (int mt = 0; mt < 2; mt++)
#pragma unroll
                for (int nt = 0; nt < 4; nt++) {
                    MMA2(c_[mt][nt], aF[mt], b0h[nt], b1h[nt]);
                    MMA2(c_[mt][nt], aF[mt], b0l[nt], b1l[nt]);
                }
        }
    };

    ldgA(0);
    cpB(0, 0);
    stsA(0);
    CP_WAIT0();
    __syncthreads();

    for (int c = 0; c < 16; c++) {
        int buf = c & 1;
        bool more = (c + 1 < 16);
        if (more) {
            ldgA(c + 1);
            cpB(c + 1, buf ^ 1);
        }
        compute(buf);
        if (more) {
            stsA(buf ^ 1);
            CP_WAIT0();
            __syncthreads();
        }
    }

    int g = lane >> 2;
    int base_r = row0 + wm * 32 + g;
    int col0 = wn * 32 + (lane & 3) * 2;
#pragma unroll
    for (int mt = 0; mt < 2; mt++) {
#pragma unroll
        for (int rr = 0; rr < 2; rr++) {
            int gr = base_r + mt * 16 + rr * 8;
            if (gr < NN) {
#pragma unroll
                for (int nt = 0; nt < 4; nt++) {
                    int col = col0 + nt * 8;
                    float2 v;
                    v.x = c_[mt][nt][rr * 2 + 0] * BINV;
                    v.y = c_[mt][nt][rr * 2 + 1] * BINV;
                    atomicAdd(reinterpret_cast<float2*>(&g_xw0[gr * 64 + col]), v);
                }
            }
        }
    }
}

// ---------------- L5: gather cs*(xw0+c') + relu/bias/norm + GEMV 64->32 --------
__global__ __launch_bounds__(256) void k_g64(const float* __restrict__ bg0,
                                             const float* __restrict__ Wg1) {
    __shared__ float sW[64 * 32];
    __shared__ float sb[64];
    __shared__ float sc[64];
    int t = threadIdx.x;
    for (int i = t; i < 2048; i += 256) sW[i] = Wg1[i];
    if (t < 64) { sb[t] = bg0[t]; sc[t] = g_cprime[t]; }
    __syncthreads();
    int wid = t >> 5, lane = t & 31;
    int n = blockIdx.x * 8 + wid;
    if (n >= NN) return;
    int beg = g_off[n], end = g_off[n + 1];
    int half = lane >> 4, l16 = lane & 15;
    float4 acc = make_float4(0.f, 0.f, 0.f, 0.f);
    float scs = 0.f;
    int i = beg + half;
    while (i + 6 < end) {
        int s0 = __ldg(&g_esrc[i]), s1 = __ldg(&g_esrc[i + 2]);
        int s2 = __ldg(&g_esrc[i + 4]), s3 = __ldg(&g_esrc[i + 6]);
        float cs0 = __ldg(&g_cs[s0]), cs1 = __ldg(&g_cs[s1]);
        float cs2 = __ldg(&g_cs[s2]), cs3 = __ldg(&g_cs[s3]);
        float4 v0 = __ldg(reinterpret_cast<const float4*>(&g_xw0[s0 * 64 + l16 * 4]));
        float4 v1 = __ldg(reinterpret_cast<const float4*>(&g_xw0[s1 * 64 + l16 * 4]));
        float4 v2 = __ldg(reinterpret_cast<const float4*>(&g_xw0[s2 * 64 + l16 * 4]));
        float4 v3 = __ldg(reinterpret_cast<const float4*>(&g_xw0[s3 * 64 + l16 * 4]));
        acc.x += v0.x * cs0 + v1.x * cs1 + v2.x * cs2 + v3.x * cs3;
        acc.y += v0.y * cs0 + v1.y * cs1 + v2.y * cs2 + v3.y * cs3;
        acc.z += v0.z * cs0 + v1.z * cs1 + v2.z * cs2 + v3.z * cs3;
        acc.w += v0.w * cs0 + v1.w * cs1 + v2.w * cs2 + v3.w * cs3;
        scs += cs0 + cs1 + cs2 + cs3;
        i += 8;
    }
    while (i < end) {
        int s = __ldg(&g_esrc[i]);
        float cs0 = __ldg(&g_cs[s]);
        float4 v = __ldg(reinterpret_cast<const float4*>(&g_xw0[s * 64 + l16 * 4]));
        acc.x += v.x * cs0; acc.y += v.y * cs0; acc.z += v.z * cs0; acc.w += v.w * cs0;
        scs += cs0;
        i += 2;
    }
    acc.x += __shfl_xor_sync(0xFFFFFFFFu, acc.x, 16);
    acc.y += __shfl_xor_sync(0xFFFFFFFFu, acc.y, 16);
    acc.z += __shfl_xor_sync(0xFFFFFFFFu, acc.z, 16);
    acc.w += __shfl_xor_sync(0xFFFFFFFFu, acc.w, 16);
    scs   += __shfl_xor_sync(0xFFFFFFFFu, scs, 16);
    float cdv = g_cd[n], csv = g_cs[n];
    float val[4];
    val[0] = fmaxf(fmaf(fmaf(sc[l16 * 4 + 0], scs, acc.x), cdv, sb[l16 * 4 + 0]), 0.f) * csv;
    val[1] = fmaxf(fmaf(fmaf(sc[l16 * 4 + 1], scs, acc.y), cdv, sb[l16 * 4 + 1]), 0.f) * csv;
    val[2] = fmaxf(fmaf(fmaf(sc[l16 * 4 + 2], scs, acc.z), cdv, sb[l16 * 4 + 2]), 0.f) * csv;
    val[3] = fmaxf(fmaf(fmaf(sc[l16 * 4 + 3], scs, acc.w), cdv, sb[l16 * 4 + 3]), 0.f) * csv;
    float o = 0.f;
#pragma unroll
    for (int d = 0; d < 64; d++) {
        float v = __shfl_sync(0xFFFFFFFFu, val[d & 3], d >> 2);
        o = fmaf(v, sW[d * 32 + lane], o);
    }
    g_xw1[n * 32 + lane] = o;
}

// ---------------- L6: gather xw1 + relu/bias/norm + GEMV 32->4 -> xw2 ----------
__global__ __launch_bounds__(256) void k_g32(const float* __restrict__ bg1,
                                             const float* __restrict__ Wg2) {
    __shared__ float sW[32 * 4];
    __shared__ float sb[32];
    int t = threadIdx.x;
    if (t < 128) sW[t] = Wg2[t];
    if (t < 32) sb[t] = bg1[t];
    __syncthreads();
    int wid = t >> 5, lane = t & 31;
    int n = blockIdx.x * 8 + wid;
    if (n >= NN) return;
    int beg = g_off[n], end = g_off[n + 1];
    int q = lane >> 3, l8 = lane & 7;
    float4 acc = make_float4(0.f, 0.f, 0.f, 0.f);
    int i = beg + q;
    while (i + 12 < end) {
        int s0 = __ldg(&g_esrc[i]), s1 = __ldg(&g_esrc[i + 4]);
        int s2 = __ldg(&g_esrc[i + 8]), s3 = __ldg(&g_esrc[i + 12]);
        float4 v0 = __ldg(reinterpret_cast<const float4*>(&g_xw1[s0 * 32 + l8 * 4]));
        float4 v1 = __ldg(reinterpret_cast<const float4*>(&g_xw1[s1 * 32 + l8 * 4]));
        float4 v2 = __ldg(reinterpret_cast<const float4*>(&g_xw1[s2 * 32 + l8 * 4]));
        float4 v3 = __ldg(reinterpret_cast<const float4*>(&g_xw1[s3 * 32 + l8 * 4]));
        acc.x += v0.x + v1.x + v2.x + v3.x;
        acc.y += v0.y + v1.y + v2.y + v3.y;
        acc.z += v0.z + v1.z + v2.z + v3.z;
        acc.w += v0.w + v1.w + v2.w + v3.w;
        i += 16;
    }
    while (i < end) {
        int s = __ldg(&g_esrc[i]);
        float4 v = __ldg(reinterpret_cast<const float4*>(&g_xw1[s * 32 + l8 * 4]));
        acc.x += v.x; acc.y += v.y; acc.z += v.z; acc.w += v.w;
        i += 4;
    }
    acc.x += __shfl_xor_sync(0xFFFFFFFFu, acc.x, 8);
    acc.y += __shfl_xor_sync(0xFFFFFFFFu, acc.y, 8);
    acc.z += __shfl_xor_sync(0xFFFFFFFFu, acc.z, 8);
    acc.w += __shfl_xor_sync(0xFFFFFFFFu, acc.w, 8);
    acc.x += __shfl_xor_sync(0xFFFFFFFFu, acc.x, 16);
    acc.y += __shfl_xor_sync(0xFFFFFFFFu, acc.y, 16);
    acc.z += __shfl_xor_sync(0xFFFFFFFFu, acc.z, 16);
    acc.w += __shfl_xor_sync(0xFFFFFFFFu, acc.w, 16);
    float cdv = g_cd[n], csv = g_cs[n];
    float val[4];
    val[0] = fmaxf(fmaf(acc.x, cdv, sb[l8 * 4 + 0]), 0.f) * csv;
    val[1] = fmaxf(fmaf(acc.y, cdv, sb[l8 * 4 + 1]), 0.f) * csv;
    val[2] = fmaxf(fmaf(acc.z, cdv, sb[l8 * 4 + 2]), 0.f) * csv;
    val[3] = fmaxf(fmaf(acc.w, cdv, sb[l8 * 4 + 3]), 0.f) * csv;
    float o = 0.f;
#pragma unroll
    for (int d = 0; d < 32; d++) {
        float v = __shfl_sync(0xFFFFFFFFu, val[d & 3], d >> 2);
        o = fmaf(v, sW[d * 4 + (lane & 3)], o);
    }
    if (lane < 4) g_xw2[n * 4 + lane] = o;
}

// ---------------- L7: gather xw2 + bias -> out ----------------
__global__ __launch_bounds__(256) void k_g4(const float* __restrict__ bg2,
                                            float* __restrict__ out) {
    int t = threadIdx.x;
    int wid = t >> 5, lane = t & 31;
    int n = blockIdx.x * 8 + wid;
    if (n >= NN) return;
    int beg = g_off[n], end = g_off[n + 1];
    float4 acc = make_float4(0.f, 0.f, 0.f, 0.f);
    for (int i = beg + lane; i < end; i += 32) {
        int s = __ldg(&g_esrc[i]);
        float4 v = __ldg(reinterpret_cast<const float4*>(&g_xw2[s * 4]));
        acc.x += v.x; acc.y += v.y; acc.z += v.z; acc.w += v.w;
    }
#pragma unroll
    for (int off = 16; off >= 1; off >>= 1) {
        acc.x += __shfl_xor_sync(0xFFFFFFFFu, acc.x, off);
        acc.y += __shfl_xor_sync(0xFFFFFFFFu, acc.y, off);
        acc.z += __shfl_xor_sync(0xFFFFFFFFu, acc.z, off);
        acc.w += __shfl_xor_sync(0xFFFFFFFFu, acc.w, off);
    }
    if (lane == 0) {
        float cdv = g_cd[n];
        float4 o;
        o.x = fmaf(acc.x, cdv, bg2[0]);
        o.y = fmaf(acc.y, cdv, bg2[1]);
        o.z = fmaf(acc.z, cdv, bg2[2]);
        o.w = fmaf(acc.w, cdv, bg2[3]);
        *reinterpret_cast<float4*>(&out[n * 4]) = o;
    }
}

// ---------------- launch ----------------
extern "C" void kernel_launch(void* const* d_in, const int* in_sizes, int n_in,
                              void* d_out, int out_size) {
    const float* h   = (const float*)d_in[0];
    const int*   src = (const int*)d_in[1];
    const int*   dst = (const int*)d_in[2];
    const float* W1  = (const float*)d_in[3];
    const float* b1  = (const float*)d_in[4];
    const float* g1  = (const float*)d_in[5];
    const float* be1 = (const float*)d_in[6];
    const float* m1  = (const float*)d_in[7];
    const float* v1  = (const float*)d_in[8];
    const float* W2  = (const float*)d_in[9];
    const float* b2  = (const float*)d_in[10];
    const float* g2  = (const float*)d_in[11];
    const float* be2 = (const float*)d_in[12];
    const float* m2  = (const float*)d_in[13];
    const float* v2  = (const float*)d_in[14];
    const float* Wd  = (const float*)d_in[15];
    const float* bd  = (const float*)d_in[16];
    const float* Wg0 = (const float*)d_in[17];
    const float* bg0 = (const float*)d_in[18];
    const float* Wg1 = (const float*)d_in[19];
    const float* bg1 = (const float*)d_in[20];
    const float* Wg2 = (const float*)d_in[21];
    const float* bg2 = (const float*)d_in[22];
    float* out = (float*)d_out;

    cudaFuncSetAttribute(k_gemm_hmma, cudaFuncAttributeMaxDynamicSharedMemorySize,
                         SMEM_BYTES);

    k_fold<<<3326, 512>>>(src, dst, b1, g1, be1, m1, v1, W2, b2, g2,   // 1
                          be2, m2, v2, Wd, bd, Wg0);
    k_Rscan<<<224, 512>>>(W2);                                         // 2
    k_MBscan<<<598, 512>>>(W1);                                        // 3
    k_gemm_hmma<<<6351, 128, SMEM_BYTES>>>(h, src, dst);               // 4 <- ncu
    k_g64<<<(NN + 7) / 8, 256>>>(bg0, Wg1);                            // 5
    k_g32<<<(NN + 7) / 8, 256>>>(bg1, Wg2);                            // 6
    k_g4<<<(NN + 7) / 8, 256>>>(bg2, out);                             // 7
}

// round 9
// speedup vs baseline: 3.0915x; 1.0103x over previous
#include <cuda_runtime.h>
#include <cuda_fp16.h>
#include <cstdint>

#define NN   50000
#define EE   1600000
#define DINN 2000
#define BSCALE 4096.0f
#define BINV   (1.0f / 4096.0f)

// ---------------- device scratch (allocation-free contract) ----------------
__device__ float g_alpha1[2 * 500];
__device__ float g_bb1[2 * 500];
__device__ float g_alpha2[2 * 128];
__device__ float g_t2b[2 * 128];
__device__ float g_cmean[64];
__device__ float g_cprime[64];
__device__ float g_Wde2[2 * 128 * 64];   // 0.5 * alpha2[l] * (Wd @ Wg0)
__device__ float g_R[2 * 500 * 64];      // W2 @ Wde2
__device__ __half g_Bhi[64 * 4096];      // [e][m*2048+k] hi of 4096*M^T (pad zero)
__device__ __half g_Blo[64 * 4096];      // lo
__device__ float g_xw0[NN * 64];         // sum h@M partials (no c'; cs at gather)
__device__ float g_xw1[NN * 32];
__device__ float g_xw2[NN * 4];
__device__ float g_cs[NN];
__device__ float g_cd[NN];
__device__ int   g_degS[NN];             // zero at load; re-zeroed each call
__device__ int   g_degD[NN];
__device__ int   g_off[NN + 1];
__device__ int   g_epos[EE];
__device__ int   g_esrc[EE];
__device__ int   g_bsum[128];

// ---------------- PTX helpers ----------------
__device__ __forceinline__ uint32_t smem_u32(const void* p) {
    uint32_t a;
    asm("{ .reg .u64 t; cvta.to.shared.u64 t, %1; cvt.u32.u64 %0, t; }"
        : "=r"(a) : "l"(p));
    return a;
}

#define LDSM4(r, a) \
    asm volatile("ldmatrix.sync.aligned.m8n8.x4.shared.b16 {%0,%1,%2,%3}, [%4];" \
                 : "=r"((r)[0]), "=r"((r)[1]), "=r"((r)[2]), "=r"((r)[3]) : "r"(a))

#define MMA2(c, a, b0, b1) \
    asm volatile( \
        "mma.sync.aligned.m16n8k16.row.col.f32.f16.f16.f32 " \
        "{%0,%1,%2,%3}, {%4,%5,%6,%7}, {%8,%9}, {%0,%1,%2,%3};" \
        : "+f"((c)[0]), "+f"((c)[1]), "+f"((c)[2]), "+f"((c)[3]) \
        : "r"((a)[0]), "r"((a)[1]), "r"((a)[2]), "r"((a)[3]), \
          "r"(b0), "r"(b1))

#define CP_ASYNC16(dst, src) \
    asm volatile("cp.async.cg.shared.global [%0], [%1], 16;" \
                 :: "r"(dst), "l"(src) : "memory")
#define CP_COMMIT() asm volatile("cp.async.commit_group;" ::: "memory")
#define CP_WAIT0()  asm volatile("cp.async.wait_group 0;" ::: "memory")

// ---- L1: fold (blk 0) + degrees/epos (blk 1..3125) + zero xw0 (rest) ----------
__global__ __launch_bounds__(512) void k_fold(
    const int* __restrict__ src, const int* __restrict__ dst,
    const float* __restrict__ b1, const float* __restrict__ g1,
    const float* __restrict__ be1, const float* __restrict__ m1,
    const float* __restrict__ v1, const float* __restrict__ W2,
    const float* __restrict__ b2, const float* __restrict__ g2,
    const float* __restrict__ be2, const float* __restrict__ m2,
    const float* __restrict__ v2, const float* __restrict__ Wd,
    const float* __restrict__ bd, const float* __restrict__ Wg0) {
    int b = blockIdx.x;
    if (b >= 1 && b <= 3125) {
        int e = (b - 1) * 512 + threadIdx.x;
        if (e < EE) {
            g_epos[e] = atomicAdd(&g_degD[dst[e]], 1);
            atomicAdd(&g_degS[src[e]], 1);
        }
        return;
    }
    if (b > 3125) {
        float4 z = make_float4(0.f, 0.f, 0.f, 0.f);
        for (int i = (b - 3126) * 512 + threadIdx.x; i < NN * 16; i += 200 * 512)
            reinterpret_cast<float4*>(g_xw0)[i] = z;
        return;
    }
    __shared__ float sWg0[64 * 64];
    int t = threadIdx.x;
    for (int i = t; i < 1000; i += 512) {
        float a = g1[i] * rsqrtf(v1[i] + 1e-5f);
        g_alpha1[i] = a;
        g_bb1[i] = (b1[i] - m1[i]) * a + be1[i];
    }
    for (int i = t; i < 256; i += 512)
        g_alpha2[i] = g2[i] * rsqrtf(v2[i] + 1e-5f);
    for (int i = t; i < 4096; i += 512) sWg0[i] = Wg0[i];
    __syncthreads();
    for (int i = t; i < 256; i += 512) {
        int mm = i >> 7, l = i & 127;
        float s = 0.f;
        for (int j = 0; j < 500; j++)
            s += g_bb1[mm * 500 + j] * W2[mm * 64000 + j * 128 + l];
        g_t2b[i] = (s + b2[i] - m2[i]) * g_alpha2[i] + be2[i];
    }
    for (int idx = t; idx < 16384; idx += 512) {
        int m = idx >> 13, rem = idx & 8191, l = rem >> 6, e = rem & 63;
        float s = 0.f;
        for (int d = 0; d < 64; d++)
            s += Wd[m * 8192 + l * 64 + d] * sWg0[d * 64 + e];
        g_Wde2[idx] = 0.5f * g_alpha2[m * 128 + l] * s;
    }
    __syncthreads();
    for (int d = t; d < 64; d += 512) {
        float s = 0.f;
        for (int mm = 0; mm < 2; mm++) {
            float sm = bd[mm * 64 + d];
            for (int l = 0; l < 128; l++)
                sm += g_t2b[mm * 128 + l] * Wd[mm * 8192 + l * 64 + d];
            s += sm;
        }
        g_cmean[d] = 0.5f * s;
    }
    __syncthreads();
    for (int e = t; e < 64; e += 512) {
        float s = 0.f;
        for (int d = 0; d < 64; d++) s += g_cmean[d] * sWg0[d * 64 + e];
        g_cprime[e] = s;
    }
}

// ---- L2: R (blocks 0..125, all 512 thr) + scanA (blocks 126..223) -------------
__global__ __launch_bounds__(512) void k_Rscan(const float* __restrict__ W2) {
    int b = blockIdx.x;
    int t = threadIdx.x;
    if (b < 126) {
        int m = b / 63, j0 = (b % 63) * 8;
        int jr = t >> 6, e = t & 63;
        int j = j0 + jr;
        if (j >= 500) return;
        const float* w2row = W2 + m * 64000 + j * 128;
        const float* wde = g_Wde2 + m * 8192 + e;
        float acc = 0.f;
#pragma unroll 4
        for (int l = 0; l < 128; l++)
            acc = fmaf(__ldg(&w2row[l]), __ldg(&wde[l * 64]), acc);
        g_R[m * 32000 + j * 64 + e] = acc;
        return;
    }
    // scanA: block sums of degD (98 blocks of 512)
    __shared__ int sw[16];
    int bid = b - 126;
    int i = bid * 512 + t;
    int v = (i < NN) ? g_degD[i] : 0;
#pragma unroll
    for (int o = 16; o >= 1; o >>= 1) v += __shfl_xor_sync(0xFFFFFFFFu, v, o);
    if ((t & 31) == 0) sw[t >> 5] = v;
    __syncthreads();
    if (t < 32) {
        int x = (t < 16) ? sw[t] : 0;
#pragma unroll
        for (int o = 8; o >= 1; o >>= 1) x += __shfl_xor_sync(0xFFFFFFFFu, x, o);
        if (t == 0) g_bsum[bid] = x;
    }
}

// ---- L3: MB (blocks 0..499, all 512 thr) + scanC (blocks 500..597) ------------
__global__ __launch_bounds__(512) void k_MBscan(const float* __restrict__ W1) {
    int b = blockIdx.x;
    int t = threadIdx.x;
    if (b < 500) {
        __shared__ float sA[8][500];
        __shared__ float red[7][8][64];
        int m = b / 250, i0 = (b % 250) * 8;
        for (int idx = t; idx < 4000; idx += 512) {
            int r = idx / 500, j = idx - r * 500;
            sA[r][j] = W1[m * 1000000 + (i0 + r) * 500 + j] * g_alpha1[m * 500 + j];
        }
        __syncthreads();
        int e = t & 63, jp = t >> 6;  // 8-way K split
        float acc[8] = {0, 0, 0, 0, 0, 0, 0, 0};
        for (int j = jp; j < 500; j += 8) {
            float w = g_R[m * 32000 + j * 64 + e];
#pragma unroll
            for (int r = 0; r < 8; r++) acc[r] += sA[r][j] * w;
        }
        if (jp > 0) {
#pragma unroll
            for (int r = 0; r < 8; r++) red[jp - 1][r][e] = acc[r];
        }
        __syncthreads();
        if (jp == 0) {
#pragma unroll
            for (int r = 0; r < 8; r++) {
                float v = acc[r];
#pragma unroll
                for (int p = 0; p < 7; p++) v += red[p][r][e];
                v *= BSCALE;
                __half hi = __float2half_rn(v);
                g_Bhi[e * 4096 + m * 2048 + i0 + r] = hi;
                g_Blo[e * 4096 + m * 2048 + i0 + r] = __float2half_rn(v - __half2float(hi));
            }
        }
        return;
    }
    // scanC: CSR offsets + cs/cd
    __shared__ int sd[512];
    __shared__ int sboff;
    int bid = b - 500;
    int i = bid * 512 + t;
    int v = (i < NN) ? g_degD[i] : 0;
    sd[t] = v;
    __syncthreads();
    for (int s = 1; s < 512; s <<= 1) {
        int x = (t >= s) ? sd[t - s] : 0;
        __syncthreads();
        sd[t] += x;
        __syncthreads();
    }
    if (t == 0) {
        int run = 0;
        for (int j = 0; j < bid; j++) run += g_bsum[j];
        sboff = run;
        if (bid == 0) g_off[NN] = EE;
    }
    __syncthreads();
    if (i < NN) {
        g_off[i] = sboff + sd[t] - v;
        g_cs[i] = rsqrtf(fmaxf((float)g_degS[i], 1.0f));
        g_cd[i] = rsqrtf(fmaxf((float)v, 1.0f));
    }
}

// ---- L4: 64x64-tile HMMA GEMM (splitK=4) + CSR fill + degree rezero ------------
#define SM_A 0                       // 2 buf x 8192 (fp16 A-hi, 64 rows)
#define SM_B 16384                   // 2 buf x (8192 hi + 8192 lo)
#define SMEM_BYTES 49152
#define GEMM_BLKS 3128
#define FILL_BLKS 3125

__global__ __launch_bounds__(128, 4) void k_gemm_hmma(const float* __restrict__ h,
                                                      const int* __restrict__ src,
                                                      const int* __restrict__ dst) {
    int b = blockIdx.x;
    int tid = threadIdx.x;
    if (b >= GEMM_BLKS) {
        if (b < GEMM_BLKS + FILL_BLKS) {
            int e0 = (b - GEMM_BLKS) * 512;
#pragma unroll
            for (int it = 0; it < 4; it++) {
                int e = e0 + it * 128 + tid;
                g_esrc[g_off[dst[e]] + g_epos[e]] = src[e];
            }
        } else {
            int i0 = (b - GEMM_BLKS - FILL_BLKS) * 512;
#pragma unroll
            for (int it = 0; it < 4; it++) {
                int i = i0 + it * 128 + tid;
                if (i < NN) { g_degS[i] = 0; g_degD[i] = 0; }
            }
        }
        return;
    }

    extern __shared__ __align__(1024) char smem[];
    uint32_t sbase = smem_u32(smem);
    int lane = tid & 31, wid = tid >> 5;
    int wm = wid >> 1, wn = wid & 1;
    int bx = b % 782, by = b / 782;
    int row0 = bx * 64;
    int m = by >> 1, kh = by & 1;
    const float* hb = h + (long long)m * NN * DINN;
    const __half* bhi = g_Bhi + m * 2048 + kh * 1024;
    const __half* blo = g_Blo + m * 2048 + kh * 1024;
    int kbase = kh * 1024;

    uint32_t swz = (uint32_t)(lane & 7) << 4;
    uint32_t aoff = (uint32_t)(wm * 32 + (lane & 15)) * 128;
    uint32_t acolsel = (uint32_t)(lane >> 4) << 4;
    uint32_t boff = (uint32_t)(wn * 32 + lane) * 128;

    float c_[2][4][4];
#pragma unroll
    for (int mt = 0; mt < 2; mt++)
#pragma unroll
        for (int nt = 0; nt < 4; nt++)
#pragma unroll
            for (int q = 0; q < 4; q++) c_[mt][nt][q] = 0.f;

    float4 va[8];

    auto ldgA = [&](int c) {
        int k0 = kbase + c * 64;
        const float* base = hb + (long long)row0 * DINN + k0;
        if (row0 + 64 <= NN && k0 + 64 <= 2000) {
#pragma unroll
            for (int i = 0; i < 8; i++) {
                int idx = tid + 128 * i;
                int r = idx >> 4, cg = idx & 15;
                va[i] = *reinterpret_cast<const float4*>(base + (long long)r * DINN + cg * 4);
            }
        } else {
#pragma unroll
            for (int i = 0; i < 8; i++) {
                int idx = tid + 128 * i;
                int r = idx >> 4, cg = idx & 15;
                if (row0 + r < NN && k0 + cg * 4 + 3 < 2000)
                    va[i] = *reinterpret_cast<const float4*>(base + (long long)r * DINN + cg * 4);
                else
                    va[i] = make_float4(0.f, 0.f, 0.f, 0.f);
            }
        }
    };

    auto cpB = [&](int c, int buf) {
        int k0 = c * 64;
        uint32_t bH = sbase + SM_B + buf * 16384, bL = bH + 8192;
#pragma unroll
        for (int i = 0; i < 4; i++) {
            int idx = tid + 128 * i;
            int r = idx >> 3, cg = idx & 7;
            uint32_t off = (uint32_t)r * 128 +
                           (((uint32_t)cg * 16) ^ (((uint32_t)r & 7) << 4));
            CP_ASYNC16(bH + off, bhi + r * 4096 + k0 + cg * 8);
            CP_ASYNC16(bL + off, blo + r * 4096 + k0 + cg * 8);
        }
        CP_COMMIT();
    };

    auto stsA = [&](int buf) {
        uint32_t aH = SM_A + buf * 8192;
#pragma unroll
        for (int i = 0; i < 8; i++) {
            int idx = tid + 128 * i;
            int r = idx >> 4, cg = idx & 15;
            float4 v = va[i];
            __half2 h01 = __float22half2_rn(make_float2(v.x, v.y));
            __half2 h23 = __float22half2_rn(make_float2(v.z, v.w));
            uint32_t off = (uint32_t)r * 128 +
                           (((uint32_t)cg * 8) ^ (((uint32_t)r & 7) << 4));
            *reinterpret_cast<uint2*>(smem + aH + off) =
                make_uint2(*reinterpret_cast<uint32_t*>(&h01),
                           *reinterpret_cast<uint32_t*>(&h23));
        }
    };

    auto compute = [&](int buf) {
        uint32_t aH = sbase + SM_A + buf * 8192;
        uint32_t bH = sbase + SM_B + buf * 16384, bL = bH + 8192;
#pragma unroll
        for (int ks = 0; ks < 4; ks++) {
            uint32_t kb = (uint32_t)ks * 32;
            uint32_t aF[2][4];
            uint32_t b0h[4], b1h[4], b0l[4], b1l[4];
#pragma unroll
            for (int mt = 0; mt < 2; mt++) {
                uint32_t adr = aoff + (uint32_t)mt * 2048 + ((kb + acolsel) ^ swz);
                LDSM4(aF[mt], aH + adr);
            }
            LDSM4(b0h, bH + boff + ((kb + 0) ^ swz));
            LDSM4(b1h, bH + boff + ((kb + 16) ^ swz));
            LDSM4(b0l, bL + boff + ((kb + 0) ^ swz));
            LDSM4(b1l, bL + boff + ((kb + 16) ^ swz));
#pragma unroll
            for (int mt = 0; mt < 2; mt++)
#pragma unroll
                for (int nt = 0; nt < 4; nt++) {
                    MMA2(c_[mt][nt], aF[mt], b0h[nt], b1h[nt]);
                    MMA2(c_[mt][nt], aF[mt], b0l[nt], b1l[nt]);
                }
        }
    };

    ldgA(0);
    cpB(0, 0);
    stsA(0);
    CP_WAIT0();
    __syncthreads();

    for (int c = 0; c < 16; c++) {
        int buf = c & 1;
        bool more = (c + 1 < 16);
        if (more) {
            ldgA(c + 1);
            cpB(c + 1, buf ^ 1);
        }
        compute(buf);
        if (more) {
            stsA(buf ^ 1);
            CP_WAIT0();
            __syncthreads();
        }
    }

    int g = lane >> 2;
    int base_r = row0 + wm * 32 + g;
    int col0 = wn * 32 + (lane & 3) * 2;
#pragma unroll
    for (int mt = 0; mt < 2; mt++) {
#pragma unroll
        for (int rr = 0; rr < 2; rr++) {
            int gr = base_r + mt * 16 + rr * 8;
            if (gr < NN) {
#pragma unroll
                for (int nt = 0; nt < 4; nt++) {
                    int col = col0 + nt * 8;
                    float2 v;
                    v.x = c_[mt][nt][rr * 2 + 0] * BINV;
                    v.y = c_[mt][nt][rr * 2 + 1] * BINV;
                    atomicAdd(reinterpret_cast<float2*>(&g_xw0[gr * 64 + col]), v);
                }
            }
        }
    }
}

// ---------------- L5: gather cs*(xw0+c') + relu/bias/norm + GEMV 64->32 --------
__global__ __launch_bounds__(256) void k_g64(const float* __restrict__ bg0,
                                             const float* __restrict__ Wg1) {
    __shared__ float sW[64 * 32];
    __shared__ float sb[64];
    __shared__ float sc[64];
    int t = threadIdx.x;
    for (int i = t; i < 2048; i += 256) sW[i] = Wg1[i];
    if (t < 64) { sb[t] = bg0[t]; sc[t] = g_cprime[t]; }
    __syncthreads();
    int wid = t >> 5, lane = t & 31;
    int n = blockIdx.x * 8 + wid;
    if (n >= NN) return;
    int beg = g_off[n], end = g_off[n + 1];
    int half = lane >> 4, l16 = lane & 15;
    float4 acc = make_float4(0.f, 0.f, 0.f, 0.f);
    float scs = 0.f;
    int i = beg + half;
    // 8 rows in flight per half-warp
    while (i + 14 < end) {
        int s[8];
        float cs[8];
#pragma unroll
        for (int u = 0; u < 8; u++) s[u] = __ldg(&g_esrc[i + 2 * u]);
#pragma unroll
        for (int u = 0; u < 8; u++) cs[u] = __ldg(&g_cs[s[u]]);
#pragma unroll
        for (int u = 0; u < 8; u++) {
            float4 v = __ldg(reinterpret_cast<const float4*>(&g_xw0[s[u] * 64 + l16 * 4]));
            acc.x += v.x * cs[u];
            acc.y += v.y * cs[u];
            acc.z += v.z * cs[u];
            acc.w += v.w * cs[u];
            scs += cs[u];
        }
        i += 16;
    }
    while (i < end) {
        int s = __ldg(&g_esrc[i]);
        float cs0 = __ldg(&g_cs[s]);
        float4 v = __ldg(reinterpret_cast<const float4*>(&g_xw0[s * 64 + l16 * 4]));
        acc.x += v.x * cs0; acc.y += v.y * cs0; acc.z += v.z * cs0; acc.w += v.w * cs0;
        scs += cs0;
        i += 2;
    }
    acc.x += __shfl_xor_sync(0xFFFFFFFFu, acc.x, 16);
    acc.y += __shfl_xor_sync(0xFFFFFFFFu, acc.y, 16);
    acc.z += __shfl_xor_sync(0xFFFFFFFFu, acc.z, 16);
    acc.w += __shfl_xor_sync(0xFFFFFFFFu, acc.w, 16);
    scs   += __shfl_xor_sync(0xFFFFFFFFu, scs, 16);
    float cdv = g_cd[n], csv = g_cs[n];
    float val[4];
    val[0] = fmaxf(fmaf(fmaf(sc[l16 * 4 + 0], scs, acc.x), cdv, sb[l16 * 4 + 0]), 0.f) * csv;
    val[1] = fmaxf(fmaf(fmaf(sc[l16 * 4 + 1], scs, acc.y), cdv, sb[l16 * 4 + 1]), 0.f) * csv;
    val[2] = fmaxf(fmaf(fmaf(sc[l16 * 4 + 2], scs, acc.z), cdv, sb[l16 * 4 + 2]), 0.f) * csv;
    val[3] = fmaxf(fmaf(fmaf(sc[l16 * 4 + 3], scs, acc.w), cdv, sb[l16 * 4 + 3]), 0.f) * csv;
    float o = 0.f;
#pragma unroll
    for (int d = 0; d < 64; d++) {
        float v = __shfl_sync(0xFFFFFFFFu, val[d & 3], d >> 2);
        o = fmaf(v, sW[d * 32 + lane], o);
    }
    g_xw1[n * 32 + lane] = o;
}

// ---------------- L6: gather xw1 + relu/bias/norm + GEMV 32->4 -> xw2 ----------
__global__ __launch_bounds__(256) void k_g32(const float* __restrict__ bg1,
                                             const float* __restrict__ Wg2) {
    __shared__ float sW[32 * 4];
    __shared__ float sb[32];
    int t = threadIdx.x;
    if (t < 128) sW[t] = Wg2[t];
    if (t < 32) sb[t] = bg1[t];
    __syncthreads();
    int wid = t >> 5, lane = t & 31;
    int n = blockIdx.x * 8 + wid;
    if (n >= NN) return;
    int beg = g_off[n], end = g_off[n + 1];
    int q = lane >> 3, l8 = lane & 7;
    float4 acc = make_float4(0.f, 0.f, 0.f, 0.f);
    int i = beg + q;
    // 8 rows in flight per quarter-warp
    while (i + 28 < end) {
        int s[8];
#pragma unroll
        for (int u = 0; u < 8; u++) s[u] = __ldg(&g_esrc[i + 4 * u]);
#pragma unroll
        for (int u = 0; u < 8; u++) {
            float4 v = __ldg(reinterpret_cast<const float4*>(&g_xw1[s[u] * 32 + l8 * 4]));
            acc.x += v.x; acc.y += v.y; acc.z += v.z; acc.w += v.w;
        }
        i += 32;
    }
    while (i < end) {
        int s = __ldg(&g_esrc[i]);
        float4 v = __ldg(reinterpret_cast<const float4*>(&g_xw1[s * 32 + l8 * 4]));
        acc.x += v.x; acc.y += v.y; acc.z += v.z; acc.w += v.w;
        i += 4;
    }
    acc.x += __shfl_xor_sync(0xFFFFFFFFu, acc.x, 8);
    acc.y += __shfl_xor_sync(0xFFFFFFFFu, acc.y, 8);
    acc.z += __shfl_xor_sync(0xFFFFFFFFu, acc.z, 8);
    acc.w += __shfl_xor_sync(0xFFFFFFFFu, acc.w, 8);
    acc.x += __shfl_xor_sync(0xFFFFFFFFu, acc.x, 16);
    acc.y += __shfl_xor_sync(0xFFFFFFFFu, acc.y, 16);
    acc.z += __shfl_xor_sync(0xFFFFFFFFu, acc.z, 16);
    acc.w += __shfl_xor_sync(0xFFFFFFFFu, acc.w, 16);
    float cdv = g_cd[n], csv = g_cs[n];
    float val[4];
    val[0] = fmaxf(fmaf(acc.x, cdv, sb[l8 * 4 + 0]), 0.f) * csv;
    val[1] = fmaxf(fmaf(acc.y, cdv, sb[l8 * 4 + 1]), 0.f) * csv;
    val[2] = fmaxf(fmaf(acc.z, cdv, sb[l8 * 4 + 2]), 0.f) * csv;
    val[3] = fmaxf(fmaf(acc.w, cdv, sb[l8 * 4 + 3]), 0.f) * csv;
    float o = 0.f;
#pragma unroll
    for (int d = 0; d < 32; d++) {
        float v = __shfl_sync(0xFFFFFFFFu, val[d & 3], d >> 2);
        o = fmaf(v, sW[d * 4 + (lane & 3)], o);
    }
    if (lane < 4) g_xw2[n * 4 + lane] = o;
}

// ---------------- L7: gather xw2 + bias -> out ----------------
__global__ __launch_bounds__(256) void k_g4(const float* __restrict__ bg2,
                                            float* __restrict__ out) {
    int t = threadIdx.x;
    int wid = t >> 5, lane = t & 31;
    int n = blockIdx.x * 8 + wid;
    if (n >= NN) return;
    int beg = g_off[n], end = g_off[n + 1];
    float4 acc = make_float4(0.f, 0.f, 0.f, 0.f);
    for (int i = beg + lane; i < end; i += 32) {
        int s = __ldg(&g_esrc[i]);
        float4 v = __ldg(reinterpret_cast<const float4*>(&g_xw2[s * 4]));
        acc.x += v.x; acc.y += v.y; acc.z += v.z; acc.w += v.w;
    }
#pragma unroll
    for (int off = 16; off >= 1; off >>= 1) {
        acc.x += __shfl_xor_sync(0xFFFFFFFFu, acc.x, off);
        acc.y += __shfl_xor_sync(0xFFFFFFFFu, acc.y, off);
        acc.z += __shfl_xor_sync(0xFFFFFFFFu, acc.z, off);
        acc.w += __shfl_xor_sync(0xFFFFFFFFu, acc.w, off);
    }
    if (lane == 0) {
        float cdv = g_cd[n];
        float4 o;
        o.x = fmaf(acc.x, cdv, bg2[0]);
        o.y = fmaf(acc.y, cdv, bg2[1]);
        o.z = fmaf(acc.z, cdv, bg2[2]);
        o.w = fmaf(acc.w, cdv, bg2[3]);
        *reinterpret_cast<float4*>(&out[n * 4]) = o;
    }
}

// ---------------- launch ----------------
extern "C" void kernel_launch(void* const* d_in, const int* in_sizes, int n_in,
                              void* d_out, int out_size) {
    const float* h   = (const float*)d_in[0];
    const int*   src = (const int*)d_in[1];
    const int*   dst = (const int*)d_in[2];
    const float* W1  = (const float*)d_in[3];
    const float* b1  = (const float*)d_in[4];
    const float* g1  = (const float*)d_in[5];
    const float* be1 = (const float*)d_in[6];
    const float* m1  = (const float*)d_in[7];
    const float* v1  = (const float*)d_in[8];
    const float* W2  = (const float*)d_in[9];
    const float* b2  = (const float*)d_in[10];
    const float* g2  = (const float*)d_in[11];
    const float* be2 = (const float*)d_in[12];
    const float* m2  = (const float*)d_in[13];
    const float* v2  = (const float*)d_in[14];
    const float* Wd  = (const float*)d_in[15];
    const float* bd  = (const float*)d_in[16];
    const float* Wg0 = (const float*)d_in[17];
    const float* bg0 = (const float*)d_in[18];
    const float* Wg1 = (const float*)d_in[19];
    const float* bg1 = (const float*)d_in[20];
    const float* Wg2 = (const float*)d_in[21];
    const float* bg2 = (const float*)d_in[22];
    float* out = (float*)d_out;

    cudaFuncSetAttribute(k_gemm_hmma, cudaFuncAttributeMaxDynamicSharedMemorySize,
                         SMEM_BYTES);

    k_fold<<<3326, 512>>>(src, dst, b1, g1, be1, m1, v1, W2, b2, g2,   // 1
                          be2, m2, v2, Wd, bd, Wg0);
    k_Rscan<<<224, 512>>>(W2);                                         // 2
    k_MBscan<<<598, 512>>>(W1);                                        // 3
    k_gemm_hmma<<<6351, 128, SMEM_BYTES>>>(h, src, dst);               // 4 <- ncu
    k_g64<<<(NN + 7) / 8, 256>>>(bg0, Wg1);                            // 5
    k_g32<<<(NN + 7) / 8, 256>>>(bg1, Wg2);                            // 6
    k_g4<<<(NN + 7) / 8, 256>>>(bg2, out);                             // 7
}

// round 10
// speedup vs baseline: 3.0974x; 1.0019x over previous
#include <cuda_runtime.h>
#include <cuda_fp16.h>
#include <cstdint>

#define NN   50000
#define EE   1600000
#define DINN 2000
#define BSCALE 4096.0f
#define BINV   (1.0f / 4096.0f)

// ---------------- device scratch (allocation-free contract) ----------------
__device__ float g_alpha1[2 * 500];
__device__ float g_bb1[2 * 500];
__device__ float g_alpha2[2 * 128];
__device__ float g_t2b[2 * 128];
__device__ float g_cmean[64];
__device__ float g_cprime[64];
__device__ float g_Wde2[2 * 128 * 64];   // 0.5 * alpha2[l] * (Wd @ Wg0)
__device__ float g_R[2 * 500 * 64];      // W2 @ Wde2
__device__ __half g_Bhi[64 * 4096];      // [e][m*2048+k] hi of 4096*M^T (pad zero)
__device__ __half g_Blo[64 * 4096];      // lo
__device__ float g_xw0[NN * 64];         // fp32 splitK accumulation target
__device__ __half g_xh0[NN * 64];        // fp16 mirror for gather
__device__ __half g_xh1[NN * 32];        // layer-1 output (fp16)
__device__ float g_xw2[NN * 4];
__device__ float g_cs[NN];
__device__ float g_cd[NN];
__device__ int   g_degS[NN];             // zero at load; re-zeroed each call
__device__ int   g_degD[NN];
__device__ int   g_off[NN + 1];
__device__ int   g_epos[EE];
__device__ int   g_esrc[EE];
__device__ int   g_bsum[128];

// ---------------- PTX helpers ----------------
__device__ __forceinline__ uint32_t smem_u32(const void* p) {
    uint32_t a;
    asm("{ .reg .u64 t; cvta.to.shared.u64 t, %1; cvt.u32.u64 %0, t; }"
        : "=r"(a) : "l"(p));
    return a;
}

#define LDSM4(r, a) \
    asm volatile("ldmatrix.sync.aligned.m8n8.x4.shared.b16 {%0,%1,%2,%3}, [%4];" \
                 : "=r"((r)[0]), "=r"((r)[1]), "=r"((r)[2]), "=r"((r)[3]) : "r"(a))

#define MMA2(c, a, b0, b1) \
    asm volatile( \
        "mma.sync.aligned.m16n8k16.row.col.f32.f16.f16.f32 " \
        "{%0,%1,%2,%3}, {%4,%5,%6,%7}, {%8,%9}, {%0,%1,%2,%3};" \
        : "+f"((c)[0]), "+f"((c)[1]), "+f"((c)[2]), "+f"((c)[3]) \
        : "r"((a)[0]), "r"((a)[1]), "r"((a)[2]), "r"((a)[3]), \
          "r"(b0), "r"(b1))

#define CP_ASYNC16(dst, src) \
    asm volatile("cp.async.cg.shared.global [%0], [%1], 16;" \
                 :: "r"(dst), "l"(src) : "memory")
#define CP_COMMIT() asm volatile("cp.async.commit_group;" ::: "memory")
#define CP_WAIT0()  asm volatile("cp.async.wait_group 0;" ::: "memory")

// ---- L1: fold (blk 0) + degrees/epos (blk 1..3125) + zero xw0 (rest) ----------
__global__ __launch_bounds__(512) void k_fold(
    const int* __restrict__ src, const int* __restrict__ dst,
    const float* __restrict__ b1, const float* __restrict__ g1,
    const float* __restrict__ be1, const float* __restrict__ m1,
    const float* __restrict__ v1, const float* __restrict__ W2,
    const float* __restrict__ b2, const float* __restrict__ g2,
    const float* __restrict__ be2, const float* __restrict__ m2,
    const float* __restrict__ v2, const float* __restrict__ Wd,
    const float* __restrict__ bd, const float* __restrict__ Wg0) {
    int b = blockIdx.x;
    if (b >= 1 && b <= 3125) {
        int e = (b - 1) * 512 + threadIdx.x;
        if (e < EE) {
            g_epos[e] = atomicAdd(&g_degD[dst[e]], 1);
            atomicAdd(&g_degS[src[e]], 1);
        }
        return;
    }
    if (b > 3125) {
        float4 z = make_float4(0.f, 0.f, 0.f, 0.f);
        for (int i = (b - 3126) * 512 + threadIdx.x; i < NN * 16; i += 200 * 512)
            reinterpret_cast<float4*>(g_xw0)[i] = z;
        return;
    }
    __shared__ float sWg0[64 * 64];
    int t = threadIdx.x;
    for (int i = t; i < 1000; i += 512) {
        float a = g1[i] * rsqrtf(v1[i] + 1e-5f);
        g_alpha1[i] = a;
        g_bb1[i] = (b1[i] - m1[i]) * a + be1[i];
    }
    for (int i = t; i < 256; i += 512)
        g_alpha2[i] = g2[i] * rsqrtf(v2[i] + 1e-5f);
    for (int i = t; i < 4096; i += 512) sWg0[i] = Wg0[i];
    __syncthreads();
    for (int i = t; i < 256; i += 512) {
        int mm = i >> 7, l = i & 127;
        float s = 0.f;
        for (int j = 0; j < 500; j++)
            s += g_bb1[mm * 500 + j] * W2[mm * 64000 + j * 128 + l];
        g_t2b[i] = (s + b2[i] - m2[i]) * g_alpha2[i] + be2[i];
    }
    for (int idx = t; idx < 16384; idx += 512) {
        int m = idx >> 13, rem = idx & 8191, l = rem >> 6, e = rem & 63;
        float s = 0.f;
        for (int d = 0; d < 64; d++)
            s += Wd[m * 8192 + l * 64 + d] * sWg0[d * 64 + e];
        g_Wde2[idx] = 0.5f * g_alpha2[m * 128 + l] * s;
    }
    __syncthreads();
    for (int d = t; d < 64; d += 512) {
        float s = 0.f;
        for (int mm = 0; mm < 2; mm++) {
            float sm = bd[mm * 64 + d];
            for (int l = 0; l < 128; l++)
                sm += g_t2b[mm * 128 + l] * Wd[mm * 8192 + l * 64 + d];
            s += sm;
        }
        g_cmean[d] = 0.5f * s;
    }
    __syncthreads();
    for (int e = t; e < 64; e += 512) {
        float s = 0.f;
        for (int d = 0; d < 64; d++) s += g_cmean[d] * sWg0[d * 64 + e];
        g_cprime[e] = s;
    }
}

// ---- L2: R (blocks 0..125, all 512 thr) + scanA (blocks 126..223) -------------
__global__ __launch_bounds__(512) void k_Rscan(const float* __restrict__ W2) {
    int b = blockIdx.x;
    int t = threadIdx.x;
    if (b < 126) {
        int m = b / 63, j0 = (b % 63) * 8;
        int jr = t >> 6, e = t & 63;
        int j = j0 + jr;
        if (j >= 500) return;
        const float* w2row = W2 + m * 64000 + j * 128;
        const float* wde = g_Wde2 + m * 8192 + e;
        float acc = 0.f;
#pragma unroll 4
        for (int l = 0; l < 128; l++)
            acc = fmaf(__ldg(&w2row[l]), __ldg(&wde[l * 64]), acc);
        g_R[m * 32000 + j * 64 + e] = acc;
        return;
    }
    __shared__ int sw[16];
    int bid = b - 126;
    int i = bid * 512 + t;
    int v = (i < NN) ? g_degD[i] : 0;
#pragma unroll
    for (int o = 16; o >= 1; o >>= 1) v += __shfl_xor_sync(0xFFFFFFFFu, v, o);
    if ((t & 31) == 0) sw[t >> 5] = v;
    __syncthreads();
    if (t < 32) {
        int x = (t < 16) ? sw[t] : 0;
#pragma unroll
        for (int o = 8; o >= 1; o >>= 1) x += __shfl_xor_sync(0xFFFFFFFFu, x, o);
        if (t == 0) g_bsum[bid] = x;
    }
}

// ---- L3: MB (blocks 0..499, all 512 thr) + scanC (blocks 500..597) ------------
__global__ __launch_bounds__(512) void k_MBscan(const float* __restrict__ W1) {
    int b = blockIdx.x;
    int t = threadIdx.x;
    if (b < 500) {
        __shared__ float sA[8][500];
        __shared__ float red[7][8][64];
        int m = b / 250, i0 = (b % 250) * 8;
        for (int idx = t; idx < 4000; idx += 512) {
            int r = idx / 500, j = idx - r * 500;
            sA[r][j] = W1[m * 1000000 + (i0 + r) * 500 + j] * g_alpha1[m * 500 + j];
        }
        __syncthreads();
        int e = t & 63, jp = t >> 6;
        float acc[8] = {0, 0, 0, 0, 0, 0, 0, 0};
        for (int j = jp; j < 500; j += 8) {
            float w = g_R[m * 32000 + j * 64 + e];
#pragma unroll
            for (int r = 0; r < 8; r++) acc[r] += sA[r][j] * w;
        }
        if (jp > 0) {
#pragma unroll
            for (int r = 0; r < 8; r++) red[jp - 1][r][e] = acc[r];
        }
        __syncthreads();
        if (jp == 0) {
#pragma unroll
            for (int r = 0; r < 8; r++) {
                float v = acc[r];
#pragma unroll
                for (int p = 0; p < 7; p++) v += red[p][r][e];
                v *= BSCALE;
                __half hi = __float2half_rn(v);
                g_Bhi[e * 4096 + m * 2048 + i0 + r] = hi;
                g_Blo[e * 4096 + m * 2048 + i0 + r] = __float2half_rn(v - __half2float(hi));
            }
        }
        return;
    }
    __shared__ int sd[512];
    __shared__ int sboff;
    int bid = b - 500;
    int i = bid * 512 + t;
    int v = (i < NN) ? g_degD[i] : 0;
    sd[t] = v;
    __syncthreads();
    for (int s = 1; s < 512; s <<= 1) {
        int x = (t >= s) ? sd[t - s] : 0;
        __syncthreads();
        sd[t] += x;
        __syncthreads();
    }
    if (t == 0) {
        int run = 0;
        for (int j = 0; j < bid; j++) run += g_bsum[j];
        sboff = run;
        if (bid == 0) g_off[NN] = EE;
    }
    __syncthreads();
    if (i < NN) {
        g_off[i] = sboff + sd[t] - v;
        g_cs[i] = rsqrtf(fmaxf((float)g_degS[i], 1.0f));
        g_cd[i] = rsqrtf(fmaxf((float)v, 1.0f));
    }
}

// ---- L4: 64x64-tile HMMA GEMM (splitK=4) + CSR fill ---------------------------
#define SM_A 0                       // 2 buf x 8192 (fp16 A-hi, 64 rows)
#define SM_B 16384                   // 2 buf x (8192 hi + 8192 lo)
#define SMEM_BYTES 49152
#define GEMM_BLKS 3128
#define FILL_BLKS 3125

__global__ __launch_bounds__(128, 4) void k_gemm_hmma(const float* __restrict__ h,
                                                      const int* __restrict__ src,
                                                      const int* __restrict__ dst) {
    int b = blockIdx.x;
    int tid = threadIdx.x;
    if (b >= GEMM_BLKS) {
        int e0 = (b - GEMM_BLKS) * 512;
#pragma unroll
        for (int it = 0; it < 4; it++) {
            int e = e0 + it * 128 + tid;
            g_esrc[g_off[dst[e]] + g_epos[e]] = src[e];
        }
        return;
    }

    extern __shared__ __align__(1024) char smem[];
    uint32_t sbase = smem_u32(smem);
    int lane = tid & 31, wid = tid >> 5;
    int wm = wid >> 1, wn = wid & 1;
    int bx = b % 782, by = b / 782;
    int row0 = bx * 64;
    int m = by >> 1, kh = by & 1;
    const float* hb = h + (long long)m * NN * DINN;
    const __half* bhi = g_Bhi + m * 2048 + kh * 1024;
    const __half* blo = g_Blo + m * 2048 + kh * 1024;
    int kbase = kh * 1024;

    uint32_t swz = (uint32_t)(lane & 7) << 4;
    uint32_t aoff = (uint32_t)(wm * 32 + (lane & 15)) * 128;
    uint32_t acolsel = (uint32_t)(lane >> 4) << 4;
    uint32_t boff = (uint32_t)(wn * 32 + lane) * 128;

    float c_[2][4][4];
#pragma unroll
    for (int mt = 0; mt < 2; mt++)
#pragma unroll
        for (int nt = 0; nt < 4; nt++)
#pragma unroll
            for (int q = 0; q < 4; q++) c_[mt][nt][q] = 0.f;

    float4 va[8];

    auto ldgA = [&](int c) {
        int k0 = kbase + c * 64;
        const float* base = hb + (long long)row0 * DINN + k0;
        if (row0 + 64 <= NN && k0 + 64 <= 2000) {
#pragma unroll
            for (int i = 0; i < 8; i++) {
                int idx = tid + 128 * i;
                int r = idx >> 4, cg = idx & 15;
                va[i] = *reinterpret_cast<const float4*>(base + (long long)r * DINN + cg * 4);
            }
        } else {
#pragma unroll
            for (int i = 0; i < 8; i++) {
                int idx = tid + 128 * i;
                int r = idx >> 4, cg = idx & 15;
                if (row0 + r < NN && k0 + cg * 4 + 3 < 2000)
                    va[i] = *reinterpret_cast<const float4*>(base + (long long)r * DINN + cg * 4);
                else
                    va[i] = make_float4(0.f, 0.f, 0.f, 0.f);
            }
        }
    };

    auto cpB = [&](int c, int buf) {
        int k0 = c * 64;
        uint32_t bH = sbase + SM_B + buf * 16384, bL = bH + 8192;
#pragma unroll
        for (int i = 0; i < 4; i++) {
            int idx = tid + 128 * i;
            int r = idx >> 3, cg = idx & 7;
            uint32_t off = (uint32_t)r * 128 +
                           (((uint32_t)cg * 16) ^ (((uint32_t)r & 7) << 4));
            CP_ASYNC16(bH + off, bhi + r * 4096 + k0 + cg * 8);
            CP_ASYNC16(bL + off, blo + r * 4096 + k0 + cg * 8);
        }
        CP_COMMIT();
    };

    auto stsA = [&](int buf) {
        uint32_t aH = SM_A + buf * 8192;
#pragma unroll
        for (int i = 0; i < 8; i++) {
            int idx = tid + 128 * i;
            int r = idx >> 4, cg = idx & 15;
            float4 v = va[i];
            __half2 h01 = __float22half2_rn(make_float2(v.x, v.y));
            __half2 h23 = __float22half2_rn(make_float2(v.z, v.w));
            uint32_t off = (uint32_t)r * 128 +
                           (((uint32_t)cg * 8) ^ (((uint32_t)r & 7) << 4));
            *reinterpret_cast<uint2*>(smem + aH + off) =
                make_uint2(*reinterpret_cast<uint32_t*>(&h01),
                           *reinterpret_cast<uint32_t*>(&h23));
        }
    };

    auto compute = [&](int buf) {
        uint32_t aH = sbase + SM_A + buf * 8192;
        uint32_t bH = sbase + SM_B + buf * 16384, bL = bH + 8192;
#pragma unroll
        for (int ks = 0; ks < 4; ks++) {
            uint32_t kb = (uint32_t)ks * 32;
            uint32_t aF[2][4];
            uint32_t b0h[4], b1h[4], b0l[4], b1l[4];
#pragma unroll
            for (int mt = 0; mt < 2; mt++) {
                uint32_t adr = aoff + (uint32_t)mt * 2048 + ((kb + acolsel) ^ swz);
                LDSM4(aF[mt], aH + adr);
            }
            LDSM4(b0h, bH + boff + ((kb + 0) ^ swz));
            LDSM4(b1h, bH + boff + ((kb + 16) ^ swz));
            LDSM4(b0l, bL + boff + ((kb + 0) ^ swz));
            LDSM4(b1l, bL + boff + ((kb + 16) ^ swz));
#pragma unroll
            for (int mt = 0; mt < 2; mt++)
#pragma unroll
                for (int nt = 0; nt < 4; nt++) {
                    MMA2(c_[mt][nt], aF[mt], b0h[nt], b1h[nt]);
                    MMA2(c_[mt][nt], aF[mt], b0l[nt], b1l[nt]);
                }
        }
    };

    ldgA(0);
    cpB(0, 0);
    stsA(0);
    CP_WAIT0();
    __syncthreads();

    for (int c = 0; c < 16; c++) {
        int buf = c & 1;
        bool more = (c + 1 < 16);
        if (more) {
            ldgA(c + 1);
            cpB(c + 1, buf ^ 1);
        }
        compute(buf);
        if (more) {
            stsA(buf ^ 1);
            CP_WAIT0();
            __syncthreads();
        }
    }

    int g = lane >> 2;
    int base_r = row0 + wm * 32 + g;
    int col0 = wn * 32 + (lane & 3) * 2;
#pragma unroll
    for (int mt = 0; mt < 2; mt++) {
#pragma unroll
        for (int rr = 0; rr < 2; rr++) {
            int gr = base_r + mt * 16 + rr * 8;
            if (gr < NN) {
#pragma unroll
                for (int nt = 0; nt < 4; nt++) {
                    int col = col0 + nt * 8;
                    float2 v;
                    v.x = c_[mt][nt][rr * 2 + 0] * BINV;
                    v.y = c_[mt][nt][rr * 2 + 1] * BINV;
                    atomicAdd(reinterpret_cast<float2*>(&g_xw0[gr * 64 + col]), v);
                }
            }
        }
    }
}

// ---- L5: xw0 -> fp16 mirror + degree rezero -----------------------------------
__global__ __launch_bounds__(512) void k_cvt() {
    int b = blockIdx.x;
    if (b < 782) {
        int t = b * 512 + threadIdx.x;  // one thread = 8 floats
        if (t < 400000) {
            const float4* src = reinterpret_cast<const float4*>(g_xw0) + t * 2;
            float4 v0 = src[0], v1 = src[1];
            uint4 o;
            __half2 p;
            p = __float22half2_rn(make_float2(v0.x, v0.y)); o.x = *reinterpret_cast<uint32_t*>(&p);
            p = __float22half2_rn(make_float2(v0.z, v0.w)); o.y = *reinterpret_cast<uint32_t*>(&p);
            p = __float22half2_rn(make_float2(v1.x, v1.y)); o.z = *reinterpret_cast<uint32_t*>(&p);
            p = __float22half2_rn(make_float2(v1.z, v1.w)); o.w = *reinterpret_cast<uint32_t*>(&p);
            reinterpret_cast<uint4*>(g_xh0)[t] = o;
        }
        return;
    }
    int i = (b - 782) * 512 + threadIdx.x;
    if (i < NN) { g_degS[i] = 0; g_degD[i] = 0; }
}

// ---- L6: gather cs*(xh0+c') + relu/bias/norm + GEMV 64->32 -> xh1 (fp16) ------
__global__ __launch_bounds__(256) void k_g64(const float* __restrict__ bg0,
                                             const float* __restrict__ Wg1) {
    __shared__ float sW[64 * 32];
    __shared__ float sb[64];
    __shared__ float sc[64];
    int t = threadIdx.x;
    for (int i = t; i < 2048; i += 256) sW[i] = Wg1[i];
    if (t < 64) { sb[t] = bg0[t]; sc[t] = g_cprime[t]; }
    __syncthreads();
    int wid = t >> 5, lane = t & 31;
    int n = blockIdx.x * 8 + wid;
    if (n >= NN) return;
    int beg = g_off[n], end = g_off[n + 1];
    int half = lane >> 4, l16 = lane & 15;
    float4 acc = make_float4(0.f, 0.f, 0.f, 0.f);
    float scs = 0.f;
    int i = beg + half;
    while (i + 14 < end) {
        int s[8];
        float cs[8];
#pragma unroll
        for (int u = 0; u < 8; u++) s[u] = __ldg(&g_esrc[i + 2 * u]);
#pragma unroll
        for (int u = 0; u < 8; u++) cs[u] = __ldg(&g_cs[s[u]]);
#pragma unroll
        for (int u = 0; u < 8; u++) {
            uint2 p = __ldg(reinterpret_cast<const uint2*>(&g_xh0[s[u] * 64 + l16 * 4]));
            float2 f0 = __half22float2(*reinterpret_cast<__half2*>(&p.x));
            float2 f1 = __half22float2(*reinterpret_cast<__half2*>(&p.y));
            acc.x += f0.x * cs[u];
            acc.y += f0.y * cs[u];
            acc.z += f1.x * cs[u];
            acc.w += f1.y * cs[u];
            scs += cs[u];
        }
        i += 16;
    }
    while (i < end) {
        int s = __ldg(&g_esrc[i]);
        float cs0 = __ldg(&g_cs[s]);
        uint2 p = __ldg(reinterpret_cast<const uint2*>(&g_xh0[s * 64 + l16 * 4]));
        float2 f0 = __half22float2(*reinterpret_cast<__half2*>(&p.x));
        float2 f1 = __half22float2(*reinterpret_cast<__half2*>(&p.y));
        acc.x += f0.x * cs0; acc.y += f0.y * cs0;
        acc.z += f1.x * cs0; acc.w += f1.y * cs0;
        scs += cs0;
        i += 2;
    }
    acc.x += __shfl_xor_sync(0xFFFFFFFFu, acc.x, 16);
    acc.y += __shfl_xor_sync(0xFFFFFFFFu, acc.y, 16);
    acc.z += __shfl_xor_sync(0xFFFFFFFFu, acc.z, 16);
    acc.w += __shfl_xor_sync(0xFFFFFFFFu, acc.w, 16);
    scs   += __shfl_xor_sync(0xFFFFFFFFu, scs, 16);
    float cdv = g_cd[n], csv = g_cs[n];
    float val[4];
    val[0] = fmaxf(fmaf(fmaf(sc[l16 * 4 + 0], scs, acc.x), cdv, sb[l16 * 4 + 0]), 0.f) * csv;
    val[1] = fmaxf(fmaf(fmaf(sc[l16 * 4 + 1], scs, acc.y), cdv, sb[l16 * 4 + 1]), 0.f) * csv;
    val[2] = fmaxf(fmaf(fmaf(sc[l16 * 4 + 2], scs, acc.z), cdv, sb[l16 * 4 + 2]), 0.f) * csv;
    val[3] = fmaxf(fmaf(fmaf(sc[l16 * 4 + 3], scs, acc.w), cdv, sb[l16 * 4 + 3]), 0.f) * csv;
    float o = 0.f;
#pragma unroll
    for (int d = 0; d < 64; d++) {
        float v = __shfl_sync(0xFFFFFFFFu, val[d & 3], d >> 2);
        o = fmaf(v, sW[d * 32 + lane], o);
    }
    g_xh1[n * 32 + lane] = __float2half_rn(o);
}

// ---- L7: gather xh1 + relu/bias/norm + GEMV 32->4 -> xw2 ----------------------
__global__ __launch_bounds__(256) void k_g32(const float* __restrict__ bg1,
                                             const float* __restrict__ Wg2) {
    __shared__ float sW[32 * 4];
    __shared__ float sb[32];
    int t = threadIdx.x;
    if (t < 128) sW[t] = Wg2[t];
    if (t < 32) sb[t] = bg1[t];
    __syncthreads();
    int wid = t >> 5, lane = t & 31;
    int n = blockIdx.x * 8 + wid;
    if (n >= NN) return;
    int beg = g_off[n], end = g_off[n + 1];
    int q = lane >> 3, l8 = lane & 7;
    float4 acc = make_float4(0.f, 0.f, 0.f, 0.f);
    int i = beg + q;
    while (i + 28 < end) {
        int s[8];
#pragma unroll
        for (int u = 0; u < 8; u++) s[u] = __ldg(&g_esrc[i + 4 * u]);
#pragma unroll
        for (int u = 0; u < 8; u++) {
            uint2 p = __ldg(reinterpret_cast<const uint2*>(&g_xh1[s[u] * 32 + l8 * 4]));
            float2 f0 = __half22float2(*reinterpret_cast<__half2*>(&p.x));
            float2 f1 = __half22float2(*reinterpret_cast<__half2*>(&p.y));
            acc.x += f0.x; acc.y += f0.y; acc.z += f1.x; acc.w += f1.y;
        }
        i += 32;
    }
    while (i < end) {
        int s = __ldg(&g_esrc[i]);
        uint2 p = __ldg(reinterpret_cast<const uint2*>(&g_xh1[s * 32 + l8 * 4]));
        float2 f0 = __half22float2(*reinterpret_cast<__half2*>(&p.x));
        float2 f1 = __half22float2(*reinterpret_cast<__half2*>(&p.y));
        acc.x += f0.x; acc.y += f0.y; acc.z += f1.x; acc.w += f1.y;
        i += 4;
    }
    acc.x += __shfl_xor_sync(0xFFFFFFFFu, acc.x, 8);
    acc.y += __shfl_xor_sync(0xFFFFFFFFu, acc.y, 8);
    acc.z += __shfl_xor_sync(0xFFFFFFFFu, acc.z, 8);
    acc.w += __shfl_xor_sync(0xFFFFFFFFu, acc.w, 8);
    acc.x += __shfl_xor_sync(0xFFFFFFFFu, acc.x, 16);
    acc.y += __shfl_xor_sync(0xFFFFFFFFu, acc.y, 16);
    acc.z += __shfl_xor_sync(0xFFFFFFFFu, acc.z, 16);
    acc.w += __shfl_xor_sync(0xFFFFFFFFu, acc.w, 16);
    float cdv = g_cd[n], csv = g_cs[n];
    float val[4];
    val[0] = fmaxf(fmaf(acc.x, cdv, sb[l8 * 4 + 0]), 0.f) * csv;
    val[1] = fmaxf(fmaf(acc.y, cdv, sb[l8 * 4 + 1]), 0.f) * csv;
    val[2] = fmaxf(fmaf(acc.z, cdv, sb[l8 * 4 + 2]), 0.f) * csv;
    val[3] = fmaxf(fmaf(acc.w, cdv, sb[l8 * 4 + 3]), 0.f) * csv;
    float o = 0.f;
#pragma unroll
    for (int d = 0; d < 32; d++) {
        float v = __shfl_sync(0xFFFFFFFFu, val[d & 3], d >> 2);
        o = fmaf(v, sW[d * 4 + (lane & 3)], o);
    }
    if (lane < 4) g_xw2[n * 4 + lane] = o;
}

// ---- L8: gather xw2 + bias -> out ---------------------------------------------
__global__ __launch_bounds__(256) void k_g4(const float* __restrict__ bg2,
                                            float* __restrict__ out) {
    int t = threadIdx.x;
    int wid = t >> 5, lane = t & 31;
    int n = blockIdx.x * 8 + wid;
    if (n >= NN) return;
    int beg = g_off[n], end = g_off[n + 1];
    float4 acc = make_float4(0.f, 0.f, 0.f, 0.f);
    for (int i = beg + lane; i < end; i += 32) {
        int s = __ldg(&g_esrc[i]);
        float4 v = __ldg(reinterpret_cast<const float4*>(&g_xw2[s * 4]));
        acc.x += v.x; acc.y += v.y; acc.z += v.z; acc.w += v.w;
    }
#pragma unroll
    for (int off = 16; off >= 1; off >>= 1) {
        acc.x += __shfl_xor_sync(0xFFFFFFFFu, acc.x, off);
        acc.y += __shfl_xor_sync(0xFFFFFFFFu, acc.y, off);
        acc.z += __shfl_xor_sync(0xFFFFFFFFu, acc.z, off);
        acc.w += __shfl_xor_sync(0xFFFFFFFFu, acc.w, off);
    }
    if (lane == 0) {
        float cdv = g_cd[n];
        float4 o;
        o.x = fmaf(acc.x, cdv, bg2[0]);
        o.y = fmaf(acc.y, cdv, bg2[1]);
        o.z = fmaf(acc.z, cdv, bg2[2]);
        o.w = fmaf(acc.w, cdv, bg2[3]);
        *reinterpret_cast<float4*>(&out[n * 4]) = o;
    }
}

// ---------------- launch ----------------
extern "C" void kernel_launch(void* const* d_in, const int* in_sizes, int n_in,
                              void* d_out, int out_size) {
    const float* h   = (const float*)d_in[0];
    const int*   src = (const int*)d_in[1];
    const int*   dst = (const int*)d_in[2];
    const float* W1  = (const float*)d_in[3];
    const float* b1  = (const float*)d_in[4];
    const float* g1  = (const float*)d_in[5];
    const float* be1 = (const float*)d_in[6];
    const float* m1  = (const float*)d_in[7];
    const float* v1  = (const float*)d_in[8];
    const float* W2  = (const float*)d_in[9];
    const float* b2  = (const float*)d_in[10];
    const float* g2  = (const float*)d_in[11];
    const float* be2 = (const float*)d_in[12];
    const float* m2  = (const float*)d_in[13];
    const float* v2  = (const float*)d_in[14];
    const float* Wd  = (const float*)d_in[15];
    const float* bd  = (const float*)d_in[16];
    const float* Wg0 = (const float*)d_in[17];
    const float* bg0 = (const float*)d_in[18];
    const float* Wg1 = (const float*)d_in[19];
    const float* bg1 = (const float*)d_in[20];
    const float* Wg2 = (const float*)d_in[21];
    const float* bg2 = (const float*)d_in[22];
    float* out = (float*)d_out;

    cudaFuncSetAttribute(k_gemm_hmma, cudaFuncAttributeMaxDynamicSharedMemorySize,
                         SMEM_BYTES);

    k_fold<<<3326, 512>>>(src, dst, b1, g1, be1, m1, v1, W2, b2, g2,   // 1
                          be2, m2, v2, Wd, bd, Wg0);
    k_Rscan<<<224, 512>>>(W2);                                         // 2
    k_MBscan<<<598, 512>>>(W1);                                        // 3
    k_gemm_hmma<<<GEMM_BLKS + FILL_BLKS, 128, SMEM_BYTES>>>(h, src, dst);  // 4 <- ncu
    k_cvt<<<880, 512>>>();                                             // 5
    k_g64<<<(NN + 7) / 8, 256>>>(bg0, Wg1);                            // 6
    k_g32<<<(NN + 7) / 8, 256>>>(bg1, Wg2);                            // 7
    k_g4<<<(NN + 7) / 8, 256>>>(bg2, out);                             // 8
}